// round 1
// baseline (speedup 1.0000x reference)
#include <cuda_runtime.h>
#include <math.h>

// Problem constants
#define BB 64
#define LL 512
#define DD 768
#define HH 768

static const int   M_ROWS = BB * LL;                   // 32768
static const size_t PLH = (size_t)BB * LL * HH;        // 25165824
static const size_t ALL = (size_t)BB * LL * LL;        // 16777216
static const size_t SCRATCH_FLOATS = 6 * 25165824ULL + 3 * 16777216ULL + 4 * 32768ULL;

__device__ __align__(16) float g_scratch[6 * 25165824ULL + 3 * 16777216ULL + 4 * 32768ULL];

// ---------------------------------------------------------------------------
// Tiled GEMM config: BM=BN=64, BK=16, 256 threads (16x16), 4x4 micro-tile,
// strided (conflict-free) smem fragment reads: row m = m0 + ty + 16*i,
// col n = n0 + tx + 16*j.
// ---------------------------------------------------------------------------

#define GEMM_COMPUTE()                                                        \
    _Pragma("unroll")                                                         \
    for (int kk = 0; kk < 16; kk++) {                                         \
        float a[4], b[4];                                                     \
        _Pragma("unroll")                                                     \
        for (int i = 0; i < 4; i++) a[i] = As[kk][ty + 16 * i];               \
        _Pragma("unroll")                                                     \
        for (int j = 0; j < 4; j++) b[j] = Bs[kk][tx + 16 * j];               \
        _Pragma("unroll")                                                     \
        for (int i = 0; i < 4; i++)                                           \
            _Pragma("unroll")                                                 \
            for (int j = 0; j < 4; j++)                                       \
                acc[i][j] = fmaf(a[i], b[j], acc[i][j]);                      \
    }

// proj / attend-F: C[m,n] = relu(A[m,:]@W[:,n] + bias[n]) * (mask ? mask[m] : 1)
// A: [M_ROWS, K] row-major.  W: [K, HH] row-major.
__global__ __launch_bounds__(256) void k_proj(
    const float* __restrict__ A, const float* __restrict__ W,
    const float* __restrict__ bias, const int* __restrict__ mask,
    float* __restrict__ C, int K)
{
    __shared__ __align__(16) float As[16][68];
    __shared__ __align__(16) float Bs[16][68];
    const int tx = threadIdx.x, ty = threadIdx.y;
    const int t = ty * 16 + tx;
    const int m0 = blockIdx.y << 6, n0 = blockIdx.x << 6;
    const int arow = t >> 2, acg = (t & 3) << 2;
    const int brow = t >> 4, bcg = (t & 15) << 2;
    float acc[4][4] = {};
    for (int k0 = 0; k0 < K; k0 += 16) {
        float4 av = *reinterpret_cast<const float4*>(A + (size_t)(m0 + arow) * K + (k0 + acg));
        float4 bv = *reinterpret_cast<const float4*>(W + (size_t)(k0 + brow) * HH + (n0 + bcg));
        As[acg + 0][arow] = av.x; As[acg + 1][arow] = av.y;
        As[acg + 2][arow] = av.z; As[acg + 3][arow] = av.w;
        *reinterpret_cast<float4*>(&Bs[brow][bcg]) = bv;
        __syncthreads();
        GEMM_COMPUTE();
        __syncthreads();
    }
#pragma unroll
    for (int i = 0; i < 4; i++) {
        int m = m0 + ty + 16 * i;
        float mk = mask ? (float)mask[m] : 1.0f;
#pragma unroll
        for (int j = 0; j < 4; j++) {
            int n = n0 + tx + 16 * j;
            float v = fmaxf(acc[i][j] + bias[n], 0.0f) * mk;
            C[(size_t)m * HH + n] = v;
        }
    }
}

// att[b,i,j] = sum_k Fa[b,i,k] * Fb[b,j,k]   (batched NT)
__global__ __launch_bounds__(256) void k_att(
    const float* __restrict__ Fa, const float* __restrict__ Fb, float* __restrict__ att)
{
    __shared__ __align__(16) float As[16][68];
    __shared__ __align__(16) float Bs[16][68];
    const int tx = threadIdx.x, ty = threadIdx.y;
    const int t = ty * 16 + tx;
    const int b = blockIdx.z;
    const int i0 = blockIdx.y << 6, j0 = blockIdx.x << 6;
    const float* Ab = Fa + (size_t)b * LL * HH;
    const float* Bb = Fb + (size_t)b * LL * HH;
    const int arow = t >> 2, acg = (t & 3) << 2;
    float acc[4][4] = {};
    for (int k0 = 0; k0 < HH; k0 += 16) {
        float4 av = *reinterpret_cast<const float4*>(Ab + (size_t)(i0 + arow) * HH + (k0 + acg));
        float4 bv = *reinterpret_cast<const float4*>(Bb + (size_t)(j0 + arow) * HH + (k0 + acg));
        As[acg + 0][arow] = av.x; As[acg + 1][arow] = av.y;
        As[acg + 2][arow] = av.z; As[acg + 3][arow] = av.w;
        Bs[acg + 0][arow] = bv.x; Bs[acg + 1][arow] = bv.y;
        Bs[acg + 2][arow] = bv.z; Bs[acg + 3][arow] = bv.w;
        __syncthreads();
        GEMM_COMPUTE();
        __syncthreads();
    }
#pragma unroll
    for (int i = 0; i < 4; i++) {
        int ii = i0 + ty + 16 * i;
#pragma unroll
        for (int j = 0; j < 4; j++) {
            int jj = j0 + tx + 16 * j;
            att[((size_t)b * LL + ii) * LL + jj] = acc[i][j];
        }
    }
}

// beta[b,m,n] = sum_k S1[b,m,k] * Pb[b,k,n]   (batched NN, K=512)
__global__ __launch_bounds__(256) void k_ctx_nn(
    const float* __restrict__ S, const float* __restrict__ Pb, float* __restrict__ C)
{
    __shared__ __align__(16) float As[16][68];
    __shared__ __align__(16) float Bs[16][68];
    const int tx = threadIdx.x, ty = threadIdx.y;
    const int t = ty * 16 + tx;
    const int b = blockIdx.z;
    const int m0 = blockIdx.y << 6, n0 = blockIdx.x << 6;
    const float* Ab = S + (size_t)b * LL * LL;
    const float* Bb = Pb + (size_t)b * LL * HH;
    const int arow = t >> 2, acg = (t & 3) << 2;
    const int brow = t >> 4, bcg = (t & 15) << 2;
    float acc[4][4] = {};
    for (int k0 = 0; k0 < LL; k0 += 16) {
        float4 av = *reinterpret_cast<const float4*>(Ab + (size_t)(m0 + arow) * LL + (k0 + acg));
        float4 bv = *reinterpret_cast<const float4*>(Bb + (size_t)(k0 + brow) * HH + (n0 + bcg));
        As[acg + 0][arow] = av.x; As[acg + 1][arow] = av.y;
        As[acg + 2][arow] = av.z; As[acg + 3][arow] = av.w;
        *reinterpret_cast<float4*>(&Bs[brow][bcg]) = bv;
        __syncthreads();
        GEMM_COMPUTE();
        __syncthreads();
    }
#pragma unroll
    for (int i = 0; i < 4; i++) {
        int m = m0 + ty + 16 * i;
#pragma unroll
        for (int j = 0; j < 4; j++) {
            int n = n0 + tx + 16 * j;
            C[((size_t)b * LL + m) * HH + n] = acc[i][j];
        }
    }
}

// alpha[b,m,n] = sum_k S2[b,k,m] * Pa[b,k,n]   (batched TN; S2 stored [b,i,j] i-major)
__global__ __launch_bounds__(256) void k_ctx_tn(
    const float* __restrict__ S2, const float* __restrict__ Pa, float* __restrict__ C)
{
    __shared__ __align__(16) float As[16][68];
    __shared__ __align__(16) float Bs[16][68];
    const int tx = threadIdx.x, ty = threadIdx.y;
    const int t = ty * 16 + tx;
    const int b = blockIdx.z;
    const int m0 = blockIdx.y << 6, n0 = blockIdx.x << 6;
    const float* Ab = S2 + (size_t)b * LL * LL;
    const float* Bb = Pa + (size_t)b * LL * HH;
    const int krow = t >> 4, kcg = (t & 15) << 2;
    float acc[4][4] = {};
    for (int k0 = 0; k0 < LL; k0 += 16) {
        float4 av = *reinterpret_cast<const float4*>(Ab + (size_t)(k0 + krow) * LL + (m0 + kcg));
        float4 bv = *reinterpret_cast<const float4*>(Bb + (size_t)(k0 + krow) * HH + (n0 + kcg));
        *reinterpret_cast<float4*>(&As[krow][kcg]) = av;
        *reinterpret_cast<float4*>(&Bs[krow][kcg]) = bv;
        __syncthreads();
        GEMM_COMPUTE();
        __syncthreads();
    }
#pragma unroll
    for (int i = 0; i < 4; i++) {
        int m = m0 + ty + 16 * i;
#pragma unroll
        for (int j = 0; j < 4; j++) {
            int n = n0 + tx + 16 * j;
            C[((size_t)b * LL + m) * HH + n] = acc[i][j];
        }
    }
}

// compare + aggregate: v[m,n] = relu([P|CTX][m,:]@Wg[:,n] + bg[n]) * mask[m]
// then per-(batch,col): atomicAdd(sum), atomicMax(max) into out.
__global__ __launch_bounds__(256) void k_cmp(
    const float* __restrict__ P, const float* __restrict__ CTX,
    const float* __restrict__ Wg, const float* __restrict__ bg,
    const int* __restrict__ mask, float* __restrict__ out,
    int sumoff, int maxoff)
{
    __shared__ __align__(16) float As[16][68];
    __shared__ __align__(16) float Bs[16][68];
    const int tx = threadIdx.x, ty = threadIdx.y;
    const int t = ty * 16 + tx;
    const int m0 = blockIdx.y << 6, n0 = blockIdx.x << 6;
    const int arow = t >> 2, acg = (t & 3) << 2;
    const int brow = t >> 4, bcg = (t & 15) << 2;
    float acc[4][4] = {};
    for (int k0 = 0; k0 < 2 * HH; k0 += 16) {
        const float* Asrc = (k0 < HH) ? P : CTX;
        const int kk0 = (k0 < HH) ? k0 : (k0 - HH);
        float4 av = *reinterpret_cast<const float4*>(Asrc + (size_t)(m0 + arow) * HH + (kk0 + acg));
        float4 bv = *reinterpret_cast<const float4*>(Wg + (size_t)(k0 + brow) * HH + (n0 + bcg));
        As[acg + 0][arow] = av.x; As[acg + 1][arow] = av.y;
        As[acg + 2][arow] = av.z; As[acg + 3][arow] = av.w;
        *reinterpret_cast<float4*>(&Bs[brow][bcg]) = bv;
        __syncthreads();
        GEMM_COMPUTE();
        __syncthreads();
    }
    const int bb = m0 >> 9;  // batch index (64 | 512)
    float psum[4] = {0.f, 0.f, 0.f, 0.f};
    float pmax[4] = {0.f, 0.f, 0.f, 0.f};
#pragma unroll
    for (int i = 0; i < 4; i++) {
        int m = m0 + ty + 16 * i;
        float mk = (float)mask[m];
#pragma unroll
        for (int j = 0; j < 4; j++) {
            int n = n0 + tx + 16 * j;
            float v = fmaxf(acc[i][j] + bg[n], 0.0f) * mk;
            psum[j] += v;
            pmax[j] = fmaxf(pmax[j], v);
        }
    }
#pragma unroll
    for (int j = 0; j < 4; j++) {
        As[ty][tx + 16 * j] = psum[j];
        Bs[ty][tx + 16 * j] = pmax[j];
    }
    __syncthreads();
    if (t < 64) {
        float s = 0.f, mx = 0.f;
#pragma unroll
        for (int r = 0; r < 16; r++) {
            s += As[r][t];
            mx = fmaxf(mx, Bs[r][t]);
        }
        atomicAdd(&out[bb * 3072 + sumoff + n0 + t], s);
        // values are nonnegative; int compare == float compare for nonneg floats
        atomicMax((int*)&out[bb * 3072 + maxoff + n0 + t], __float_as_int(mx));
    }
}

// Row softmax stats: rowmax (unmasked), rowsum = 768*am_i * sum_j exp(a-rm)*bm_j
__global__ void k_rowstats(const float* __restrict__ att,
                           const int* __restrict__ a_mask, const int* __restrict__ b_mask,
                           float* __restrict__ rm, float* __restrict__ rs)
{
    const int i = blockIdx.x, bb = blockIdx.y;
    const float* row = att + ((size_t)bb * LL + i) * LL;
    const int t = threadIdx.x;
    __shared__ float sm[256];
    float m = fmaxf(row[t], row[t + 256]);
    sm[t] = m; __syncthreads();
    for (int s = 128; s > 0; s >>= 1) {
        if (t < s) sm[t] = fmaxf(sm[t], sm[t + s]);
        __syncthreads();
    }
    m = sm[0];
    __syncthreads();
    float s1 = expf(row[t] - m) * (float)b_mask[bb * LL + t]
             + expf(row[t + 256] - m) * (float)b_mask[bb * LL + t + 256];
    sm[t] = s1; __syncthreads();
    for (int s = 128; s > 0; s >>= 1) {
        if (t < s) sm[t] += sm[t + s];
        __syncthreads();
    }
    if (t == 0) {
        rm[bb * LL + i] = m;
        rs[bb * LL + i] = 768.0f * (float)a_mask[bb * LL + i] * sm[0];
    }
}

// Column softmax stats (coalesced: threads over columns, loop rows)
__global__ void k_colstats(const float* __restrict__ att,
                           const int* __restrict__ a_mask, const int* __restrict__ b_mask,
                           float* __restrict__ cm, float* __restrict__ cs)
{
    const int bb = blockIdx.y;
    const int j = blockIdx.x * 128 + threadIdx.x;
    __shared__ float ams[LL];
    for (int i = threadIdx.x; i < LL; i += 128) ams[i] = (float)a_mask[bb * LL + i];
    __syncthreads();
    const float* base = att + (size_t)bb * LL * LL;
    float m = -1e30f;
    for (int i = 0; i < LL; i++) m = fmaxf(m, base[(size_t)i * LL + j]);
    float s = 0.f;
    for (int i = 0; i < LL; i++) s += expf(base[(size_t)i * LL + j] - m) * ams[i];
    cm[bb * LL + j] = m;
    cs[bb * LL + j] = 768.0f * (float)b_mask[bb * LL + j] * s;
}

// Map att -> S1 (row-softmax) and S2 (col-softmax numerators/denominators, i-major)
__global__ void k_map(const float* __restrict__ att,
                      const int* __restrict__ a_mask, const int* __restrict__ b_mask,
                      const float* __restrict__ rm, const float* __restrict__ rs,
                      const float* __restrict__ cm, const float* __restrict__ cs,
                      float* __restrict__ S1, float* __restrict__ S2)
{
    const int i = blockIdx.x, bb = blockIdx.y;
    const size_t off = ((size_t)bb * LL + i) * LL;
    const float am = (float)a_mask[bb * LL + i];
    const float rmi = rm[bb * LL + i];
    const float rinv = 1.0f / (rs[bb * LL + i] + 1e-8f);
    const int t = threadIdx.x;
    for (int j = t; j < LL; j += 256) {
        float a = att[off + j];
        float mfac = 768.0f * am * (float)b_mask[bb * LL + j];
        S1[off + j] = expf(a - rmi) * mfac * rinv;
        S2[off + j] = expf(a - cm[bb * LL + j]) * mfac / (cs[bb * LL + j] + 1e-8f);
    }
}

__global__ void k_zero(float* __restrict__ out)
{
    int i = blockIdx.x * blockDim.x + threadIdx.x;
    if (i < BB * 4 * HH) out[i] = 0.0f;
}

extern "C" void kernel_launch(void* const* d_in, const int* in_sizes, int n_in,
                              void* d_out, int out_size)
{
    const float* a_embeds = (const float*)d_in[0];
    const float* b_embeds = (const float*)d_in[1];
    const int*   a_mask   = (const int*)d_in[2];
    const int*   b_mask   = (const int*)d_in[3];
    const float* Wp = (const float*)d_in[4];
    const float* bp = (const float*)d_in[5];
    const float* Wf = (const float*)d_in[6];
    const float* bf = (const float*)d_in[7];
    const float* Wg = (const float*)d_in[8];
    const float* bg = (const float*)d_in[9];
    float* out = (float*)d_out;

    float* base = nullptr;
    cudaGetSymbolAddress((void**)&base, g_scratch);
    float* ap    = base;
    float* bp_   = base + PLH;
    float* Fa    = base + 2 * PLH;
    float* Fb    = base + 3 * PLH;
    float* beta  = base + 4 * PLH;
    float* alpha = base + 5 * PLH;
    float* att   = base + 6 * PLH;
    float* S1    = att + ALL;
    float* S2    = S1 + ALL;
    float* rm    = S2 + ALL;
    float* rs    = rm + M_ROWS;
    float* cm    = rs + M_ROWS;
    float* cs    = cm + M_ROWS;

    dim3 thr(16, 16);

    k_zero<<<(BB * 4 * HH + 1023) / 1024, 1024>>>(out);

    // shared projection FFN
    k_proj<<<dim3(12, 512), thr>>>(a_embeds, Wp, bp, nullptr, ap, DD);
    k_proj<<<dim3(12, 512), thr>>>(b_embeds, Wp, bp, nullptr, bp_, DD);

    // attend features (relu + mask)
    k_proj<<<dim3(12, 512), thr>>>(ap, Wf, bf, a_mask, Fa, HH);
    k_proj<<<dim3(12, 512), thr>>>(bp_, Wf, bf, b_mask, Fb, HH);

    // attention scores
    k_att<<<dim3(8, 8, 64), thr>>>(Fa, Fb, att);

    // dual softmax
    k_rowstats<<<dim3(512, 64), 256>>>(att, a_mask, b_mask, rm, rs);
    k_colstats<<<dim3(4, 64), 128>>>(att, a_mask, b_mask, cm, cs);
    k_map<<<dim3(512, 64), 256>>>(att, a_mask, b_mask, rm, rs, cm, cs, S1, S2);

    // contexts
    k_ctx_nn<<<dim3(12, 8, 64), thr>>>(S1, bp_, beta);    // beta  = soft1 @ b_p
    k_ctx_tn<<<dim3(12, 8, 64), thr>>>(S2, ap, alpha);    // alpha = soft2 @ a_p

    // compare + aggregate (fused sum/max epilogue)
    k_cmp<<<dim3(12, 512), thr>>>(ap,  beta,  Wg, bg, a_mask, out, 0,   1536);
    k_cmp<<<dim3(12, 512), thr>>>(bp_, alpha, Wg, bg, b_mask, out, 768, 2304);
}

// round 2
// speedup vs baseline: 4.1637x; 4.1637x over previous
#include <cuda_runtime.h>
#include <stdint.h>
#include <math.h>

// Problem constants
#define BB 64
#define LL 512
#define DD 768
#define HH 768

#define BM 128
#define BN 128
#define BK 16

static const int    M_ROWS = BB * LL;                  // 32768
static const size_t PLH = (size_t)BB * LL * HH;        // 25165824
static const size_t ALL = (size_t)BB * LL * LL;        // 16777216

__device__ __align__(16) float g_scratch[6 * 25165824ULL + 3 * 16777216ULL + 4 * 32768ULL];

// ---------------------------------------------------------------------------
// tensor-core helpers
// ---------------------------------------------------------------------------
__device__ __forceinline__ void cp16(void* s, const void* g) {
    uint32_t sa = (uint32_t)__cvta_generic_to_shared(s);
    asm volatile("cp.async.cg.shared.global [%0], [%1], 16;" :: "r"(sa), "l"(g));
}
__device__ __forceinline__ void cp_commit() { asm volatile("cp.async.commit_group;"); }
__device__ __forceinline__ void cp_wait0()  { asm volatile("cp.async.wait_group 0;"); }

__device__ __forceinline__ uint32_t f2tf(float x) {
    uint32_t r;
    asm("cvt.rna.tf32.f32 %0, %1;" : "=r"(r) : "f"(x));
    return r;
}
__device__ __forceinline__ void mma8(float* c, const uint32_t* a, const uint32_t* b) {
    asm volatile(
        "mma.sync.aligned.m16n8k8.row.col.f32.tf32.tf32.f32 "
        "{%0,%1,%2,%3},{%4,%5,%6,%7},{%8,%9},{%0,%1,%2,%3};"
        : "+f"(c[0]), "+f"(c[1]), "+f"(c[2]), "+f"(c[3])
        : "r"(a[0]), "r"(a[1]), "r"(a[2]), "r"(a[3]), "r"(b[0]), "r"(b[1]));
}

// Fragment loaders. g = lane/4, q = lane%4.
// mk layout: rows[m][20] (k contiguous, pad 20 -> conflict-free)
#define LA_MK                                                                  \
    _Pragma("unroll")                                                          \
    for (int fm = 0; fm < 4; fm++) {                                           \
        int m = wm * 64 + fm * 16 + g;                                         \
        af[fm][0] = f2tf(As[buf][m][kk + q]);                                  \
        af[fm][1] = f2tf(As[buf][m + 8][kk + q]);                              \
        af[fm][2] = f2tf(As[buf][m][kk + q + 4]);                              \
        af[fm][3] = f2tf(As[buf][m + 8][kk + q + 4]);                          \
    }
// km layout: [k][136] (m contiguous, pad 8 -> conflict-free)
#define LA_KM                                                                  \
    _Pragma("unroll")                                                          \
    for (int fm = 0; fm < 4; fm++) {                                           \
        int m = wm * 64 + fm * 16 + g;                                         \
        af[fm][0] = f2tf(As[buf][kk + q][m]);                                  \
        af[fm][1] = f2tf(As[buf][kk + q][m + 8]);                              \
        af[fm][2] = f2tf(As[buf][kk + q + 4][m]);                              \
        af[fm][3] = f2tf(As[buf][kk + q + 4][m + 8]);                          \
    }
#define LB_KN                                                                  \
    _Pragma("unroll")                                                          \
    for (int fn = 0; fn < 4; fn++) {                                           \
        int n = wn * 32 + fn * 8 + g;                                          \
        bf_[fn][0] = f2tf(Bs[buf][kk + q][n]);                                 \
        bf_[fn][1] = f2tf(Bs[buf][kk + q + 4][n]);                             \
    }
#define LB_NK                                                                  \
    _Pragma("unroll")                                                          \
    for (int fn = 0; fn < 4; fn++) {                                           \
        int n = wn * 32 + fn * 8 + g;                                          \
        bf_[fn][0] = f2tf(Bs[buf][n][kk + q]);                                 \
        bf_[fn][1] = f2tf(Bs[buf][n][kk + q + 4]);                             \
    }

#define COMPUTE_TILE(LOADA, LOADB)                                             \
    _Pragma("unroll")                                                          \
    for (int ks = 0; ks < 2; ks++) {                                           \
        const int kk = ks * 8;                                                 \
        uint32_t af[4][4], bf_[4][2];                                          \
        LOADA                                                                  \
        LOADB                                                                  \
        _Pragma("unroll")                                                      \
        for (int fm = 0; fm < 4; fm++)                                         \
            _Pragma("unroll")                                                  \
            for (int fn = 0; fn < 4; fn++)                                     \
                mma8(acc[fm][fn], af[fm], bf_[fn]);                            \
    }

// ---------------------------------------------------------------------------
// proj / attend-F: C = relu(A[M,K] @ W[K,768] + bias) * (mask?)
// ---------------------------------------------------------------------------
__global__ __launch_bounds__(256, 2) void k_proj(
    const float* __restrict__ A, const float* __restrict__ W,
    const float* __restrict__ bias, const int* __restrict__ mask,
    float* __restrict__ C, int K)
{
    __shared__ float As[2][BM][20];
    __shared__ float Bs[2][BK][BN + 8];
    const int t = threadIdx.x;
    const int w = t >> 5, l = t & 31, g = l >> 2, q = l & 3;
    const int wm = w >> 2, wn = w & 3;
    const int m0 = blockIdx.y * BM, n0 = blockIdx.x * BN;
    const int ar = t >> 2, ac = (t & 3) * 4;
    const int brk = t >> 5, bcn = (t & 31) * 4;
    float acc[4][4][4] = {};
    const int nt = K / BK;
#pragma unroll
    for (int i = 0; i < 2; i++) cp16(&As[0][ar + 64 * i][ac], A + (size_t)(m0 + ar + 64 * i) * K + ac);
#pragma unroll
    for (int i = 0; i < 2; i++) cp16(&Bs[0][brk + 8 * i][bcn], W + (size_t)(brk + 8 * i) * HH + n0 + bcn);
    cp_commit();
    for (int kt = 0; kt < nt; kt++) {
        cp_wait0();
        __syncthreads();
        const int buf = kt & 1;
        if (kt + 1 < nt) {
            const int k0 = (kt + 1) * BK, nb = buf ^ 1;
#pragma unroll
            for (int i = 0; i < 2; i++) cp16(&As[nb][ar + 64 * i][ac], A + (size_t)(m0 + ar + 64 * i) * K + k0 + ac);
#pragma unroll
            for (int i = 0; i < 2; i++) cp16(&Bs[nb][brk + 8 * i][bcn], W + (size_t)(k0 + brk + 8 * i) * HH + n0 + bcn);
            cp_commit();
        }
        COMPUTE_TILE(LA_MK, LB_KN)
    }
    const int mbase = m0 + wm * 64, nbase = n0 + wn * 32;
#pragma unroll
    for (int fm = 0; fm < 4; fm++) {
        int m = mbase + fm * 16 + g;
        float mk0 = mask ? (float)mask[m] : 1.0f;
        float mk1 = mask ? (float)mask[m + 8] : 1.0f;
#pragma unroll
        for (int fn = 0; fn < 4; fn++) {
            int n = nbase + fn * 8 + 2 * q;
            float b0 = bias[n], b1 = bias[n + 1];
            float2 v0 = make_float2(fmaxf(acc[fm][fn][0] + b0, 0.f) * mk0,
                                    fmaxf(acc[fm][fn][1] + b1, 0.f) * mk0);
            float2 v1 = make_float2(fmaxf(acc[fm][fn][2] + b0, 0.f) * mk1,
                                    fmaxf(acc[fm][fn][3] + b1, 0.f) * mk1);
            *(float2*)&C[(size_t)m * HH + n] = v0;
            *(float2*)&C[(size_t)(m + 8) * HH + n] = v1;
        }
    }
}

// ---------------------------------------------------------------------------
// att[b,i,j] = Fa[b,i,:] . Fb[b,j,:]   (NT)
// ---------------------------------------------------------------------------
__global__ __launch_bounds__(256, 2) void k_att(
    const float* __restrict__ Fa, const float* __restrict__ Fb, float* __restrict__ att)
{
    __shared__ float As[2][BM][20];
    __shared__ float Bs[2][BN][20];
    const int t = threadIdx.x;
    const int w = t >> 5, l = t & 31, g = l >> 2, q = l & 3;
    const int wm = w >> 2, wn = w & 3;
    const int b = blockIdx.z;
    const int m0 = blockIdx.y * BM, n0 = blockIdx.x * BN;
    const float* Ab = Fa + (size_t)b * LL * HH;
    const float* Bb = Fb + (size_t)b * LL * HH;
    const int ar = t >> 2, ac = (t & 3) * 4;
    float acc[4][4][4] = {};
    const int nt = HH / BK;
#pragma unroll
    for (int i = 0; i < 2; i++) cp16(&As[0][ar + 64 * i][ac], Ab + (size_t)(m0 + ar + 64 * i) * HH + ac);
#pragma unroll
    for (int i = 0; i < 2; i++) cp16(&Bs[0][ar + 64 * i][ac], Bb + (size_t)(n0 + ar + 64 * i) * HH + ac);
    cp_commit();
    for (int kt = 0; kt < nt; kt++) {
        cp_wait0();
        __syncthreads();
        const int buf = kt & 1;
        if (kt + 1 < nt) {
            const int k0 = (kt + 1) * BK, nb = buf ^ 1;
#pragma unroll
            for (int i = 0; i < 2; i++) cp16(&As[nb][ar + 64 * i][ac], Ab + (size_t)(m0 + ar + 64 * i) * HH + k0 + ac);
#pragma unroll
            for (int i = 0; i < 2; i++) cp16(&Bs[nb][ar + 64 * i][ac], Bb + (size_t)(n0 + ar + 64 * i) * HH + k0 + ac);
            cp_commit();
        }
        COMPUTE_TILE(LA_MK, LB_NK)
    }
    const int mbase = m0 + wm * 64, nbase = n0 + wn * 32;
#pragma unroll
    for (int fm = 0; fm < 4; fm++) {
        int m = mbase + fm * 16 + g;
#pragma unroll
        for (int fn = 0; fn < 4; fn++) {
            int n = nbase + fn * 8 + 2 * q;
            *(float2*)&att[((size_t)b * LL + m) * LL + n] =
                make_float2(acc[fm][fn][0], acc[fm][fn][1]);
            *(float2*)&att[((size_t)b * LL + m + 8) * LL + n] =
                make_float2(acc[fm][fn][2], acc[fm][fn][3]);
        }
    }
}

// ---------------------------------------------------------------------------
// beta[b] = S1[b] @ Pb[b]   (NN, K=512)
// ---------------------------------------------------------------------------
__global__ __launch_bounds__(256, 2) void k_ctx_nn(
    const float* __restrict__ S, const float* __restrict__ Pb, float* __restrict__ C)
{
    __shared__ float As[2][BM][20];
    __shared__ float Bs[2][BK][BN + 8];
    const int t = threadIdx.x;
    const int w = t >> 5, l = t & 31, g = l >> 2, q = l & 3;
    const int wm = w >> 2, wn = w & 3;
    const int b = blockIdx.z;
    const int m0 = blockIdx.y * BM, n0 = blockIdx.x * BN;
    const float* Ab = S + (size_t)b * LL * LL;
    const float* Bb = Pb + (size_t)b * LL * HH;
    const int ar = t >> 2, ac = (t & 3) * 4;
    const int brk = t >> 5, bcn = (t & 31) * 4;
    float acc[4][4][4] = {};
    const int nt = LL / BK;
#pragma unroll
    for (int i = 0; i < 2; i++) cp16(&As[0][ar + 64 * i][ac], Ab + (size_t)(m0 + ar + 64 * i) * LL + ac);
#pragma unroll
    for (int i = 0; i < 2; i++) cp16(&Bs[0][brk + 8 * i][bcn], Bb + (size_t)(brk + 8 * i) * HH + n0 + bcn);
    cp_commit();
    for (int kt = 0; kt < nt; kt++) {
        cp_wait0();
        __syncthreads();
        const int buf = kt & 1;
        if (kt + 1 < nt) {
            const int k0 = (kt + 1) * BK, nb = buf ^ 1;
#pragma unroll
            for (int i = 0; i < 2; i++) cp16(&As[nb][ar + 64 * i][ac], Ab + (size_t)(m0 + ar + 64 * i) * LL + k0 + ac);
#pragma unroll
            for (int i = 0; i < 2; i++) cp16(&Bs[nb][brk + 8 * i][bcn], Bb + (size_t)(k0 + brk + 8 * i) * HH + n0 + bcn);
            cp_commit();
        }
        COMPUTE_TILE(LA_MK, LB_KN)
    }
    const int mbase = m0 + wm * 64, nbase = n0 + wn * 32;
#pragma unroll
    for (int fm = 0; fm < 4; fm++) {
        int m = mbase + fm * 16 + g;
#pragma unroll
        for (int fn = 0; fn < 4; fn++) {
            int n = nbase + fn * 8 + 2 * q;
            *(float2*)&C[((size_t)b * LL + m) * HH + n] =
                make_float2(acc[fm][fn][0], acc[fm][fn][1]);
            *(float2*)&C[((size_t)b * LL + m + 8) * HH + n] =
                make_float2(acc[fm][fn][2], acc[fm][fn][3]);
        }
    }
}

// ---------------------------------------------------------------------------
// alpha[b,m,n] = sum_k S2[b,k,m] * Pa[b,k,n]   (TN; S2 stored i-major)
// ---------------------------------------------------------------------------
__global__ __launch_bounds__(256, 2) void k_ctx_tn(
    const float* __restrict__ S2, const float* __restrict__ Pa, float* __restrict__ C)
{
    __shared__ float As[2][BK][BM + 8];
    __shared__ float Bs[2][BK][BN + 8];
    const int t = threadIdx.x;
    const int w = t >> 5, l = t & 31, g = l >> 2, q = l & 3;
    const int wm = w >> 2, wn = w & 3;
    const int b = blockIdx.z;
    const int m0 = blockIdx.y * BM, n0 = blockIdx.x * BN;
    const float* Ab = S2 + (size_t)b * LL * LL;
    const float* Bb = Pa + (size_t)b * LL * HH;
    const int rk = t >> 5, cm = (t & 31) * 4;
    float acc[4][4][4] = {};
    const int nt = LL / BK;
#pragma unroll
    for (int i = 0; i < 2; i++) cp16(&As[0][rk + 8 * i][cm], Ab + (size_t)(rk + 8 * i) * LL + m0 + cm);
#pragma unroll
    for (int i = 0; i < 2; i++) cp16(&Bs[0][rk + 8 * i][cm], Bb + (size_t)(rk + 8 * i) * HH + n0 + cm);
    cp_commit();
    for (int kt = 0; kt < nt; kt++) {
        cp_wait0();
        __syncthreads();
        const int buf = kt & 1;
        if (kt + 1 < nt) {
            const int k0 = (kt + 1) * BK, nb = buf ^ 1;
#pragma unroll
            for (int i = 0; i < 2; i++) cp16(&As[nb][rk + 8 * i][cm], Ab + (size_t)(k0 + rk + 8 * i) * LL + m0 + cm);
#pragma unroll
            for (int i = 0; i < 2; i++) cp16(&Bs[nb][rk + 8 * i][cm], Bb + (size_t)(k0 + rk + 8 * i) * HH + n0 + cm);
            cp_commit();
        }
        COMPUTE_TILE(LA_KM, LB_KN)
    }
    const int mbase = m0 + wm * 64, nbase = n0 + wn * 32;
#pragma unroll
    for (int fm = 0; fm < 4; fm++) {
        int m = mbase + fm * 16 + g;
#pragma unroll
        for (int fn = 0; fn < 4; fn++) {
            int n = nbase + fn * 8 + 2 * q;
            *(float2*)&C[((size_t)b * LL + m) * HH + n] =
                make_float2(acc[fm][fn][0], acc[fm][fn][1]);
            *(float2*)&C[((size_t)b * LL + m + 8) * HH + n] =
                make_float2(acc[fm][fn][2], acc[fm][fn][3]);
        }
    }
}

// ---------------------------------------------------------------------------
// compare + aggregate: v = relu([P|CTX] @ Wg + bg) * mask; out += sum / max
// ---------------------------------------------------------------------------
__global__ __launch_bounds__(256, 2) void k_cmp(
    const float* __restrict__ P, const float* __restrict__ CTX,
    const float* __restrict__ Wg, const float* __restrict__ bg,
    const int* __restrict__ mask, float* __restrict__ out,
    int sumoff, int maxoff)
{
    __shared__ float As[2][BM][20];
    __shared__ float Bs[2][BK][BN + 8];
    __shared__ float red_s[128][2];
    __shared__ float red_m[128][2];
    const int t = threadIdx.x;
    const int w = t >> 5, l = t & 31, g = l >> 2, q = l & 3;
    const int wm = w >> 2, wn = w & 3;
    const int m0 = blockIdx.y * BM, n0 = blockIdx.x * BN;
    const int ar = t >> 2, ac = (t & 3) * 4;
    const int brk = t >> 5, bcn = (t & 31) * 4;
    float acc[4][4][4] = {};
    const int nt = (2 * HH) / BK;   // 96
#pragma unroll
    for (int i = 0; i < 2; i++) cp16(&As[0][ar + 64 * i][ac], P + (size_t)(m0 + ar + 64 * i) * HH + ac);
#pragma unroll
    for (int i = 0; i < 2; i++) cp16(&Bs[0][brk + 8 * i][bcn], Wg + (size_t)(brk + 8 * i) * HH + n0 + bcn);
    cp_commit();
    for (int kt = 0; kt < nt; kt++) {
        cp_wait0();
        __syncthreads();
        const int buf = kt & 1;
        if (kt + 1 < nt) {
            const int k0 = (kt + 1) * BK, nb = buf ^ 1;
            const float* Asrc = (k0 < HH) ? P : CTX;
            const int kk0 = (k0 < HH) ? k0 : (k0 - HH);
#pragma unroll
            for (int i = 0; i < 2; i++) cp16(&As[nb][ar + 64 * i][ac], Asrc + (size_t)(m0 + ar + 64 * i) * HH + kk0 + ac);
#pragma unroll
            for (int i = 0; i < 2; i++) cp16(&Bs[nb][brk + 8 * i][bcn], Wg + (size_t)(k0 + brk + 8 * i) * HH + n0 + bcn);
            cp_commit();
        }
        COMPUTE_TILE(LA_MK, LB_KN)
    }
    const int mbase = m0 + wm * 64, nbase = n0 + wn * 32;
    float psum[4][2] = {}, pmax[4][2] = {};
#pragma unroll
    for (int fm = 0; fm < 4; fm++) {
        int m = mbase + fm * 16 + g;
        float mk0 = (float)mask[m];
        float mk1 = (float)mask[m + 8];
#pragma unroll
        for (int fn = 0; fn < 4; fn++) {
            int n = nbase + fn * 8 + 2 * q;
            float b0 = bg[n], b1 = bg[n + 1];
            float v00 = fmaxf(acc[fm][fn][0] + b0, 0.f) * mk0;
            float v01 = fmaxf(acc[fm][fn][1] + b1, 0.f) * mk0;
            float v10 = fmaxf(acc[fm][fn][2] + b0, 0.f) * mk1;
            float v11 = fmaxf(acc[fm][fn][3] + b1, 0.f) * mk1;
            psum[fn][0] += v00 + v10;
            psum[fn][1] += v01 + v11;
            pmax[fn][0] = fmaxf(pmax[fn][0], fmaxf(v00, v10));
            pmax[fn][1] = fmaxf(pmax[fn][1], fmaxf(v01, v11));
        }
    }
#pragma unroll
    for (int fn = 0; fn < 4; fn++)
#pragma unroll
        for (int e = 0; e < 2; e++) {
#pragma unroll
            for (int o = 4; o < 32; o <<= 1) {
                psum[fn][e] += __shfl_xor_sync(0xffffffffu, psum[fn][e], o);
                pmax[fn][e] = fmaxf(pmax[fn][e], __shfl_xor_sync(0xffffffffu, pmax[fn][e], o));
            }
        }
    if (l < 4) {
#pragma unroll
        for (int fn = 0; fn < 4; fn++)
#pragma unroll
            for (int e = 0; e < 2; e++) {
                int c = wn * 32 + fn * 8 + 2 * q + e;
                red_s[c][wm] = psum[fn][e];
                red_m[c][wm] = pmax[fn][e];
            }
    }
    __syncthreads();
    if (t < 128) {
        const int bb = m0 >> 9;
        float s = red_s[t][0] + red_s[t][1];
        float mx = fmaxf(red_m[t][0], red_m[t][1]);
        atomicAdd(&out[bb * 3072 + sumoff + n0 + t], s);
        atomicMax((int*)&out[bb * 3072 + maxoff + n0 + t], __float_as_int(mx));
    }
}

// ---------------------------------------------------------------------------
// softmax stats + map (unchanged, memory-bound)
// ---------------------------------------------------------------------------
__global__ void k_rowstats(const float* __restrict__ att,
                           const int* __restrict__ a_mask, const int* __restrict__ b_mask,
                           float* __restrict__ rm, float* __restrict__ rs)
{
    const int i = blockIdx.x, bb = blockIdx.y;
    const float* row = att + ((size_t)bb * LL + i) * LL;
    const int t = threadIdx.x;
    __shared__ float sm[256];
    float m = fmaxf(row[t], row[t + 256]);
    sm[t] = m; __syncthreads();
    for (int s = 128; s > 0; s >>= 1) {
        if (t < s) sm[t] = fmaxf(sm[t], sm[t + s]);
        __syncthreads();
    }
    m = sm[0];
    __syncthreads();
    float s1 = expf(row[t] - m) * (float)b_mask[bb * LL + t]
             + expf(row[t + 256] - m) * (float)b_mask[bb * LL + t + 256];
    sm[t] = s1; __syncthreads();
    for (int s = 128; s > 0; s >>= 1) {
        if (t < s) sm[t] += sm[t + s];
        __syncthreads();
    }
    if (t == 0) {
        rm[bb * LL + i] = m;
        rs[bb * LL + i] = 768.0f * (float)a_mask[bb * LL + i] * sm[0];
    }
}

__global__ void k_colstats(const float* __restrict__ att,
                           const int* __restrict__ a_mask, const int* __restrict__ b_mask,
                           float* __restrict__ cm, float* __restrict__ cs)
{
    const int bb = blockIdx.y;
    const int j = blockIdx.x * 128 + threadIdx.x;
    __shared__ float ams[LL];
    for (int i = threadIdx.x; i < LL; i += 128) ams[i] = (float)a_mask[bb * LL + i];
    __syncthreads();
    const float* base = att + (size_t)bb * LL * LL;
    float m = -1e30f;
    for (int i = 0; i < LL; i++) m = fmaxf(m, base[(size_t)i * LL + j]);
    float s = 0.f;
    for (int i = 0; i < LL; i++) s += expf(base[(size_t)i * LL + j] - m) * ams[i];
    cm[bb * LL + j] = m;
    cs[bb * LL + j] = 768.0f * (float)b_mask[bb * LL + j] * s;
}

__global__ void k_map(const float* __restrict__ att,
                      const int* __restrict__ a_mask, const int* __restrict__ b_mask,
                      const float* __restrict__ rm, const float* __restrict__ rs,
                      const float* __restrict__ cm, const float* __restrict__ cs,
                      float* __restrict__ S1, float* __restrict__ S2)
{
    const int i = blockIdx.x, bb = blockIdx.y;
    const size_t off = ((size_t)bb * LL + i) * LL;
    const float am = (float)a_mask[bb * LL + i];
    const float rmi = rm[bb * LL + i];
    const float rinv = 1.0f / (rs[bb * LL + i] + 1e-8f);
    const int t = threadIdx.x;
    for (int j = t; j < LL; j += 256) {
        float a = att[off + j];
        float mfac = 768.0f * am * (float)b_mask[bb * LL + j];
        S1[off + j] = expf(a - rmi) * mfac * rinv;
        S2[off + j] = expf(a - cm[bb * LL + j]) * mfac / (cs[bb * LL + j] + 1e-8f);
    }
}

__global__ void k_zero(float* __restrict__ out)
{
    int i = blockIdx.x * blockDim.x + threadIdx.x;
    if (i < BB * 4 * HH) out[i] = 0.0f;
}

extern "C" void kernel_launch(void* const* d_in, const int* in_sizes, int n_in,
                              void* d_out, int out_size)
{
    const float* a_embeds = (const float*)d_in[0];
    const float* b_embeds = (const float*)d_in[1];
    const int*   a_mask   = (const int*)d_in[2];
    const int*   b_mask   = (const int*)d_in[3];
    const float* Wp = (const float*)d_in[4];
    const float* bp = (const float*)d_in[5];
    const float* Wf = (const float*)d_in[6];
    const float* bf = (const float*)d_in[7];
    const float* Wg = (const float*)d_in[8];
    const float* bg = (const float*)d_in[9];
    float* out = (float*)d_out;

    float* base = nullptr;
    cudaGetSymbolAddress((void**)&base, g_scratch);
    float* ap    = base;
    float* bp_   = base + PLH;
    float* Fa    = base + 2 * PLH;
    float* Fb    = base + 3 * PLH;
    float* beta  = base + 4 * PLH;
    float* alpha = base + 5 * PLH;
    float* att   = base + 6 * PLH;
    float* S1    = att + ALL;
    float* S2    = S1 + ALL;
    float* rm    = S2 + ALL;
    float* rs    = rm + M_ROWS;
    float* cm    = rs + M_ROWS;
    float* cs    = cm + M_ROWS;

    k_zero<<<(BB * 4 * HH + 1023) / 1024, 1024>>>(out);

    // shared projection FFN
    k_proj<<<dim3(6, 256), 256>>>(a_embeds, Wp, bp, nullptr, ap, DD);
    k_proj<<<dim3(6, 256), 256>>>(b_embeds, Wp, bp, nullptr, bp_, DD);

    // attend features (relu + mask)
    k_proj<<<dim3(6, 256), 256>>>(ap, Wf, bf, a_mask, Fa, HH);
    k_proj<<<dim3(6, 256), 256>>>(bp_, Wf, bf, b_mask, Fb, HH);

    // attention scores
    k_att<<<dim3(4, 4, 64), 256>>>(Fa, Fb, att);

    // dual softmax
    k_rowstats<<<dim3(512, 64), 256>>>(att, a_mask, b_mask, rm, rs);
    k_colstats<<<dim3(4, 64), 128>>>(att, a_mask, b_mask, cm, cs);
    k_map<<<dim3(512, 64), 256>>>(att, a_mask, b_mask, rm, rs, cm, cs, S1, S2);

    // contexts
    k_ctx_nn<<<dim3(6, 4, 64), 256>>>(S1, bp_, beta);
    k_ctx_tn<<<dim3(6, 4, 64), 256>>>(S2, ap, alpha);

    // compare + aggregate (fused sum/max epilogue)
    k_cmp<<<dim3(6, 256), 256>>>(ap,  beta,  Wg, bg, a_mask, out, 0,   1536);
    k_cmp<<<dim3(6, 256), 256>>>(bp_, alpha, Wg, bg, b_mask, out, 768, 2304);
}

// round 3
// speedup vs baseline: 4.5240x; 1.0865x over previous
#include <cuda_runtime.h>
#include <stdint.h>
#include <math.h>

// Problem constants
#define BB 64
#define LL 512
#define DD 768
#define HH 768

#define BM 128
#define BN 128
#define BK 16

static const int    M_ROWS = BB * LL;                  // 32768
static const size_t PLH = (size_t)BB * LL * HH;        // 25165824
static const size_t ALL = (size_t)BB * LL * LL;        // 16777216
// 6*PLH + 3*ALL + 4*M_ROWS + weight copies (2*589824 + 1179648)
__device__ __align__(16) float g_scratch[6 * 25165824ULL + 3 * 16777216ULL + 4 * 32768ULL + 2359296ULL];

// ---------------------------------------------------------------------------
// helpers
// ---------------------------------------------------------------------------
__device__ __forceinline__ void cp16(void* s, const void* g) {
    uint32_t sa = (uint32_t)__cvta_generic_to_shared(s);
    asm volatile("cp.async.cg.shared.global [%0], [%1], 16;" :: "r"(sa), "l"(g));
}
__device__ __forceinline__ void cp_commit() { asm volatile("cp.async.commit_group;"); }
__device__ __forceinline__ void cp_wait1()  { asm volatile("cp.async.wait_group 1;"); }

__device__ __forceinline__ uint32_t f2tf(float x) {
    uint32_t r;
    asm("cvt.rna.tf32.f32 %0, %1;" : "=r"(r) : "f"(x));
    return r;
}
__device__ __forceinline__ float rtf(float x) { return __uint_as_float(f2tf(x)); }

__device__ __forceinline__ void mma8(float* c, const uint32_t* a, const uint32_t* b) {
    asm volatile(
        "mma.sync.aligned.m16n8k8.row.col.f32.tf32.tf32.f32 "
        "{%0,%1,%2,%3},{%4,%5,%6,%7},{%8,%9},{%0,%1,%2,%3};"
        : "+f"(c[0]), "+f"(c[1]), "+f"(c[2]), "+f"(c[3])
        : "r"(a[0]), "r"(a[1]), "r"(a[2]), "r"(a[3]), "r"(b[0]), "r"(b[1]));
}

// Fragment loaders. g = lane/4, q = lane%4. Operands are pre-rounded tf32 bits
// except CVT variant (raw fp32 inputs).
#define LA_MK_G(CV)                                                            \
    _Pragma("unroll")                                                          \
    for (int fm = 0; fm < 4; fm++) {                                           \
        int m = wm * 64 + fm * 16 + g;                                         \
        af[fm][0] = CV(As[buf][m][kk + q]);                                    \
        af[fm][1] = CV(As[buf][m + 8][kk + q]);                                \
        af[fm][2] = CV(As[buf][m][kk + q + 4]);                                \
        af[fm][3] = CV(As[buf][m + 8][kk + q + 4]);                            \
    }
#define LA_MK      LA_MK_G(__float_as_uint)
#define LA_MK_CVT  LA_MK_G(f2tf)
#define LB_KN                                                                  \
    _Pragma("unroll")                                                          \
    for (int fn = 0; fn < 4; fn++) {                                           \
        int n = wn * 32 + fn * 8 + g;                                          \
        bf_[fn][0] = __float_as_uint(Bs[buf][kk + q][n]);                      \
        bf_[fn][1] = __float_as_uint(Bs[buf][kk + q + 4][n]);                  \
    }
#define LB_NK                                                                  \
    _Pragma("unroll")                                                          \
    for (int fn = 0; fn < 4; fn++) {                                           \
        int n = wn * 32 + fn * 8 + g;                                          \
        bf_[fn][0] = __float_as_uint(Bs[buf][n][kk + q]);                      \
        bf_[fn][1] = __float_as_uint(Bs[buf][n][kk + q + 4]);                  \
    }

#define COMPUTE_TILE(LOADA, LOADB)                                             \
    _Pragma("unroll")                                                          \
    for (int ks = 0; ks < 2; ks++) {                                           \
        const int kk = ks * 8;                                                 \
        uint32_t af[4][4], bf_[4][2];                                          \
        LOADA                                                                  \
        LOADB                                                                  \
        _Pragma("unroll")                                                      \
        for (int fm = 0; fm < 4; fm++)                                         \
            _Pragma("unroll")                                                  \
            for (int fn = 0; fn < 4; fn++)                                     \
                mma8(acc[fm][fn], af[fm], bf_[fn]);                            \
    }

static const int PROJ_SMEM = (3 * BM * 20 + 3 * BK * 136) * 4;   // 56832
static const int ATT_SMEM  = (3 * BM * 20 + 3 * BN * 20) * 4;    // 61440

// ---------------------------------------------------------------------------
// weight pre-convert: dst = tf32_round(src)
// ---------------------------------------------------------------------------
__global__ void k_cvt(const float* __restrict__ src, float* __restrict__ dst, int n)
{
    int i = blockIdx.x * blockDim.x + threadIdx.x;
    if (i < n) dst[i] = rtf(src[i]);
}

// ---------------------------------------------------------------------------
// proj / attend-F: C = rtf(relu(A[M,K] @ W[K,768] + bias) * mask)
// ---------------------------------------------------------------------------
template<bool CVTA>
__global__ __launch_bounds__(256, 2) void k_proj(
    const float* __restrict__ A, const float* __restrict__ W,
    const float* __restrict__ bias, const int* __restrict__ mask,
    float* __restrict__ C, int K)
{
    extern __shared__ float dsm[];
    float (*As)[BM][20]  = (float(*)[BM][20])dsm;
    float (*Bs)[BK][136] = (float(*)[BK][136])(dsm + 3 * BM * 20);
    const int t = threadIdx.x;
    const int w = t >> 5, l = t & 31, g = l >> 2, q = l & 3;
    const int wm = w >> 2, wn = w & 3;
    const int m0 = blockIdx.y * BM, n0 = blockIdx.x * BN;
    const int ar = t >> 2, ac = (t & 3) * 4;
    const int brk = t >> 5, bcn = (t & 31) * 4;
    float acc[4][4][4] = {};
    const int nt = K / BK;
#define LOADT(st, k0)                                                                          \
    do {                                                                                       \
        _Pragma("unroll")                                                                      \
        for (int i = 0; i < 2; i++)                                                            \
            cp16(&As[st][ar + 64 * i][ac], A + (size_t)(m0 + ar + 64 * i) * K + (k0) + ac);    \
        _Pragma("unroll")                                                                      \
        for (int i = 0; i < 2; i++)                                                            \
            cp16(&Bs[st][brk + 8 * i][bcn], W + (size_t)((k0) + brk + 8 * i) * HH + n0 + bcn); \
    } while (0)
    LOADT(0, 0);  cp_commit();
    LOADT(1, BK); cp_commit();
    int buf = 0;
    for (int kt = 0; kt < nt; kt++) {
        cp_wait1();
        __syncthreads();
        if (kt + 2 < nt) {
            int st = buf - 1; if (st < 0) st += 3;   // (kt+2)%3
            LOADT(st, (kt + 2) * BK);
        }
        cp_commit();
        if constexpr (CVTA) { COMPUTE_TILE(LA_MK_CVT, LB_KN) }
        else                { COMPUTE_TILE(LA_MK,     LB_KN) }
        if (++buf == 3) buf = 0;
    }
#undef LOADT
    const int mbase = m0 + wm * 64, nbase = n0 + wn * 32;
#pragma unroll
    for (int fm = 0; fm < 4; fm++) {
        int m = mbase + fm * 16 + g;
        float mk0 = mask ? (float)mask[m] : 1.0f;
        float mk1 = mask ? (float)mask[m + 8] : 1.0f;
#pragma unroll
        for (int fn = 0; fn < 4; fn++) {
            int n = nbase + fn * 8 + 2 * q;
            float b0 = bias[n], b1 = bias[n + 1];
            float2 v0 = make_float2(rtf(fmaxf(acc[fm][fn][0] + b0, 0.f) * mk0),
                                    rtf(fmaxf(acc[fm][fn][1] + b1, 0.f) * mk0));
            float2 v1 = make_float2(rtf(fmaxf(acc[fm][fn][2] + b0, 0.f) * mk1),
                                    rtf(fmaxf(acc[fm][fn][3] + b1, 0.f) * mk1));
            *(float2*)&C[(size_t)m * HH + n] = v0;
            *(float2*)&C[(size_t)(m + 8) * HH + n] = v1;
        }
    }
}

// ---------------------------------------------------------------------------
// att[b,i,j] = Fa[b,i,:] . Fb[b,j,:]   (NT)
// ---------------------------------------------------------------------------
__global__ __launch_bounds__(256, 2) void k_att(
    const float* __restrict__ Fa, const float* __restrict__ Fb, float* __restrict__ att)
{
    extern __shared__ float dsm[];
    float (*As)[BM][20] = (float(*)[BM][20])dsm;
    float (*Bs)[BN][20] = (float(*)[BN][20])(dsm + 3 * BM * 20);
    const int t = threadIdx.x;
    const int w = t >> 5, l = t & 31, g = l >> 2, q = l & 3;
    const int wm = w >> 2, wn = w & 3;
    const int b = blockIdx.z;
    const int m0 = blockIdx.y * BM, n0 = blockIdx.x * BN;
    const float* Ab = Fa + (size_t)b * LL * HH;
    const float* Bb = Fb + (size_t)b * LL * HH;
    const int ar = t >> 2, ac = (t & 3) * 4;
    float acc[4][4][4] = {};
    const int nt = HH / BK;
#define LOADT(st, k0)                                                                           \
    do {                                                                                        \
        _Pragma("unroll")                                                                       \
        for (int i = 0; i < 2; i++)                                                             \
            cp16(&As[st][ar + 64 * i][ac], Ab + (size_t)(m0 + ar + 64 * i) * HH + (k0) + ac);   \
        _Pragma("unroll")                                                                       \
        for (int i = 0; i < 2; i++)                                                             \
            cp16(&Bs[st][ar + 64 * i][ac], Bb + (size_t)(n0 + ar + 64 * i) * HH + (k0) + ac);   \
    } while (0)
    LOADT(0, 0);  cp_commit();
    LOADT(1, BK); cp_commit();
    int buf = 0;
    for (int kt = 0; kt < nt; kt++) {
        cp_wait1();
        __syncthreads();
        if (kt + 2 < nt) {
            int st = buf - 1; if (st < 0) st += 3;
            LOADT(st, (kt + 2) * BK);
        }
        cp_commit();
        COMPUTE_TILE(LA_MK, LB_NK)
        if (++buf == 3) buf = 0;
    }
#undef LOADT
    const int mbase = m0 + wm * 64, nbase = n0 + wn * 32;
#pragma unroll
    for (int fm = 0; fm < 4; fm++) {
        int m = mbase + fm * 16 + g;
#pragma unroll
        for (int fn = 0; fn < 4; fn++) {
            int n = nbase + fn * 8 + 2 * q;
            *(float2*)&att[((size_t)b * LL + m) * LL + n] =
                make_float2(acc[fm][fn][0], acc[fm][fn][1]);
            *(float2*)&att[((size_t)b * LL + m + 8) * LL + n] =
                make_float2(acc[fm][fn][2], acc[fm][fn][3]);
        }
    }
}

// ---------------------------------------------------------------------------
// ctx (NN, K=512): C[b] = rtf(S[b] @ P[b]);  used for both beta and alpha
// ---------------------------------------------------------------------------
__global__ __launch_bounds__(256, 2) void k_ctx_nn(
    const float* __restrict__ S, const float* __restrict__ Pb, float* __restrict__ C)
{
    extern __shared__ float dsm[];
    float (*As)[BM][20]  = (float(*)[BM][20])dsm;
    float (*Bs)[BK][136] = (float(*)[BK][136])(dsm + 3 * BM * 20);
    const int t = threadIdx.x;
    const int w = t >> 5, l = t & 31, g = l >> 2, q = l & 3;
    const int wm = w >> 2, wn = w & 3;
    const int b = blockIdx.z;
    const int m0 = blockIdx.y * BM, n0 = blockIdx.x * BN;
    const float* Ab = S + (size_t)b * LL * LL;
    const float* Bb = Pb + (size_t)b * LL * HH;
    const int ar = t >> 2, ac = (t & 3) * 4;
    const int brk = t >> 5, bcn = (t & 31) * 4;
    float acc[4][4][4] = {};
    const int nt = LL / BK;
#define LOADT(st, k0)                                                                           \
    do {                                                                                        \
        _Pragma("unroll")                                                                       \
        for (int i = 0; i < 2; i++)                                                             \
            cp16(&As[st][ar + 64 * i][ac], Ab + (size_t)(m0 + ar + 64 * i) * LL + (k0) + ac);   \
        _Pragma("unroll")                                                                       \
        for (int i = 0; i < 2; i++)                                                             \
            cp16(&Bs[st][brk + 8 * i][bcn], Bb + (size_t)((k0) + brk + 8 * i) * HH + n0 + bcn); \
    } while (0)
    LOADT(0, 0);  cp_commit();
    LOADT(1, BK); cp_commit();
    int buf = 0;
    for (int kt = 0; kt < nt; kt++) {
        cp_wait1();
        __syncthreads();
        if (kt + 2 < nt) {
            int st = buf - 1; if (st < 0) st += 3;
            LOADT(st, (kt + 2) * BK);
        }
        cp_commit();
        COMPUTE_TILE(LA_MK, LB_KN)
        if (++buf == 3) buf = 0;
    }
#undef LOADT
    const int mbase = m0 + wm * 64, nbase = n0 + wn * 32;
#pragma unroll
    for (int fm = 0; fm < 4; fm++) {
        int m = mbase + fm * 16 + g;
#pragma unroll
        for (int fn = 0; fn < 4; fn++) {
            int n = nbase + fn * 8 + 2 * q;
            *(float2*)&C[((size_t)b * LL + m) * HH + n] =
                make_float2(rtf(acc[fm][fn][0]), rtf(acc[fm][fn][1]));
            *(float2*)&C[((size_t)b * LL + m + 8) * HH + n] =
                make_float2(rtf(acc[fm][fn][2]), rtf(acc[fm][fn][3]));
        }
    }
}

// ---------------------------------------------------------------------------
// compare + aggregate: v = relu([P|CTX] @ Wg + bg) * mask; out += sum / max
// ---------------------------------------------------------------------------
__global__ __launch_bounds__(256, 2) void k_cmp(
    const float* __restrict__ P, const float* __restrict__ CTX,
    const float* __restrict__ Wg, const float* __restrict__ bg,
    const int* __restrict__ mask, float* __restrict__ out,
    int sumoff, int maxoff)
{
    extern __shared__ float dsm[];
    float (*As)[BM][20]  = (float(*)[BM][20])dsm;
    float (*Bs)[BK][136] = (float(*)[BK][136])(dsm + 3 * BM * 20);
    __shared__ float red_s[128][2];
    __shared__ float red_m[128][2];
    const int t = threadIdx.x;
    const int w = t >> 5, l = t & 31, g = l >> 2, q = l & 3;
    const int wm = w >> 2, wn = w & 3;
    const int m0 = blockIdx.y * BM, n0 = blockIdx.x * BN;
    const int ar = t >> 2, ac = (t & 3) * 4;
    const int brk = t >> 5, bcn = (t & 31) * 4;
    float acc[4][4][4] = {};
    const int nt = (2 * HH) / BK;   // 96
#define LOADT(st, k0)                                                                            \
    do {                                                                                         \
        const float* Asrc = ((k0) < HH) ? P : CTX;                                               \
        const int kk0 = ((k0) < HH) ? (k0) : ((k0) - HH);                                        \
        _Pragma("unroll")                                                                        \
        for (int i = 0; i < 2; i++)                                                              \
            cp16(&As[st][ar + 64 * i][ac], Asrc + (size_t)(m0 + ar + 64 * i) * HH + kk0 + ac);   \
        _Pragma("unroll")                                                                        \
        for (int i = 0; i < 2; i++)                                                              \
            cp16(&Bs[st][brk + 8 * i][bcn], Wg + (size_t)((k0) + brk + 8 * i) * HH + n0 + bcn);  \
    } while (0)
    LOADT(0, 0);  cp_commit();
    LOADT(1, BK); cp_commit();
    int buf = 0;
    for (int kt = 0; kt < nt; kt++) {
        cp_wait1();
        __syncthreads();
        if (kt + 2 < nt) {
            int st = buf - 1; if (st < 0) st += 3;
            LOADT(st, (kt + 2) * BK);
        }
        cp_commit();
        COMPUTE_TILE(LA_MK, LB_KN)
        if (++buf == 3) buf = 0;
    }
#undef LOADT
    const int mbase = m0 + wm * 64, nbase = n0 + wn * 32;
    float psum[4][2] = {}, pmax[4][2] = {};
#pragma unroll
    for (int fm = 0; fm < 4; fm++) {
        int m = mbase + fm * 16 + g;
        float mk0 = (float)mask[m];
        float mk1 = (float)mask[m + 8];
#pragma unroll
        for (int fn = 0; fn < 4; fn++) {
            int n = nbase + fn * 8 + 2 * q;
            float b0 = bg[n], b1 = bg[n + 1];
            float v00 = fmaxf(acc[fm][fn][0] + b0, 0.f) * mk0;
            float v01 = fmaxf(acc[fm][fn][1] + b1, 0.f) * mk0;
            float v10 = fmaxf(acc[fm][fn][2] + b0, 0.f) * mk1;
            float v11 = fmaxf(acc[fm][fn][3] + b1, 0.f) * mk1;
            psum[fn][0] += v00 + v10;
            psum[fn][1] += v01 + v11;
            pmax[fn][0] = fmaxf(pmax[fn][0], fmaxf(v00, v10));
            pmax[fn][1] = fmaxf(pmax[fn][1], fmaxf(v01, v11));
        }
    }
#pragma unroll
    for (int fn = 0; fn < 4; fn++)
#pragma unroll
        for (int e = 0; e < 2; e++) {
#pragma unroll
            for (int o = 4; o < 32; o <<= 1) {
                psum[fn][e] += __shfl_xor_sync(0xffffffffu, psum[fn][e], o);
                pmax[fn][e] = fmaxf(pmax[fn][e], __shfl_xor_sync(0xffffffffu, pmax[fn][e], o));
            }
        }
    if (l < 4) {
#pragma unroll
        for (int fn = 0; fn < 4; fn++)
#pragma unroll
            for (int e = 0; e < 2; e++) {
                int c = wn * 32 + fn * 8 + 2 * q + e;
                red_s[c][wm] = psum[fn][e];
                red_m[c][wm] = pmax[fn][e];
            }
    }
    __syncthreads();
    if (t < 128) {
        const int bb = m0 >> 9;
        float s = red_s[t][0] + red_s[t][1];
        float mx = fmaxf(red_m[t][0], red_m[t][1]);
        atomicAdd(&out[bb * 3072 + sumoff + n0 + t], s);
        atomicMax((int*)&out[bb * 3072 + maxoff + n0 + t], __float_as_int(mx));
    }
}

// ---------------------------------------------------------------------------
// softmax stats
// ---------------------------------------------------------------------------
__global__ void k_rowstats(const float* __restrict__ att,
                           const int* __restrict__ a_mask, const int* __restrict__ b_mask,
                           float* __restrict__ rm, float* __restrict__ rs)
{
    const int i = blockIdx.x, bb = blockIdx.y;
    const float* row = att + ((size_t)bb * LL + i) * LL;
    const int t = threadIdx.x;
    __shared__ float sm[256];
    float m = fmaxf(row[t], row[t + 256]);
    sm[t] = m; __syncthreads();
    for (int s = 128; s > 0; s >>= 1) {
        if (t < s) sm[t] = fmaxf(sm[t], sm[t + s]);
        __syncthreads();
    }
    m = sm[0];
    __syncthreads();
    float s1 = expf(row[t] - m) * (float)b_mask[bb * LL + t]
             + expf(row[t + 256] - m) * (float)b_mask[bb * LL + t + 256];
    sm[t] = s1; __syncthreads();
    for (int s = 128; s > 0; s >>= 1) {
        if (t < s) sm[t] += sm[t + s];
        __syncthreads();
    }
    if (t == 0) {
        rm[bb * LL + i] = m;
        rs[bb * LL + i] = 768.0f * (float)a_mask[bb * LL + i] * sm[0];
    }
}

__global__ void k_colstats(const float* __restrict__ att,
                           const int* __restrict__ a_mask, const int* __restrict__ b_mask,
                           float* __restrict__ cm, float* __restrict__ cs)
{
    const int bb = blockIdx.y;
    const int j = blockIdx.x * 128 + threadIdx.x;
    __shared__ float ams[LL];
    for (int i = threadIdx.x; i < LL; i += 128) ams[i] = (float)a_mask[bb * LL + i];
    __syncthreads();
    const float* base = att + (size_t)bb * LL * LL;
    float m = -1e30f;
    for (int i = 0; i < LL; i++) m = fmaxf(m, base[(size_t)i * LL + j]);
    float s = 0.f;
    for (int i = 0; i < LL; i++) s += expf(base[(size_t)i * LL + j] - m) * ams[i];
    cm[bb * LL + j] = m;
    cs[bb * LL + j] = 768.0f * (float)b_mask[bb * LL + j] * s;
}

// map att -> S1 [b,i,j] and S2t [b,j,i] (transposed via smem tiles)
__global__ void k_map(const float* __restrict__ att,
                      const int* __restrict__ a_mask, const int* __restrict__ b_mask,
                      const float* __restrict__ rm, const float* __restrict__ rs,
                      const float* __restrict__ cm, const float* __restrict__ cs,
                      float* __restrict__ S1, float* __restrict__ S2t)
{
    const int bb = blockIdx.z;
    const int i0 = blockIdx.y * 32, j0 = blockIdx.x * 32;
    const int tx = threadIdx.x, ty = threadIdx.y;
    __shared__ float s2t[32][33];
    const int j = j0 + tx;
    const float cmv = cm[bb * LL + j];
    const float cinv = 1.0f / (cs[bb * LL + j] + 1e-8f);
    const float bmv = 768.0f * (float)b_mask[bb * LL + j];
    for (int r = ty; r < 32; r += 8) {
        const int i = i0 + r;
        const float a = att[((size_t)bb * LL + i) * LL + j];
        const float mfac = bmv * (float)a_mask[bb * LL + i];
        const float rinv = 1.0f / (rs[bb * LL + i] + 1e-8f);
        S1[((size_t)bb * LL + i) * LL + j] = rtf(expf(a - rm[bb * LL + i]) * mfac * rinv);
        s2t[tx][r] = expf(a - cmv) * mfac * cinv;
    }
    __syncthreads();
    for (int r = ty; r < 32; r += 8)
        S2t[((size_t)bb * LL + j0 + r) * LL + i0 + tx] = rtf(s2t[r][tx]);
}

__global__ void k_zero(float* __restrict__ out)
{
    int i = blockIdx.x * blockDim.x + threadIdx.x;
    if (i < BB * 4 * HH) out[i] = 0.0f;
}

extern "C" void kernel_launch(void* const* d_in, const int* in_sizes, int n_in,
                              void* d_out, int out_size)
{
    const float* a_embeds = (const float*)d_in[0];
    const float* b_embeds = (const float*)d_in[1];
    const int*   a_mask   = (const int*)d_in[2];
    const int*   b_mask   = (const int*)d_in[3];
    const float* Wp = (const float*)d_in[4];
    const float* bp = (const float*)d_in[5];
    const float* Wf = (const float*)d_in[6];
    const float* bf = (const float*)d_in[7];
    const float* Wg = (const float*)d_in[8];
    const float* bg = (const float*)d_in[9];
    float* out = (float*)d_out;

    float* base = nullptr;
    cudaGetSymbolAddress((void**)&base, g_scratch);
    float* ap    = base;
    float* bp_   = base + PLH;
    float* Fa    = base + 2 * PLH;
    float* Fb    = base + 3 * PLH;
    float* beta  = base + 4 * PLH;
    float* alpha = base + 5 * PLH;
    float* att   = base + 6 * PLH;
    float* S1    = att + ALL;
    float* S2t   = S1 + ALL;
    float* rm    = S2t + ALL;
    float* rs    = rm + M_ROWS;
    float* cm    = rs + M_ROWS;
    float* cs    = cm + M_ROWS;
    float* wWp   = cs + M_ROWS;
    float* wWf   = wWp + DD * HH;
    float* wWg   = wWf + HH * HH;

    // allow >48KB dynamic smem (idempotent host calls; not part of the graph)
    cudaFuncSetAttribute(k_proj<true>,  cudaFuncAttributeMaxDynamicSharedMemorySize, PROJ_SMEM);
    cudaFuncSetAttribute(k_proj<false>, cudaFuncAttributeMaxDynamicSharedMemorySize, PROJ_SMEM);
    cudaFuncSetAttribute(k_att,         cudaFuncAttributeMaxDynamicSharedMemorySize, ATT_SMEM);
    cudaFuncSetAttribute(k_ctx_nn,      cudaFuncAttributeMaxDynamicSharedMemorySize, PROJ_SMEM);
    cudaFuncSetAttribute(k_cmp,         cudaFuncAttributeMaxDynamicSharedMemorySize, PROJ_SMEM);

    k_zero<<<(BB * 4 * HH + 1023) / 1024, 1024>>>(out);

    // pre-round weights to tf32
    k_cvt<<<(DD * HH + 511) / 512, 512>>>(Wp, wWp, DD * HH);
    k_cvt<<<(HH * HH + 511) / 512, 512>>>(Wf, wWf, HH * HH);
    k_cvt<<<(2 * HH * HH + 511) / 512, 512>>>(Wg, wWg, 2 * HH * HH);

    // shared projection FFN (A raw -> CVTA=true)
    k_proj<true><<<dim3(6, 256), 256, PROJ_SMEM>>>(a_embeds, wWp, bp, nullptr, ap, DD);
    k_proj<true><<<dim3(6, 256), 256, PROJ_SMEM>>>(b_embeds, wWp, bp, nullptr, bp_, DD);

    // attend features (relu + mask); A pre-rounded
    k_proj<false><<<dim3(6, 256), 256, PROJ_SMEM>>>(ap, wWf, bf, a_mask, Fa, HH);
    k_proj<false><<<dim3(6, 256), 256, PROJ_SMEM>>>(bp_, wWf, bf, b_mask, Fb, HH);

    // attention scores
    k_att<<<dim3(4, 4, 64), 256, ATT_SMEM>>>(Fa, Fb, att);

    // dual softmax
    k_rowstats<<<dim3(512, 64), 256>>>(att, a_mask, b_mask, rm, rs);
    k_colstats<<<dim3(4, 64), 128>>>(att, a_mask, b_mask, cm, cs);
    k_map<<<dim3(16, 16, 64), dim3(32, 8)>>>(att, a_mask, b_mask, rm, rs, cm, cs, S1, S2t);

    // contexts (both NN now)
    k_ctx_nn<<<dim3(6, 4, 64), 256, PROJ_SMEM>>>(S1, bp_, beta);
    k_ctx_nn<<<dim3(6, 4, 64), 256, PROJ_SMEM>>>(S2t, ap, alpha);

    // compare + aggregate (fused sum/max epilogue)
    k_cmp<<<dim3(6, 256), 256, PROJ_SMEM>>>(ap,  beta,  wWg, bg, a_mask, out, 0,   1536);
    k_cmp<<<dim3(6, 256), 256, PROJ_SMEM>>>(bp_, alpha, wWg, bg, b_mask, out, 768, 2304);
}

// round 4
// speedup vs baseline: 8.6179x; 1.9049x over previous
#include <cuda_runtime.h>
#include <cuda_fp16.h>
#include <stdint.h>
#include <math.h>

// Problem constants
#define BB 64
#define LL 512
#define DD 768
#define HH 768

#define BM 128
#define BN 128
#define BK 16

static const int    M_ROWS = BB * LL;                  // 32768
static const size_t PLH = (size_t)BB * LL * HH;        // 25165824
static const size_t ALL = (size_t)BB * LL * LL;        // 16777216

// big scratch: att(f32) + stats + half buffers
__device__ __align__(16) float g_scratch[6 * 25165824ULL + 3 * 16777216ULL + 4 * 32768ULL + 2359296ULL];

// ---------------------------------------------------------------------------
// helpers
// ---------------------------------------------------------------------------
__device__ __forceinline__ void cp16(void* s, const void* g) {
    uint32_t sa = (uint32_t)__cvta_generic_to_shared(s);
    asm volatile("cp.async.cg.shared.global [%0], [%1], 16;" :: "r"(sa), "l"(g));
}
__device__ __forceinline__ void cp_commit() { asm volatile("cp.async.commit_group;"); }
__device__ __forceinline__ void cp_wait1()  { asm volatile("cp.async.wait_group 1;"); }

__device__ __forceinline__ void ldsm_x4(uint32_t* r, uint32_t addr) {
    asm volatile("ldmatrix.sync.aligned.m8n8.x4.shared.b16 {%0,%1,%2,%3}, [%4];"
        : "=r"(r[0]), "=r"(r[1]), "=r"(r[2]), "=r"(r[3]) : "r"(addr));
}
__device__ __forceinline__ void ldsm_x4t(uint32_t* r, uint32_t addr) {
    asm volatile("ldmatrix.sync.aligned.m8n8.x4.trans.shared.b16 {%0,%1,%2,%3}, [%4];"
        : "=r"(r[0]), "=r"(r[1]), "=r"(r[2]), "=r"(r[3]) : "r"(addr));
}
__device__ __forceinline__ void mma16(float* c, const uint32_t* a, const uint32_t* b) {
    asm volatile(
        "mma.sync.aligned.m16n8k16.row.col.f32.f16.f16.f32 "
        "{%0,%1,%2,%3},{%4,%5,%6,%7},{%8,%9},{%0,%1,%2,%3};"
        : "+f"(c[0]), "+f"(c[1]), "+f"(c[2]), "+f"(c[3])
        : "r"(a[0]), "r"(a[1]), "r"(a[2]), "r"(a[3]), "r"(b[0]), "r"(b[1]));
}

// A tile stage size: 128*24*2 = 6144B. B KN tile stage: 16*136*2 = 4352B.
// n-major B tile (att): 128*24*2 = 6144B.
#define A_STG 6144u
#define B_STG 4352u

// lane-address offsets (computed per kernel):
//   a_addr = a_base + ((wm*64 + (l&7) + ((l&8)?8:0))*24 + ((l&16)?8:0))*2   (+fm*768)
//   b_addr = b_base + (((l&7) + ((l&8)?8:0))*136 + wn*32 + ((l&16)?8:0))*2  (+32 for 2nd)
//   bn_addr= b_base + ((wn*32 + (l&7) + ((l&8)?8:0))*24 + ((l&16)?8:0))*2   (+768 for 2nd)

#define COMPUTE16_KN(buf)                                                      \
    do {                                                                       \
        uint32_t af[4][4], bt0[4], bt1[4];                                     \
        _Pragma("unroll")                                                      \
        for (int fm = 0; fm < 4; fm++)                                         \
            ldsm_x4(af[fm], a_addr + (buf) * A_STG + fm * 768u);               \
        ldsm_x4t(bt0, b_addr + (buf) * B_STG);                                 \
        ldsm_x4t(bt1, b_addr + (buf) * B_STG + 32u);                           \
        uint32_t bf[4][2] = {{bt0[0], bt0[1]}, {bt0[2], bt0[3]},               \
                             {bt1[0], bt1[1]}, {bt1[2], bt1[3]}};              \
        _Pragma("unroll")                                                      \
        for (int fm = 0; fm < 4; fm++)                                         \
            _Pragma("unroll")                                                  \
            for (int fn = 0; fn < 4; fn++)                                     \
                mma16(acc[fm][fn], af[fm], bf[fn]);                            \
    } while (0)

#define COMPUTE16_NT(buf)                                                      \
    do {                                                                       \
        uint32_t af[4][4], bt0[4], bt1[4];                                     \
        _Pragma("unroll")                                                      \
        for (int fm = 0; fm < 4; fm++)                                         \
            ldsm_x4(af[fm], a_addr + (buf) * A_STG + fm * 768u);               \
        ldsm_x4(bt0, bn_addr + (buf) * A_STG);                                 \
        ldsm_x4(bt1, bn_addr + (buf) * A_STG + 768u);                          \
        uint32_t bf[4][2] = {{bt0[0], bt0[2]}, {bt0[1], bt0[3]},               \
                             {bt1[0], bt1[2]}, {bt1[1], bt1[3]}};              \
        _Pragma("unroll")                                                      \
        for (int fm = 0; fm < 4; fm++)                                         \
            _Pragma("unroll")                                                  \
            for (int fn = 0; fn < 4; fn++)                                     \
                mma16(acc[fm][fn], af[fm], bf[fn]);                            \
    } while (0)

#define LANE_SETUP                                                             \
    const int t = threadIdx.x;                                                 \
    const int w = t >> 5, l = t & 31, g = l >> 2, q = l & 3;                   \
    const int wm = w >> 2, wn = w & 3;

// ---------------------------------------------------------------------------
// fp32 -> fp16 convert (vectorized)
// ---------------------------------------------------------------------------
__global__ void k_cvth(const float* __restrict__ src, __half* __restrict__ dst, int n)
{
    int i = (blockIdx.x * blockDim.x + threadIdx.x) * 4;
    if (i < n) {
        float4 v = *(const float4*)(src + i);
        *(half2*)(dst + i)     = __floats2half2_rn(v.x, v.y);
        *(half2*)(dst + i + 2) = __floats2half2_rn(v.z, v.w);
    }
}

// ---------------------------------------------------------------------------
// proj / attend-F: C = half(relu(A[M,K] @ W[K,768] + bias) * mask)
// ---------------------------------------------------------------------------
__global__ __launch_bounds__(256, 2) void k_proj(
    const __half* __restrict__ A, const __half* __restrict__ W,
    const float* __restrict__ bias, const int* __restrict__ mask,
    __half* __restrict__ C, int K)
{
    __shared__ __half As[3][BM][24];
    __shared__ __half Bs[3][BK][136];
    LANE_SETUP
    const int m0 = blockIdx.y * BM, n0 = blockIdx.x * BN;
    const uint32_t a_base = (uint32_t)__cvta_generic_to_shared(&As[0][0][0]);
    const uint32_t b_base = (uint32_t)__cvta_generic_to_shared(&Bs[0][0][0]);
    const uint32_t a_addr = a_base + (((wm * 64 + (l & 7) + ((l & 8) ? 8 : 0)) * 24 + ((l & 16) ? 8 : 0)) << 1);
    const uint32_t b_addr = b_base + ((((l & 7) + ((l & 8) ? 8 : 0)) * 136 + wn * 32 + ((l & 16) ? 8 : 0)) << 1);
    const int ar = t >> 1, ach = (t & 1) * 8;
    const int br = t >> 4, bch = (t & 15) * 8;
    float acc[4][4][4] = {};
    const int nt = K / BK;
#define LOADT(st, k0)                                                                      \
    do {                                                                                   \
        cp16(&As[st][ar][ach], A + (size_t)(m0 + ar) * K + (k0) + ach);                    \
        cp16(&Bs[st][br][bch], W + (size_t)((k0) + br) * HH + n0 + bch);                   \
    } while (0)
    LOADT(0, 0);  cp_commit();
    LOADT(1, BK); cp_commit();
    int buf = 0;
    for (int kt = 0; kt < nt; kt++) {
        cp_wait1();
        __syncthreads();
        if (kt + 2 < nt) {
            int st = buf - 1; if (st < 0) st += 3;
            LOADT(st, (kt + 2) * BK);
        }
        cp_commit();
        COMPUTE16_KN(buf);
        if (++buf == 3) buf = 0;
    }
#undef LOADT
    const int mbase = m0 + wm * 64, nbase = n0 + wn * 32;
#pragma unroll
    for (int fm = 0; fm < 4; fm++) {
        int m = mbase + fm * 16 + g;
        float mk0 = mask ? (float)mask[m] : 1.0f;
        float mk1 = mask ? (float)mask[m + 8] : 1.0f;
#pragma unroll
        for (int fn = 0; fn < 4; fn++) {
            int n = nbase + fn * 8 + 2 * q;
            float b0 = bias[n], b1 = bias[n + 1];
            *(half2*)&C[(size_t)m * HH + n] =
                __floats2half2_rn(fmaxf(acc[fm][fn][0] + b0, 0.f) * mk0,
                                  fmaxf(acc[fm][fn][1] + b1, 0.f) * mk0);
            *(half2*)&C[(size_t)(m + 8) * HH + n] =
                __floats2half2_rn(fmaxf(acc[fm][fn][2] + b0, 0.f) * mk1,
                                  fmaxf(acc[fm][fn][3] + b1, 0.f) * mk1);
        }
    }
}

// ---------------------------------------------------------------------------
// att[b,i,j] = Fa[b,i,:] . Fb[b,j,:]   (NT), fp32 output
// ---------------------------------------------------------------------------
__global__ __launch_bounds__(256, 2) void k_att(
    const __half* __restrict__ Fa, const __half* __restrict__ Fb, float* __restrict__ att)
{
    __shared__ __half As[3][BM][24];
    __shared__ __half Bs[3][BN][24];
    LANE_SETUP
    const int b = blockIdx.z;
    const int m0 = blockIdx.y * BM, n0 = blockIdx.x * BN;
    const __half* Ab = Fa + (size_t)b * LL * HH;
    const __half* Bb = Fb + (size_t)b * LL * HH;
    const uint32_t a_base = (uint32_t)__cvta_generic_to_shared(&As[0][0][0]);
    const uint32_t b_base = (uint32_t)__cvta_generic_to_shared(&Bs[0][0][0]);
    const uint32_t a_addr  = a_base + (((wm * 64 + (l & 7) + ((l & 8) ? 8 : 0)) * 24 + ((l & 16) ? 8 : 0)) << 1);
    const uint32_t bn_addr = b_base + (((wn * 32 + (l & 7) + ((l & 8) ? 8 : 0)) * 24 + ((l & 16) ? 8 : 0)) << 1);
    const int ar = t >> 1, ach = (t & 1) * 8;
    float acc[4][4][4] = {};
    const int nt = HH / BK;
#define LOADT(st, k0)                                                                      \
    do {                                                                                   \
        cp16(&As[st][ar][ach], Ab + (size_t)(m0 + ar) * HH + (k0) + ach);                  \
        cp16(&Bs[st][ar][ach], Bb + (size_t)(n0 + ar) * HH + (k0) + ach);                  \
    } while (0)
    LOADT(0, 0);  cp_commit();
    LOADT(1, BK); cp_commit();
    int buf = 0;
    for (int kt = 0; kt < nt; kt++) {
        cp_wait1();
        __syncthreads();
        if (kt + 2 < nt) {
            int st = buf - 1; if (st < 0) st += 3;
            LOADT(st, (kt + 2) * BK);
        }
        cp_commit();
        COMPUTE16_NT(buf);
        if (++buf == 3) buf = 0;
    }
#undef LOADT
    const int mbase = m0 + wm * 64, nbase = n0 + wn * 32;
#pragma unroll
    for (int fm = 0; fm < 4; fm++) {
        int m = mbase + fm * 16 + g;
#pragma unroll
        for (int fn = 0; fn < 4; fn++) {
            int n = nbase + fn * 8 + 2 * q;
            *(float2*)&att[((size_t)b * LL + m) * LL + n] =
                make_float2(acc[fm][fn][0], acc[fm][fn][1]);
            *(float2*)&att[((size_t)b * LL + m + 8) * LL + n] =
                make_float2(acc[fm][fn][2], acc[fm][fn][3]);
        }
    }
}

// ---------------------------------------------------------------------------
// ctx (NN, K=512): C[b] = half(S[b] @ P[b])
// ---------------------------------------------------------------------------
__global__ __launch_bounds__(256, 2) void k_ctx(
    const __half* __restrict__ S, const __half* __restrict__ Pb, __half* __restrict__ C)
{
    __shared__ __half As[3][BM][24];
    __shared__ __half Bs[3][BK][136];
    LANE_SETUP
    const int b = blockIdx.z;
    const int m0 = blockIdx.y * BM, n0 = blockIdx.x * BN;
    const __half* Ab = S + (size_t)b * LL * LL;
    const __half* Bb = Pb + (size_t)b * LL * HH;
    const uint32_t a_base = (uint32_t)__cvta_generic_to_shared(&As[0][0][0]);
    const uint32_t b_base = (uint32_t)__cvta_generic_to_shared(&Bs[0][0][0]);
    const uint32_t a_addr = a_base + (((wm * 64 + (l & 7) + ((l & 8) ? 8 : 0)) * 24 + ((l & 16) ? 8 : 0)) << 1);
    const uint32_t b_addr = b_base + ((((l & 7) + ((l & 8) ? 8 : 0)) * 136 + wn * 32 + ((l & 16) ? 8 : 0)) << 1);
    const int ar = t >> 1, ach = (t & 1) * 8;
    const int br = t >> 4, bch = (t & 15) * 8;
    float acc[4][4][4] = {};
    const int nt = LL / BK;
#define LOADT(st, k0)                                                                      \
    do {                                                                                   \
        cp16(&As[st][ar][ach], Ab + (size_t)(m0 + ar) * LL + (k0) + ach);                  \
        cp16(&Bs[st][br][bch], Bb + (size_t)((k0) + br) * HH + n0 + bch);                  \
    } while (0)
    LOADT(0, 0);  cp_commit();
    LOADT(1, BK); cp_commit();
    int buf = 0;
    for (int kt = 0; kt < nt; kt++) {
        cp_wait1();
        __syncthreads();
        if (kt + 2 < nt) {
            int st = buf - 1; if (st < 0) st += 3;
            LOADT(st, (kt + 2) * BK);
        }
        cp_commit();
        COMPUTE16_KN(buf);
        if (++buf == 3) buf = 0;
    }
#undef LOADT
    const int mbase = m0 + wm * 64, nbase = n0 + wn * 32;
#pragma unroll
    for (int fm = 0; fm < 4; fm++) {
        int m = mbase + fm * 16 + g;
#pragma unroll
        for (int fn = 0; fn < 4; fn++) {
            int n = nbase + fn * 8 + 2 * q;
            *(half2*)&C[((size_t)b * LL + m) * HH + n] =
                __floats2half2_rn(acc[fm][fn][0], acc[fm][fn][1]);
            *(half2*)&C[((size_t)b * LL + m + 8) * HH + n] =
                __floats2half2_rn(acc[fm][fn][2], acc[fm][fn][3]);
        }
    }
}

// ---------------------------------------------------------------------------
// compare + aggregate: v = relu([P|CTX] @ Wg + bg) * mask; out += sum / max
// ---------------------------------------------------------------------------
__global__ __launch_bounds__(256, 2) void k_cmp(
    const __half* __restrict__ P, const __half* __restrict__ CTX,
    const __half* __restrict__ Wg, const float* __restrict__ bg,
    const int* __restrict__ mask, float* __restrict__ out,
    int sumoff, int maxoff)
{
    __shared__ __half As[3][BM][24];
    __shared__ __half Bs[3][BK][136];
    __shared__ float red_s[128][2];
    __shared__ float red_m[128][2];
    LANE_SETUP
    const int m0 = blockIdx.y * BM, n0 = blockIdx.x * BN;
    const uint32_t a_base = (uint32_t)__cvta_generic_to_shared(&As[0][0][0]);
    const uint32_t b_base = (uint32_t)__cvta_generic_to_shared(&Bs[0][0][0]);
    const uint32_t a_addr = a_base + (((wm * 64 + (l & 7) + ((l & 8) ? 8 : 0)) * 24 + ((l & 16) ? 8 : 0)) << 1);
    const uint32_t b_addr = b_base + ((((l & 7) + ((l & 8) ? 8 : 0)) * 136 + wn * 32 + ((l & 16) ? 8 : 0)) << 1);
    const int ar = t >> 1, ach = (t & 1) * 8;
    const int br = t >> 4, bch = (t & 15) * 8;
    float acc[4][4][4] = {};
    const int nt = (2 * HH) / BK;   // 96
#define LOADT(st, k0)                                                                      \
    do {                                                                                   \
        const __half* Asrc = ((k0) < HH) ? P : CTX;                                        \
        const int kk0 = ((k0) < HH) ? (k0) : ((k0) - HH);                                  \
        cp16(&As[st][ar][ach], Asrc + (size_t)(m0 + ar) * HH + kk0 + ach);                 \
        cp16(&Bs[st][br][bch], Wg + (size_t)((k0) + br) * HH + n0 + bch);                  \
    } while (0)
    LOADT(0, 0);  cp_commit();
    LOADT(1, BK); cp_commit();
    int buf = 0;
    for (int kt = 0; kt < nt; kt++) {
        cp_wait1();
        __syncthreads();
        if (kt + 2 < nt) {
            int st = buf - 1; if (st < 0) st += 3;
            LOADT(st, (kt + 2) * BK);
        }
        cp_commit();
        COMPUTE16_KN(buf);
        if (++buf == 3) buf = 0;
    }
#undef LOADT
    const int mbase = m0 + wm * 64, nbase = n0 + wn * 32;
    float psum[4][2] = {}, pmax[4][2] = {};
#pragma unroll
    for (int fm = 0; fm < 4; fm++) {
        int m = mbase + fm * 16 + g;
        float mk0 = (float)mask[m];
        float mk1 = (float)mask[m + 8];
#pragma unroll
        for (int fn = 0; fn < 4; fn++) {
            int n = nbase + fn * 8 + 2 * q;
            float b0 = bg[n], b1 = bg[n + 1];
            float v00 = fmaxf(acc[fm][fn][0] + b0, 0.f) * mk0;
            float v01 = fmaxf(acc[fm][fn][1] + b1, 0.f) * mk0;
            float v10 = fmaxf(acc[fm][fn][2] + b0, 0.f) * mk1;
            float v11 = fmaxf(acc[fm][fn][3] + b1, 0.f) * mk1;
            psum[fn][0] += v00 + v10;
            psum[fn][1] += v01 + v11;
            pmax[fn][0] = fmaxf(pmax[fn][0], fmaxf(v00, v10));
            pmax[fn][1] = fmaxf(pmax[fn][1], fmaxf(v01, v11));
        }
    }
#pragma unroll
    for (int fn = 0; fn < 4; fn++)
#pragma unroll
        for (int e = 0; e < 2; e++) {
#pragma unroll
            for (int o = 4; o < 32; o <<= 1) {
                psum[fn][e] += __shfl_xor_sync(0xffffffffu, psum[fn][e], o);
                pmax[fn][e] = fmaxf(pmax[fn][e], __shfl_xor_sync(0xffffffffu, pmax[fn][e], o));
            }
        }
    if (l < 4) {
#pragma unroll
        for (int fn = 0; fn < 4; fn++)
#pragma unroll
            for (int e = 0; e < 2; e++) {
                int c = wn * 32 + fn * 8 + 2 * q + e;
                red_s[c][wm] = psum[fn][e];
                red_m[c][wm] = pmax[fn][e];
            }
    }
    __syncthreads();
    if (t < 128) {
        const int bb = m0 >> 9;
        float s = red_s[t][0] + red_s[t][1];
        float mx = fmaxf(red_m[t][0], red_m[t][1]);
        atomicAdd(&out[bb * 3072 + sumoff + n0 + t], s);
        atomicMax((int*)&out[bb * 3072 + maxoff + n0 + t], __float_as_int(mx));
    }
}

// ---------------------------------------------------------------------------
// softmax stats + map
// ---------------------------------------------------------------------------
__global__ void k_rowstats(const float* __restrict__ att,
                           const int* __restrict__ a_mask, const int* __restrict__ b_mask,
                           float* __restrict__ rm, float* __restrict__ rs)
{
    const int i = blockIdx.x, bb = blockIdx.y;
    const float* row = att + ((size_t)bb * LL + i) * LL;
    const int t = threadIdx.x;
    __shared__ float sm[256];
    float m = fmaxf(row[t], row[t + 256]);
    sm[t] = m; __syncthreads();
    for (int s = 128; s > 0; s >>= 1) {
        if (t < s) sm[t] = fmaxf(sm[t], sm[t + s]);
        __syncthreads();
    }
    m = sm[0];
    __syncthreads();
    float s1 = expf(row[t] - m) * (float)b_mask[bb * LL + t]
             + expf(row[t + 256] - m) * (float)b_mask[bb * LL + t + 256];
    sm[t] = s1; __syncthreads();
    for (int s = 128; s > 0; s >>= 1) {
        if (t < s) sm[t] += sm[t + s];
        __syncthreads();
    }
    if (t == 0) {
        rm[bb * LL + i] = m;
        rs[bb * LL + i] = 768.0f * (float)a_mask[bb * LL + i] * sm[0];
    }
}

__global__ void k_colstats(const float* __restrict__ att,
                           const int* __restrict__ a_mask, const int* __restrict__ b_mask,
                           float* __restrict__ cm, float* __restrict__ cs)
{
    const int bb = blockIdx.y;
    const int j = blockIdx.x * 128 + threadIdx.x;
    __shared__ float ams[LL];
    for (int i = threadIdx.x; i < LL; i += 128) ams[i] = (float)a_mask[bb * LL + i];
    __syncthreads();
    const float* base = att + (size_t)bb * LL * LL;
    float m = -1e30f;
    for (int i = 0; i < LL; i++) m = fmaxf(m, base[(size_t)i * LL + j]);
    float s = 0.f;
    for (int i = 0; i < LL; i++) s += expf(base[(size_t)i * LL + j] - m) * ams[i];
    cm[bb * LL + j] = m;
    cs[bb * LL + j] = 768.0f * (float)b_mask[bb * LL + j] * s;
}

// map att -> S1 [b,i,j] (half) and S2t [b,j,i] (half, transposed via smem tile)
__global__ void k_map(const float* __restrict__ att,
                      const int* __restrict__ a_mask, const int* __restrict__ b_mask,
                      const float* __restrict__ rm, const float* __restrict__ rs,
                      const float* __restrict__ cm, const float* __restrict__ cs,
                      __half* __restrict__ S1, __half* __restrict__ S2t)
{
    const int bb = blockIdx.z;
    const int i0 = blockIdx.y * 32, j0 = blockIdx.x * 32;
    const int tx = threadIdx.x, ty = threadIdx.y;
    __shared__ float s2t[32][33];
    const int j = j0 + tx;
    const float cmv = cm[bb * LL + j];
    const float cinv = 1.0f / (cs[bb * LL + j] + 1e-8f);
    const float bmv = 768.0f * (float)b_mask[bb * LL + j];
    for (int r = ty; r < 32; r += 8) {
        const int i = i0 + r;
        const float a = att[((size_t)bb * LL + i) * LL + j];
        const float mfac = bmv * (float)a_mask[bb * LL + i];
        const float rinv = 1.0f / (rs[bb * LL + i] + 1e-8f);
        S1[((size_t)bb * LL + i) * LL + j] = __float2half_rn(expf(a - rm[bb * LL + i]) * mfac * rinv);
        s2t[tx][r] = expf(a - cmv) * mfac * cinv;
    }
    __syncthreads();
    for (int r = ty; r < 32; r += 8)
        S2t[((size_t)bb * LL + j0 + r) * LL + i0 + tx] = __float2half_rn(s2t[r][tx]);
}

__global__ void k_zero(float* __restrict__ out)
{
    int i = blockIdx.x * blockDim.x + threadIdx.x;
    if (i < BB * 4 * HH) out[i] = 0.0f;
}

extern "C" void kernel_launch(void* const* d_in, const int* in_sizes, int n_in,
                              void* d_out, int out_size)
{
    const float* a_embeds = (const float*)d_in[0];
    const float* b_embeds = (const float*)d_in[1];
    const int*   a_mask   = (const int*)d_in[2];
    const int*   b_mask   = (const int*)d_in[3];
    const float* Wp = (const float*)d_in[4];
    const float* bp = (const float*)d_in[5];
    const float* Wf = (const float*)d_in[6];
    const float* bf = (const float*)d_in[7];
    const float* Wg = (const float*)d_in[8];
    const float* bg = (const float*)d_in[9];
    float* out = (float*)d_out;

    float* base = nullptr;
    cudaGetSymbolAddress((void**)&base, g_scratch);
    float* att = base;                       // ALL f32
    float* rm  = att + ALL;
    float* rs  = rm + M_ROWS;
    float* cm  = rs + M_ROWS;
    float* cs  = cm + M_ROWS;
    __half* ah    = (__half*)(cs + M_ROWS);
    __half* bh    = ah + PLH;
    __half* ap    = bh + PLH;
    __half* bp_   = ap + PLH;
    __half* Fa    = bp_ + PLH;
    __half* Fb    = Fa + PLH;
    __half* beta  = Fb + PLH;
    __half* alpha = beta + PLH;
    __half* S1    = alpha + PLH;
    __half* S2t   = S1 + ALL;
    __half* hWp   = S2t + ALL;
    __half* hWf   = hWp + DD * HH;
    __half* hWg   = hWf + HH * HH;

    k_zero<<<(BB * 4 * HH + 1023) / 1024, 1024>>>(out);

    // fp32 -> fp16 conversions
    k_cvth<<<(int)((PLH / 4 + 255) / 256), 256>>>(a_embeds, ah, (int)PLH);
    k_cvth<<<(int)((PLH / 4 + 255) / 256), 256>>>(b_embeds, bh, (int)PLH);
    k_cvth<<<(DD * HH / 4 + 255) / 256, 256>>>(Wp, hWp, DD * HH);
    k_cvth<<<(HH * HH / 4 + 255) / 256, 256>>>(Wf, hWf, HH * HH);
    k_cvth<<<(2 * HH * HH / 4 + 255) / 256, 256>>>(Wg, hWg, 2 * HH * HH);

    // shared projection FFN
    k_proj<<<dim3(6, 256), 256>>>(ah, hWp, bp, nullptr, ap, DD);
    k_proj<<<dim3(6, 256), 256>>>(bh, hWp, bp, nullptr, bp_, DD);

    // attend features (relu + mask)
    k_proj<<<dim3(6, 256), 256>>>(ap, hWf, bf, a_mask, Fa, HH);
    k_proj<<<dim3(6, 256), 256>>>(bp_, hWf, bf, b_mask, Fb, HH);

    // attention scores
    k_att<<<dim3(4, 4, 64), 256>>>(Fa, Fb, att);

    // dual softmax
    k_rowstats<<<dim3(512, 64), 256>>>(att, a_mask, b_mask, rm, rs);
    k_colstats<<<dim3(4, 64), 128>>>(att, a_mask, b_mask, cm, cs);
    k_map<<<dim3(16, 16, 64), dim3(32, 8)>>>(att, a_mask, b_mask, rm, rs, cm, cs, S1, S2t);

    // contexts (both NN)
    k_ctx<<<dim3(6, 4, 64), 256>>>(S1, bp_, beta);
    k_ctx<<<dim3(6, 4, 64), 256>>>(S2t, ap, alpha);

    // compare + aggregate (fused sum/max epilogue)
    k_cmp<<<dim3(6, 256), 256>>>(ap,  beta,  hWg, bg, a_mask, out, 0,   1536);
    k_cmp<<<dim3(6, 256), 256>>>(bp_, alpha, hWg, bg, b_mask, out, 768, 2304);
}

// round 6
// speedup vs baseline: 9.6135x; 1.1155x over previous
#include <cuda_runtime.h>
#include <cuda_fp16.h>
#include <stdint.h>
#include <math.h>

// Problem constants
#define BB 64
#define LL 512
#define DD 768
#define HH 768

static const int    M_ROWS = BB * LL;                  // 32768
static const size_t PLH = (size_t)BB * LL * HH;        // 25165824
static const size_t ALL = (size_t)BB * LL * LL;        // 16777216

__device__ __align__(16) float g_scratch[6 * 25165824ULL + 3 * 16777216ULL + 4 * 32768ULL + 2359296ULL];

// ---------------------------------------------------------------------------
// helpers
// ---------------------------------------------------------------------------
__device__ __forceinline__ void cp16(void* s, const void* g) {
    uint32_t sa = (uint32_t)__cvta_generic_to_shared(s);
    asm volatile("cp.async.cg.shared.global [%0], [%1], 16;" :: "r"(sa), "l"(g));
}
__device__ __forceinline__ void cp_commit() { asm volatile("cp.async.commit_group;"); }
__device__ __forceinline__ void cp_wait1()  { asm volatile("cp.async.wait_group 1;"); }

__device__ __forceinline__ void ldsm_x4(uint32_t* r, uint32_t addr) {
    asm volatile("ldmatrix.sync.aligned.m8n8.x4.shared.b16 {%0,%1,%2,%3}, [%4];"
        : "=r"(r[0]), "=r"(r[1]), "=r"(r[2]), "=r"(r[3]) : "r"(addr));
}
__device__ __forceinline__ void ldsm_x4t(uint32_t* r, uint32_t addr) {
    asm volatile("ldmatrix.sync.aligned.m8n8.x4.trans.shared.b16 {%0,%1,%2,%3}, [%4];"
        : "=r"(r[0]), "=r"(r[1]), "=r"(r[2]), "=r"(r[3]) : "r"(addr));
}
__device__ __forceinline__ void mma16(float* c, const uint32_t* a, const uint32_t* b) {
    asm volatile(
        "mma.sync.aligned.m16n8k16.row.col.f32.f16.f16.f32 "
        "{%0,%1,%2,%3},{%4,%5,%6,%7},{%8,%9},{%0,%1,%2,%3};"
        : "+f"(c[0]), "+f"(c[1]), "+f"(c[2]), "+f"(c[3])
        : "r"(a[0]), "r"(a[1]), "r"(a[2]), "r"(a[3]), "r"(b[0]), "r"(b[1]));
}

// SMEM staging (BK = 32):
//  A tile:  [3][128][40] halves, stage = 10240 B  (pad 40 -> 20-word row stride, conflict-free ldmatrix)
//  B KN:    [3][32][136] halves, stage =  8704 B
//  B NT:    [3][128][40] halves, stage = 10240 B
#define A_STG_B 10240u
#define B_STG_B 8704u
#define A_STG_H 5120
#define B_STG_H 4352

#define COMPUTE32_KN(buf)                                                      \
    _Pragma("unroll")                                                          \
    for (int ks = 0; ks < 2; ks++) {                                           \
        uint32_t af[4][4], bt0[4], bt1[4];                                     \
        _Pragma("unroll")                                                      \
        for (int fm = 0; fm < 4; fm++)                                         \
            ldsm_x4(af[fm], a_addr + (buf) * A_STG_B + ks * 32u + fm * 1280u); \
        ldsm_x4t(bt0, b_addr + (buf) * B_STG_B + ks * 4352u);                  \
        ldsm_x4t(bt1, b_addr + (buf) * B_STG_B + ks * 4352u + 32u);            \
        uint32_t bf[4][2] = {{bt0[0], bt0[1]}, {bt0[2], bt0[3]},               \
                             {bt1[0], bt1[1]}, {bt1[2], bt1[3]}};              \
        _Pragma("unroll")                                                      \
        for (int fm = 0; fm < 4; fm++)                                         \
            _Pragma("unroll")                                                  \
            for (int fn = 0; fn < 4; fn++)                                     \
                mma16(acc[fm][fn], af[fm], bf[fn]);                            \
    }

#define COMPUTE32_NT(buf)                                                      \
    _Pragma("unroll")                                                          \
    for (int ks = 0; ks < 2; ks++) {                                           \
        uint32_t af[4][4], bt0[4], bt1[4];                                     \
        _Pragma("unroll")                                                      \
        for (int fm = 0; fm < 4; fm++)                                         \
            ldsm_x4(af[fm], a_addr + (buf) * A_STG_B + ks * 32u + fm * 1280u); \
        ldsm_x4(bt0, bn_addr + (buf) * A_STG_B + ks * 32u);                    \
        ldsm_x4(bt1, bn_addr + (buf) * A_STG_B + ks * 32u + 1280u);            \
        uint32_t bf[4][2] = {{bt0[0], bt0[2]}, {bt0[1], bt0[3]},               \
                             {bt1[0], bt1[2]}, {bt1[1], bt1[3]}};              \
        _Pragma("unroll")                                                      \
        for (int fm = 0; fm < 4; fm++)                                         \
            _Pragma("unroll")                                                  \
            for (int fn = 0; fn < 4; fn++)                                     \
                mma16(acc[fm][fn], af[fm], bf[fn]);                            \
    }

#define LANE_SETUP                                                             \
    const int t = threadIdx.x;                                                 \
    const int w = t >> 5, l = t & 31, g = l >> 2, q = l & 3;                   \
    const int wm = w >> 2, wn = w & 3;

#define A_ADDR_EXPR (uint32_t)(((wm * 64 + (l & 7) + ((l & 8) ? 8 : 0)) * 40 + ((l & 16) ? 8 : 0)) << 1)
#define B_ADDR_EXPR (uint32_t)((((l & 7) + ((l & 8) ? 8 : 0)) * 136 + wn * 32 + ((l & 16) ? 8 : 0)) << 1)
#define BN_ADDR_EXPR (uint32_t)(((wn * 32 + (l & 7) + ((l & 8) ? 8 : 0)) * 40 + ((l & 16) ? 8 : 0)) << 1)

static const int KN_SMEM = (3 * A_STG_H + 3 * B_STG_H) * 2;   // 56832
static const int NT_SMEM = (6 * A_STG_H) * 2;                 // 61440

// ---------------------------------------------------------------------------
// converts
// ---------------------------------------------------------------------------
__global__ void k_cvth(const float* __restrict__ src, __half* __restrict__ dst, int n)
{
    int i = (blockIdx.x * blockDim.x + threadIdx.x) * 4;
    if (i < n) {
        float4 v = *(const float4*)(src + i);
        *(half2*)(dst + i)     = __floats2half2_rn(v.x, v.y);
        *(half2*)(dst + i + 2) = __floats2half2_rn(v.z, v.w);
    }
}
__global__ void k_cvth2(const float* __restrict__ s0, const float* __restrict__ s1,
                        __half* __restrict__ d0, __half* __restrict__ d1, int n)
{
    const float* src = blockIdx.z ? s1 : s0;
    __half* dst = blockIdx.z ? d1 : d0;
    int i = (blockIdx.x * blockDim.x + threadIdx.x) * 4;
    if (i < n) {
        float4 v = *(const float4*)(src + i);
        *(half2*)(dst + i)     = __floats2half2_rn(v.x, v.y);
        *(half2*)(dst + i + 2) = __floats2half2_rn(v.z, v.w);
    }
}

// ---------------------------------------------------------------------------
// paired proj / attend-F: C = half(relu(A @ W + bias) * mask)   (z selects a/b)
// ---------------------------------------------------------------------------
__global__ __launch_bounds__(256, 2) void k_proj(
    const __half* __restrict__ Aa, const __half* __restrict__ Ab,
    const __half* __restrict__ W, const float* __restrict__ bias,
    const int* __restrict__ ma, const int* __restrict__ mb,
    __half* __restrict__ Ca, __half* __restrict__ Cb, int K)
{
    extern __shared__ __half sm[];
    __half* smA = sm;
    __half* smB = sm + 3 * A_STG_H;
    LANE_SETUP
    const __half* A = blockIdx.z ? Ab : Aa;
    const int* mask = blockIdx.z ? mb : ma;
    __half* C = blockIdx.z ? Cb : Ca;
    const int m0 = blockIdx.y * 128, n0 = blockIdx.x * 128;
    const uint32_t a_base = (uint32_t)__cvta_generic_to_shared(smA);
    const uint32_t b_base = (uint32_t)__cvta_generic_to_shared(smB);
    const uint32_t a_addr = a_base + A_ADDR_EXPR;
    const uint32_t b_addr = b_base + B_ADDR_EXPR;
    float acc[4][4][4] = {};
    const int nt = K / 32;
#define LOADT(st, k0)                                                                       \
    do {                                                                                    \
        _Pragma("unroll")                                                                   \
        for (int p = 0; p < 2; p++) {                                                       \
            int id = t + p * 256;                                                           \
            int arow = id >> 2, aq = id & 3;                                                \
            cp16(smA + (st) * A_STG_H + arow * 40 + aq * 8,                                 \
                 A + (size_t)(m0 + arow) * K + (k0) + aq * 8);                              \
            int brow = id >> 4, bc = id & 15;                                               \
            cp16(smB + (st) * B_STG_H + brow * 136 + bc * 8,                                \
                 W + (size_t)((k0) + brow) * HH + n0 + bc * 8);                             \
        }                                                                                   \
    } while (0)
    LOADT(0, 0);  cp_commit();
    LOADT(1, 32); cp_commit();
    int buf = 0;
    for (int kt = 0; kt < nt; kt++) {
        cp_wait1();
        __syncthreads();
        if (kt + 2 < nt) {
            int st = buf - 1; if (st < 0) st += 3;
            LOADT(st, (kt + 2) * 32);
        }
        cp_commit();
        COMPUTE32_KN(buf);
        if (++buf == 3) buf = 0;
    }
#undef LOADT
    const int mbase = m0 + wm * 64, nbase = n0 + wn * 32;
#pragma unroll
    for (int fm = 0; fm < 4; fm++) {
        int m = mbase + fm * 16 + g;
        float mk0 = mask ? (float)mask[m] : 1.0f;
        float mk1 = mask ? (float)mask[m + 8] : 1.0f;
#pragma unroll
        for (int fn = 0; fn < 4; fn++) {
            int n = nbase + fn * 8 + 2 * q;
            float b0 = bias[n], b1 = bias[n + 1];
            *(half2*)&C[(size_t)m * HH + n] =
                __floats2half2_rn(fmaxf(acc[fm][fn][0] + b0, 0.f) * mk0,
                                  fmaxf(acc[fm][fn][1] + b1, 0.f) * mk0);
            *(half2*)&C[(size_t)(m + 8) * HH + n] =
                __floats2half2_rn(fmaxf(acc[fm][fn][2] + b0, 0.f) * mk1,
                                  fmaxf(acc[fm][fn][3] + b1, 0.f) * mk1);
        }
    }
}

// ---------------------------------------------------------------------------
// att[b,i,j] = Fa[b,i,:] . Fb[b,j,:]   (NT), fp32 output
// ---------------------------------------------------------------------------
__global__ __launch_bounds__(256, 2) void k_att(
    const __half* __restrict__ Fa, const __half* __restrict__ Fb, float* __restrict__ att)
{
    extern __shared__ __half sm[];
    __half* smA = sm;
    __half* smB = sm + 3 * A_STG_H;
    LANE_SETUP
    const int b = blockIdx.z;
    const int m0 = blockIdx.y * 128, n0 = blockIdx.x * 128;
    const __half* Ab = Fa + (size_t)b * LL * HH;
    const __half* Bb = Fb + (size_t)b * LL * HH;
    const uint32_t a_base = (uint32_t)__cvta_generic_to_shared(smA);
    const uint32_t b_base = (uint32_t)__cvta_generic_to_shared(smB);
    const uint32_t a_addr  = a_base + A_ADDR_EXPR;
    const uint32_t bn_addr = b_base + BN_ADDR_EXPR;
    float acc[4][4][4] = {};
    const int nt = HH / 32;
#define LOADT(st, k0)                                                                       \
    do {                                                                                    \
        _Pragma("unroll")                                                                   \
        for (int p = 0; p < 2; p++) {                                                       \
            int id = t + p * 256;                                                           \
            int row = id >> 2, qq = id & 3;                                                 \
            cp16(smA + (st) * A_STG_H + row * 40 + qq * 8,                                  \
                 Ab + (size_t)(m0 + row) * HH + (k0) + qq * 8);                             \
            cp16(smB + (st) * A_STG_H + row * 40 + qq * 8,                                  \
                 Bb + (size_t)(n0 + row) * HH + (k0) + qq * 8);                             \
        }                                                                                   \
    } while (0)
    LOADT(0, 0);  cp_commit();
    LOADT(1, 32); cp_commit();
    int buf = 0;
    for (int kt = 0; kt < nt; kt++) {
        cp_wait1();
        __syncthreads();
        if (kt + 2 < nt) {
            int st = buf - 1; if (st < 0) st += 3;
            LOADT(st, (kt + 2) * 32);
        }
        cp_commit();
        COMPUTE32_NT(buf);
        if (++buf == 3) buf = 0;
    }
#undef LOADT
    const int mbase = m0 + wm * 64, nbase = n0 + wn * 32;
#pragma unroll
    for (int fm = 0; fm < 4; fm++) {
        int m = mbase + fm * 16 + g;
#pragma unroll
        for (int fn = 0; fn < 4; fn++) {
            int n = nbase + fn * 8 + 2 * q;
            *(float2*)&att[((size_t)b * LL + m) * LL + n] =
                make_float2(acc[fm][fn][0], acc[fm][fn][1]);
            *(float2*)&att[((size_t)b * LL + m + 8) * LL + n] =
                make_float2(acc[fm][fn][2], acc[fm][fn][3]);
        }
    }
}

// ---------------------------------------------------------------------------
// paired ctx (NN, K=512): z selects (S1,bp_)->beta or (S2t,ap)->alpha
// ---------------------------------------------------------------------------
__global__ __launch_bounds__(256, 2) void k_ctx(
    const __half* __restrict__ Sa, const __half* __restrict__ Sb,
    const __half* __restrict__ Pa, const __half* __restrict__ Pb,
    __half* __restrict__ Ca, __half* __restrict__ Cb)
{
    extern __shared__ __half sm[];
    __half* smA = sm;
    __half* smB = sm + 3 * A_STG_H;
    LANE_SETUP
    const int pair = blockIdx.z >> 6;
    const int b = blockIdx.z & 63;
    const __half* S = pair ? Sb : Sa;
    const __half* P = pair ? Pb : Pa;
    __half* C = pair ? Cb : Ca;
    const int m0 = blockIdx.y * 128, n0 = blockIdx.x * 128;
    const __half* Abp = S + (size_t)b * LL * LL;
    const __half* Bbp = P + (size_t)b * LL * HH;
    const uint32_t a_base = (uint32_t)__cvta_generic_to_shared(smA);
    const uint32_t b_base = (uint32_t)__cvta_generic_to_shared(smB);
    const uint32_t a_addr = a_base + A_ADDR_EXPR;
    const uint32_t b_addr = b_base + B_ADDR_EXPR;
    float acc[4][4][4] = {};
    const int nt = LL / 32;
#define LOADT(st, k0)                                                                       \
    do {                                                                                    \
        _Pragma("unroll")                                                                   \
        for (int p = 0; p < 2; p++) {                                                       \
            int id = t + p * 256;                                                           \
            int arow = id >> 2, aq = id & 3;                                                \
            cp16(smA + (st) * A_STG_H + arow * 40 + aq * 8,                                 \
                 Abp + (size_t)(m0 + arow) * LL + (k0) + aq * 8);                           \
            int brow = id >> 4, bc = id & 15;                                               \
            cp16(smB + (st) * B_STG_H + brow * 136 + bc * 8,                                \
                 Bbp + (size_t)((k0) + brow) * HH + n0 + bc * 8);                           \
        }                                                                                   \
    } while (0)
    LOADT(0, 0);  cp_commit();
    LOADT(1, 32); cp_commit();
    int buf = 0;
    for (int kt = 0; kt < nt; kt++) {
        cp_wait1();
        __syncthreads();
        if (kt + 2 < nt) {
            int st = buf - 1; if (st < 0) st += 3;
            LOADT(st, (kt + 2) * 32);
        }
        cp_commit();
        COMPUTE32_KN(buf);
        if (++buf == 3) buf = 0;
    }
#undef LOADT
    const int mbase = m0 + wm * 64, nbase = n0 + wn * 32;
#pragma unroll
    for (int fm = 0; fm < 4; fm++) {
        int m = mbase + fm * 16 + g;
#pragma unroll
        for (int fn = 0; fn < 4; fn++) {
            int n = nbase + fn * 8 + 2 * q;
            *(half2*)&C[((size_t)b * LL + m) * HH + n] =
                __floats2half2_rn(acc[fm][fn][0], acc[fm][fn][1]);
            *(half2*)&C[((size_t)b * LL + m + 8) * HH + n] =
                __floats2half2_rn(acc[fm][fn][2], acc[fm][fn][3]);
        }
    }
}

// ---------------------------------------------------------------------------
// paired compare + aggregate: z selects (ap,beta,a_mask)/(bp_,alpha,b_mask)
// ---------------------------------------------------------------------------
__global__ __launch_bounds__(256, 2) void k_cmp(
    const __half* __restrict__ Pa, const __half* __restrict__ Pb,
    const __half* __restrict__ Xa, const __half* __restrict__ Xb,
    const __half* __restrict__ Wg, const float* __restrict__ bg,
    const int* __restrict__ ma, const int* __restrict__ mb,
    float* __restrict__ out)
{
    extern __shared__ __half sm[];
    __half* smA = sm;
    __half* smB = sm + 3 * A_STG_H;
    __shared__ float red_s[128][2];
    __shared__ float red_m[128][2];
    LANE_SETUP
    const int z = blockIdx.z;
    const __half* P = z ? Pb : Pa;
    const __half* CTX = z ? Xb : Xa;
    const int* mask = z ? mb : ma;
    const int sumoff = z ? 768 : 0, maxoff = z ? 2304 : 1536;
    const int m0 = blockIdx.y * 128, n0 = blockIdx.x * 128;
    const uint32_t a_base = (uint32_t)__cvta_generic_to_shared(smA);
    const uint32_t b_base = (uint32_t)__cvta_generic_to_shared(smB);
    const uint32_t a_addr = a_base + A_ADDR_EXPR;
    const uint32_t b_addr = b_base + B_ADDR_EXPR;
    float acc[4][4][4] = {};
    const int nt = (2 * HH) / 32;  // 48
#define LOADT(st, k0)                                                                       \
    do {                                                                                    \
        const __half* Asrc = ((k0) < HH) ? P : CTX;                                         \
        const int kk0 = ((k0) < HH) ? (k0) : ((k0) - HH);                                   \
        _Pragma("unroll")                                                                   \
        for (int p = 0; p < 2; p++) {                                                       \
            int id = t + p * 256;                                                           \
            int arow = id >> 2, aq = id & 3;                                                \
            cp16(smA + (st) * A_STG_H + arow * 40 + aq * 8,                                 \
                 Asrc + (size_t)(m0 + arow) * HH + kk0 + aq * 8);                           \
            int brow = id >> 4, bc = id & 15;                                               \
            cp16(smB + (st) * B_STG_H + brow * 136 + bc * 8,                                \
                 Wg + (size_t)((k0) + brow) * HH + n0 + bc * 8);                            \
        }                                                                                   \
    } while (0)
    LOADT(0, 0);  cp_commit();
    LOADT(1, 32); cp_commit();
    int buf = 0;
    for (int kt = 0; kt < nt; kt++) {
        cp_wait1();
        __syncthreads();
        if (kt + 2 < nt) {
            int st = buf - 1; if (st < 0) st += 3;
            LOADT(st, (kt + 2) * 32);
        }
        cp_commit();
        COMPUTE32_KN(buf);
        if (++buf == 3) buf = 0;
    }
#undef LOADT
    const int mbase = m0 + wm * 64, nbase = n0 + wn * 32;
    float psum[4][2] = {}, pmax[4][2] = {};
#pragma unroll
    for (int fm = 0; fm < 4; fm++) {
        int m = mbase + fm * 16 + g;
        float mk0 = (float)mask[m];
        float mk1 = (float)mask[m + 8];
#pragma unroll
        for (int fn = 0; fn < 4; fn++) {
            int n = nbase + fn * 8 + 2 * q;
            float b0 = bg[n], b1 = bg[n + 1];
            float v00 = fmaxf(acc[fm][fn][0] + b0, 0.f) * mk0;
            float v01 = fmaxf(acc[fm][fn][1] + b1, 0.f) * mk0;
            float v10 = fmaxf(acc[fm][fn][2] + b0, 0.f) * mk1;
            float v11 = fmaxf(acc[fm][fn][3] + b1, 0.f) * mk1;
            psum[fn][0] += v00 + v10;
            psum[fn][1] += v01 + v11;
            pmax[fn][0] = fmaxf(pmax[fn][0], fmaxf(v00, v10));
            pmax[fn][1] = fmaxf(pmax[fn][1], fmaxf(v01, v11));
        }
    }
#pragma unroll
    for (int fn = 0; fn < 4; fn++)
#pragma unroll
        for (int e = 0; e < 2; e++) {
#pragma unroll
            for (int o = 4; o < 32; o <<= 1) {
                psum[fn][e] += __shfl_xor_sync(0xffffffffu, psum[fn][e], o);
                pmax[fn][e] = fmaxf(pmax[fn][e], __shfl_xor_sync(0xffffffffu, pmax[fn][e], o));
            }
        }
    if (l < 4) {
#pragma unroll
        for (int fn = 0; fn < 4; fn++)
#pragma unroll
            for (int e = 0; e < 2; e++) {
                int c = wn * 32 + fn * 8 + 2 * q + e;
                red_s[c][wm] = psum[fn][e];
                red_m[c][wm] = pmax[fn][e];
            }
    }
    __syncthreads();
    if (t < 128) {
        const int bb = m0 >> 9;
        float s = red_s[t][0] + red_s[t][1];
        float mx = fmaxf(red_m[t][0], red_m[t][1]);
        atomicAdd(&out[bb * 3072 + sumoff + n0 + t], s);
        atomicMax((int*)&out[bb * 3072 + maxoff + n0 + t], __float_as_int(mx));
    }
}

// ---------------------------------------------------------------------------
// softmax stats + map
// ---------------------------------------------------------------------------
__global__ void k_rowstats(const float* __restrict__ att,
                           const int* __restrict__ a_mask, const int* __restrict__ b_mask,
                           float* __restrict__ rm, float* __restrict__ rs)
{
    const int i = blockIdx.x, bb = blockIdx.y;
    const float* row = att + ((size_t)bb * LL + i) * LL;
    const int t = threadIdx.x;
    __shared__ float sm[256];
    float m = fmaxf(row[t], row[t + 256]);
    sm[t] = m; __syncthreads();
    for (int s = 128; s > 0; s >>= 1) {
        if (t < s) sm[t] = fmaxf(sm[t], sm[t + s]);
        __syncthreads();
    }
    m = sm[0];
    __syncthreads();
    float s1 = expf(row[t] - m) * (float)b_mask[bb * LL + t]
             + expf(row[t + 256] - m) * (float)b_mask[bb * LL + t + 256];
    sm[t] = s1; __syncthreads();
    for (int s = 128; s > 0; s >>= 1) {
        if (t < s) sm[t] += sm[t + s];
        __syncthreads();
    }
    if (t == 0) {
        rm[bb * LL + i] = m;
        rs[bb * LL + i] = 768.0f * (float)a_mask[bb * LL + i] * sm[0];
    }
}

__global__ void k_colstats(const float* __restrict__ att,
                           const int* __restrict__ a_mask, const int* __restrict__ b_mask,
                           float* __restrict__ cm, float* __restrict__ cs)
{
    const int bb = blockIdx.y;
    const int j = blockIdx.x * 128 + threadIdx.x;
    __shared__ float ams[LL];
    for (int i = threadIdx.x; i < LL; i += 128) ams[i] = (float)a_mask[bb * LL + i];
    __syncthreads();
    const float* base = att + (size_t)bb * LL * LL;
    float m = -1e30f;
    for (int i = 0; i < LL; i++) m = fmaxf(m, base[(size_t)i * LL + j]);
    float s = 0.f;
    for (int i = 0; i < LL; i++) s += expf(base[(size_t)i * LL + j] - m) * ams[i];
    cm[bb * LL + j] = m;
    cs[bb * LL + j] = 768.0f * (float)b_mask[bb * LL + j] * s;
}

__global__ void k_map(const float* __restrict__ att,
                      const int* __restrict__ a_mask, const int* __restrict__ b_mask,
                      const float* __restrict__ rm, const float* __restrict__ rs,
                      const float* __restrict__ cm, const float* __restrict__ cs,
                      __half* __restrict__ S1, __half* __restrict__ S2t)
{
    const int bb = blockIdx.z;
    const int i0 = blockIdx.y * 32, j0 = blockIdx.x * 32;
    const int tx = threadIdx.x, ty = threadIdx.y;
    __shared__ float s2t[32][33];
    const int j = j0 + tx;
    const float cmv = cm[bb * LL + j];
    const float cinv = 1.0f / (cs[bb * LL + j] + 1e-8f);
    const float bmv = 768.0f * (float)b_mask[bb * LL + j];
    for (int r = ty; r < 32; r += 8) {
        const int i = i0 + r;
        const float a = att[((size_t)bb * LL + i) * LL + j];
        const float mfac = bmv * (float)a_mask[bb * LL + i];
        const float rinv = 1.0f / (rs[bb * LL + i] + 1e-8f);
        S1[((size_t)bb * LL + i) * LL + j] = __float2half_rn(expf(a - rm[bb * LL + i]) * mfac * rinv);
        s2t[tx][r] = expf(a - cmv) * mfac * cinv;
    }
    __syncthreads();
    for (int r = ty; r < 32; r += 8)
        S2t[((size_t)bb * LL + j0 + r) * LL + i0 + tx] = __float2half_rn(s2t[r][tx]);
}

__global__ void k_zero(float* __restrict__ out)
{
    int i = blockIdx.x * blockDim.x + threadIdx.x;
    if (i < BB * 4 * HH) out[i] = 0.0f;
}

extern "C" void kernel_launch(void* const* d_in, const int* in_sizes, int n_in,
                              void* d_out, int out_size)
{
    const float* a_embeds = (const float*)d_in[0];
    const float* b_embeds = (const float*)d_in[1];
    const int*   a_mask   = (const int*)d_in[2];
    const int*   b_mask   = (const int*)d_in[3];
    const float* Wp = (const float*)d_in[4];
    const float* bp = (const float*)d_in[5];
    const float* Wf = (const float*)d_in[6];
    const float* bf = (const float*)d_in[7];
    const float* Wg = (const float*)d_in[8];
    const float* bg = (const float*)d_in[9];
    float* out = (float*)d_out;

    float* base = nullptr;
    cudaGetSymbolAddress((void**)&base, g_scratch);
    float* att = base;
    float* rm  = att + ALL;
    float* rs  = rm + M_ROWS;
    float* cm  = rs + M_ROWS;
    float* cs  = cm + M_ROWS;
    __half* ah    = (__half*)(cs + M_ROWS);
    __half* bh    = ah + PLH;
    __half* ap    = bh + PLH;
    __half* bp_   = ap + PLH;
    __half* Fa    = bp_ + PLH;
    __half* Fb    = Fa + PLH;
    __half* beta  = Fb + PLH;
    __half* alpha = beta + PLH;
    __half* S1    = alpha + PLH;
    __half* S2t   = S1 + ALL;
    __half* hWp   = S2t + ALL;
    __half* hWf   = hWp + DD * HH;
    __half* hWg   = hWf + HH * HH;

    cudaFuncSetAttribute(k_proj, cudaFuncAttributeMaxDynamicSharedMemorySize, KN_SMEM);
    cudaFuncSetAttribute(k_att,  cudaFuncAttributeMaxDynamicSharedMemorySize, NT_SMEM);
    cudaFuncSetAttribute(k_ctx,  cudaFuncAttributeMaxDynamicSharedMemorySize, KN_SMEM);
    cudaFuncSetAttribute(k_cmp,  cudaFuncAttributeMaxDynamicSharedMemorySize, KN_SMEM);

    k_zero<<<(BB * 4 * HH + 1023) / 1024, 1024>>>(out);

    // fp32 -> fp16 conversions
    k_cvth2<<<dim3((int)((PLH / 4 + 255) / 256), 1, 2), 256>>>(a_embeds, b_embeds, ah, bh, (int)PLH);
    k_cvth<<<(DD * HH / 4 + 255) / 256, 256>>>(Wp, hWp, DD * HH);
    k_cvth<<<(HH * HH / 4 + 255) / 256, 256>>>(Wf, hWf, HH * HH);
    k_cvth<<<(2 * HH * HH / 4 + 255) / 256, 256>>>(Wg, hWg, 2 * HH * HH);

    // shared projection FFN (paired a/b)
    k_proj<<<dim3(6, 256, 2), 256, KN_SMEM>>>(ah, bh, hWp, bp, nullptr, nullptr, ap, bp_, DD);

    // attend features (paired, relu + mask)
    k_proj<<<dim3(6, 256, 2), 256, KN_SMEM>>>(ap, bp_, hWf, bf, a_mask, b_mask, Fa, Fb, HH);

    // attention scores
    k_att<<<dim3(4, 4, 64), 256, NT_SMEM>>>(Fa, Fb, att);

    // dual softmax
    k_rowstats<<<dim3(512, 64), 256>>>(att, a_mask, b_mask, rm, rs);
    k_colstats<<<dim3(4, 64), 128>>>(att, a_mask, b_mask, cm, cs);
    k_map<<<dim3(16, 16, 64), dim3(32, 8)>>>(att, a_mask, b_mask, rm, rs, cm, cs, S1, S2t);

    // contexts (paired via z: pair = z>>6, batch = z&63)
    k_ctx<<<dim3(6, 4, 128), 256, KN_SMEM>>>(S1, S2t, bp_, ap, beta, alpha);

    // compare + aggregate (paired)
    k_cmp<<<dim3(6, 256, 2), 256, KN_SMEM>>>(ap, bp_, beta, alpha, hWg, bg, a_mask, b_mask, out);
}

// round 7
// speedup vs baseline: 9.7692x; 1.0162x over previous
#include <cuda_runtime.h>
#include <cuda_fp16.h>
#include <stdint.h>
#include <math.h>

// Problem constants
#define BB 64
#define LL 512
#define DD 768
#define HH 768

static const int    M_ROWS = BB * LL;                  // 32768
static const size_t PLH = (size_t)BB * LL * HH;        // 25165824
static const size_t ALL = (size_t)BB * LL * LL;        // 16777216

__device__ __align__(16) float g_scratch[6 * 25165824ULL + 3 * 16777216ULL + 4 * 32768ULL + 2359296ULL];

// ---------------------------------------------------------------------------
// helpers
// ---------------------------------------------------------------------------
__device__ __forceinline__ void cp16(void* s, const void* g) {
    uint32_t sa = (uint32_t)__cvta_generic_to_shared(s);
    asm volatile("cp.async.cg.shared.global [%0], [%1], 16;" :: "r"(sa), "l"(g));
}
__device__ __forceinline__ void cp_commit() { asm volatile("cp.async.commit_group;"); }
__device__ __forceinline__ void cp_wait2()  { asm volatile("cp.async.wait_group 2;"); }

__device__ __forceinline__ void ldsm_x4(uint32_t* r, uint32_t addr) {
    asm volatile("ldmatrix.sync.aligned.m8n8.x4.shared.b16 {%0,%1,%2,%3}, [%4];"
        : "=r"(r[0]), "=r"(r[1]), "=r"(r[2]), "=r"(r[3]) : "r"(addr));
}
__device__ __forceinline__ void ldsm_x4t(uint32_t* r, uint32_t addr) {
    asm volatile("ldmatrix.sync.aligned.m8n8.x4.trans.shared.b16 {%0,%1,%2,%3}, [%4];"
        : "=r"(r[0]), "=r"(r[1]), "=r"(r[2]), "=r"(r[3]) : "r"(addr));
}
__device__ __forceinline__ void mma16(float* c, const uint32_t* a, const uint32_t* b) {
    asm volatile(
        "mma.sync.aligned.m16n8k16.row.col.f32.f16.f16.f32 "
        "{%0,%1,%2,%3},{%4,%5,%6,%7},{%8,%9},{%0,%1,%2,%3};"
        : "+f"(c[0]), "+f"(c[1]), "+f"(c[2]), "+f"(c[3])
        : "r"(a[0]), "r"(a[1]), "r"(a[2]), "r"(a[3]), "r"(b[0]), "r"(b[1]));
}

// monotone float<->uint encoding for atomicMax on floats of any sign
__device__ __forceinline__ uint32_t encf(float f) {
    uint32_t u = __float_as_uint(f);
    return u ^ (uint32_t)(((int32_t)u >> 31) | 0x80000000);
}
__device__ __forceinline__ float decf(uint32_t u) {
    u = (u & 0x80000000u) ? (u ^ 0x80000000u) : ~u;
    return __uint_as_float(u);
}

// SMEM staging (BK = 32, 4 stages):
#define A_STG_B 10240u
#define B_STG_B 8704u
#define A_STG_H 5120
#define B_STG_H 4352

#define COMPUTE32_KN(buf)                                                      \
    _Pragma("unroll")                                                          \
    for (int ks = 0; ks < 2; ks++) {                                           \
        uint32_t af[4][4], bt0[4], bt1[4];                                     \
        _Pragma("unroll")                                                      \
        for (int fm = 0; fm < 4; fm++)                                         \
            ldsm_x4(af[fm], a_addr + (buf) * A_STG_B + ks * 32u + fm * 1280u); \
        ldsm_x4t(bt0, b_addr + (buf) * B_STG_B + ks * 4352u);                  \
        ldsm_x4t(bt1, b_addr + (buf) * B_STG_B + ks * 4352u + 32u);            \
        uint32_t bf[4][2] = {{bt0[0], bt0[1]}, {bt0[2], bt0[3]},               \
                             {bt1[0], bt1[1]}, {bt1[2], bt1[3]}};              \
        _Pragma("unroll")                                                      \
        for (int fm = 0; fm < 4; fm++)                                         \
            _Pragma("unroll")                                                  \
            for (int fn = 0; fn < 4; fn++)                                     \
                mma16(acc[fm][fn], af[fm], bf[fn]);                            \
    }

#define COMPUTE32_NT(buf)                                                      \
    _Pragma("unroll")                                                          \
    for (int ks = 0; ks < 2; ks++) {                                           \
        uint32_t af[4][4], bt0[4], bt1[4];                                     \
        _Pragma("unroll")                                                      \
        for (int fm = 0; fm < 4; fm++)                                         \
            ldsm_x4(af[fm], a_addr + (buf) * A_STG_B + ks * 32u + fm * 1280u); \
        ldsm_x4(bt0, bn_addr + (buf) * A_STG_B + ks * 32u);                    \
        ldsm_x4(bt1, bn_addr + (buf) * A_STG_B + ks * 32u + 1280u);            \
        uint32_t bf[4][2] = {{bt0[0], bt0[2]}, {bt0[1], bt0[3]},               \
                             {bt1[0], bt1[2]}, {bt1[1], bt1[3]}};              \
        _Pragma("unroll")                                                      \
        for (int fm = 0; fm < 4; fm++)                                         \
            _Pragma("unroll")                                                  \
            for (int fn = 0; fn < 4; fn++)                                     \
                mma16(acc[fm][fn], af[fm], bf[fn]);                            \
    }

#define LANE_SETUP                                                             \
    const int t = threadIdx.x;                                                 \
    const int w = t >> 5, l = t & 31, g = l >> 2, q = l & 3;                   \
    const int wm = w >> 2, wn = w & 3;

#define A_ADDR_EXPR (uint32_t)(((wm * 64 + (l & 7) + ((l & 8) ? 8 : 0)) * 40 + ((l & 16) ? 8 : 0)) << 1)
#define B_ADDR_EXPR (uint32_t)((((l & 7) + ((l & 8) ? 8 : 0)) * 136 + wn * 32 + ((l & 16) ? 8 : 0)) << 1)
#define BN_ADDR_EXPR (uint32_t)(((wn * 32 + (l & 7) + ((l & 8) ? 8 : 0)) * 40 + ((l & 16) ? 8 : 0)) << 1)

static const int KN_SMEM = (4 * A_STG_H + 4 * B_STG_H) * 2;   // 75776
static const int NT_SMEM = (8 * A_STG_H) * 2;                 // 81920

#define PIPE4_PROLOG()                                                         \
    LOADT(0, 0);  cp_commit();                                                 \
    LOADT(1, 32); cp_commit();                                                 \
    LOADT(2, 64); cp_commit();

#define PIPE4_BODY(COMPUTE)                                                    \
    for (int kt = 0; kt < nt; kt++) {                                          \
        cp_wait2();                                                            \
        __syncthreads();                                                       \
        if (kt + 3 < nt) { LOADT((kt + 3) & 3, (kt + 3) * 32); }               \
        cp_commit();                                                           \
        COMPUTE(kt & 3);                                                       \
    }

// ---------------------------------------------------------------------------
// converts
// ---------------------------------------------------------------------------
__global__ void k_cvth2(const float* __restrict__ s0, const float* __restrict__ s1,
                        __half* __restrict__ d0, __half* __restrict__ d1, int n)
{
    const float* src = blockIdx.z ? s1 : s0;
    __half* dst = blockIdx.z ? d1 : d0;
    int i = (blockIdx.x * blockDim.x + threadIdx.x) * 4;
    if (i < n) {
        float4 v = *(const float4*)(src + i);
        *(half2*)(dst + i)     = __floats2half2_rn(v.x, v.y);
        *(half2*)(dst + i + 2) = __floats2half2_rn(v.z, v.w);
    }
}
__global__ void k_cvtw(const float* __restrict__ w0, const float* __restrict__ w1,
                       const float* __restrict__ w2,
                       __half* __restrict__ d0, __half* __restrict__ d1, __half* __restrict__ d2)
{
    int z = blockIdx.z;
    const float* src = (z == 0) ? w0 : (z == 1 ? w1 : w2);
    __half* dst = (z == 0) ? d0 : (z == 1 ? d1 : d2);
    int n = (z == 2) ? 2 * HH * HH : DD * HH;
    int i = (blockIdx.x * blockDim.x + threadIdx.x) * 4;
    if (i < n) {
        float4 v = *(const float4*)(src + i);
        *(half2*)(dst + i)     = __floats2half2_rn(v.x, v.y);
        *(half2*)(dst + i + 2) = __floats2half2_rn(v.z, v.w);
    }
}

// ---------------------------------------------------------------------------
// paired proj / attend-F: C = half(relu(A @ W + bias) * mask)   (z selects a/b)
// ---------------------------------------------------------------------------
__global__ __launch_bounds__(256, 2) void k_proj(
    const __half* __restrict__ Aa, const __half* __restrict__ Ab,
    const __half* __restrict__ W, const float* __restrict__ bias,
    const int* __restrict__ ma, const int* __restrict__ mb,
    __half* __restrict__ Ca, __half* __restrict__ Cb, int K)
{
    extern __shared__ __half sm[];
    __half* smA = sm;
    __half* smB = sm + 4 * A_STG_H;
    LANE_SETUP
    const __half* A = blockIdx.z ? Ab : Aa;
    const int* mask = blockIdx.z ? mb : ma;
    __half* C = blockIdx.z ? Cb : Ca;
    const int m0 = blockIdx.y * 128, n0 = blockIdx.x * 128;
    const uint32_t a_base = (uint32_t)__cvta_generic_to_shared(smA);
    const uint32_t b_base = (uint32_t)__cvta_generic_to_shared(smB);
    const uint32_t a_addr = a_base + A_ADDR_EXPR;
    const uint32_t b_addr = b_base + B_ADDR_EXPR;
    float acc[4][4][4] = {};
    const int nt = K / 32;
#define LOADT(st, k0)                                                                       \
    do {                                                                                    \
        _Pragma("unroll")                                                                   \
        for (int p = 0; p < 2; p++) {                                                       \
            int id = t + p * 256;                                                           \
            int arow = id >> 2, aq = id & 3;                                                \
            cp16(smA + (st) * A_STG_H + arow * 40 + aq * 8,                                 \
                 A + (size_t)(m0 + arow) * K + (k0) + aq * 8);                              \
            int brow = id >> 4, bc = id & 15;                                               \
            cp16(smB + (st) * B_STG_H + brow * 136 + bc * 8,                                \
                 W + (size_t)((k0) + brow) * HH + n0 + bc * 8);                             \
        }                                                                                   \
    } while (0)
    PIPE4_PROLOG()
    PIPE4_BODY(COMPUTE32_KN)
#undef LOADT
    const int mbase = m0 + wm * 64, nbase = n0 + wn * 32;
#pragma unroll
    for (int fm = 0; fm < 4; fm++) {
        int m = mbase + fm * 16 + g;
        float mk0 = mask ? (float)mask[m] : 1.0f;
        float mk1 = mask ? (float)mask[m + 8] : 1.0f;
#pragma unroll
        for (int fn = 0; fn < 4; fn++) {
            int n = nbase + fn * 8 + 2 * q;
            float b0 = bias[n], b1 = bias[n + 1];
            *(half2*)&C[(size_t)m * HH + n] =
                __floats2half2_rn(fmaxf(acc[fm][fn][0] + b0, 0.f) * mk0,
                                  fmaxf(acc[fm][fn][1] + b1, 0.f) * mk0);
            *(half2*)&C[(size_t)(m + 8) * HH + n] =
                __floats2half2_rn(fmaxf(acc[fm][fn][2] + b0, 0.f) * mk1,
                                  fmaxf(acc[fm][fn][3] + b1, 0.f) * mk1);
        }
    }
}

// ---------------------------------------------------------------------------
// att[b,i,j] = Fa[b,i,:] . Fb[b,j,:]  (NT), fp32 out + fused row/col max atomics
// ---------------------------------------------------------------------------
__global__ __launch_bounds__(256, 2) void k_att(
    const __half* __restrict__ Fa, const __half* __restrict__ Fb, float* __restrict__ att,
    uint32_t* __restrict__ rm, uint32_t* __restrict__ cm)
{
    extern __shared__ __half sm[];
    __half* smA = sm;
    __half* smB = sm + 4 * A_STG_H;
    LANE_SETUP
    const int b = blockIdx.z;
    const int m0 = blockIdx.y * 128, n0 = blockIdx.x * 128;
    const __half* Ab = Fa + (size_t)b * LL * HH;
    const __half* Bb = Fb + (size_t)b * LL * HH;
    const uint32_t a_base = (uint32_t)__cvta_generic_to_shared(smA);
    const uint32_t b_base = (uint32_t)__cvta_generic_to_shared(smB);
    const uint32_t a_addr  = a_base + A_ADDR_EXPR;
    const uint32_t bn_addr = b_base + BN_ADDR_EXPR;
    float acc[4][4][4] = {};
    const int nt = HH / 32;
#define LOADT(st, k0)                                                                       \
    do {                                                                                    \
        _Pragma("unroll")                                                                   \
        for (int p = 0; p < 2; p++) {                                                       \
            int id = t + p * 256;                                                           \
            int row = id >> 2, qq = id & 3;                                                 \
            cp16(smA + (st) * A_STG_H + row * 40 + qq * 8,                                  \
                 Ab + (size_t)(m0 + row) * HH + (k0) + qq * 8);                             \
            cp16(smB + (st) * A_STG_H + row * 40 + qq * 8,                                  \
                 Bb + (size_t)(n0 + row) * HH + (k0) + qq * 8);                             \
        }                                                                                   \
    } while (0)
    PIPE4_PROLOG()
    PIPE4_BODY(COMPUTE32_NT)
#undef LOADT
    const int mbase = m0 + wm * 64, nbase = n0 + wn * 32;
#pragma unroll
    for (int fm = 0; fm < 4; fm++) {
        int m = mbase + fm * 16 + g;
#pragma unroll
        for (int fn = 0; fn < 4; fn++) {
            int n = nbase + fn * 8 + 2 * q;
            *(float2*)&att[((size_t)b * LL + m) * LL + n] =
                make_float2(acc[fm][fn][0], acc[fm][fn][1]);
            *(float2*)&att[((size_t)b * LL + m + 8) * LL + n] =
                make_float2(acc[fm][fn][2], acc[fm][fn][3]);
        }
    }
    // fused row maxes (over this 128-col tile) -> global atomicMax
#pragma unroll
    for (int fm = 0; fm < 4; fm++) {
        float r0 = acc[fm][0][0], r1 = acc[fm][0][2];
#pragma unroll
        for (int fn = 0; fn < 4; fn++) {
            r0 = fmaxf(r0, fmaxf(acc[fm][fn][0], acc[fm][fn][1]));
            r1 = fmaxf(r1, fmaxf(acc[fm][fn][2], acc[fm][fn][3]));
        }
        r0 = fmaxf(r0, __shfl_xor_sync(0xffffffffu, r0, 1));
        r0 = fmaxf(r0, __shfl_xor_sync(0xffffffffu, r0, 2));
        r1 = fmaxf(r1, __shfl_xor_sync(0xffffffffu, r1, 1));
        r1 = fmaxf(r1, __shfl_xor_sync(0xffffffffu, r1, 2));
        if (q == 0) {
            int m = mbase + fm * 16 + g;
            atomicMax(&rm[b * LL + m], encf(r0));
            atomicMax(&rm[b * LL + m + 8], encf(r1));
        }
    }
    // fused col maxes (over this 128-row tile)
#pragma unroll
    for (int fn = 0; fn < 4; fn++) {
        float c0 = acc[0][fn][0], c1 = acc[0][fn][1];
#pragma unroll
        for (int fm = 0; fm < 4; fm++) {
            c0 = fmaxf(c0, fmaxf(acc[fm][fn][0], acc[fm][fn][2]));
            c1 = fmaxf(c1, fmaxf(acc[fm][fn][1], acc[fm][fn][3]));
        }
        c0 = fmaxf(c0, __shfl_xor_sync(0xffffffffu, c0, 4));
        c0 = fmaxf(c0, __shfl_xor_sync(0xffffffffu, c0, 8));
        c0 = fmaxf(c0, __shfl_xor_sync(0xffffffffu, c0, 16));
        c1 = fmaxf(c1, __shfl_xor_sync(0xffffffffu, c1, 4));
        c1 = fmaxf(c1, __shfl_xor_sync(0xffffffffu, c1, 8));
        c1 = fmaxf(c1, __shfl_xor_sync(0xffffffffu, c1, 16));
        if (g == 0) {
            int n = nbase + fn * 8 + 2 * q;
            atomicMax(&cm[b * LL + n], encf(c0));
            atomicMax(&cm[b * LL + n + 1], encf(c1));
        }
    }
}

// ---------------------------------------------------------------------------
// map: att -> S1u [b,i,j], S2tu [b,j,i] (unnormalized, half), accumulates rs, cs
// ---------------------------------------------------------------------------
__global__ void k_map(const float* __restrict__ att,
                      const int* __restrict__ a_mask, const int* __restrict__ b_mask,
                      const uint32_t* __restrict__ rm, const uint32_t* __restrict__ cm,
                      float* __restrict__ rs, float* __restrict__ cs,
                      __half* __restrict__ S1, __half* __restrict__ S2t)
{
    const int bb = blockIdx.z;
    const int i0 = blockIdx.y * 32, j0 = blockIdx.x * 32;
    const int tx = threadIdx.x, ty = threadIdx.y;
    const int tid = ty * 32 + tx;
    __shared__ float rmv[32], ermv[32], amv[32];
    __shared__ float ecm[32], bmv[32];
    __shared__ float s2t_sh[32][33];
    __shared__ float colp[8][32];
    if (tid < 32) {
        float c = decf(cm[bb * LL + j0 + tid]);
        ecm[tid] = __expf(-c);
        bmv[tid] = 768.0f * (float)b_mask[bb * LL + j0 + tid];
    } else if (tid < 64) {
        int r = tid - 32;
        float rf = decf(rm[bb * LL + i0 + r]);
        rmv[r] = rf;
        ermv[r] = __expf(rf);
        amv[r] = (float)a_mask[bb * LL + i0 + r];
    }
    __syncthreads();
    float colsum = 0.f;
    for (int r = ty; r < 32; r += 8) {
        const int i = i0 + r;
        float a = att[((size_t)bb * LL + i) * LL + j0 + tx];
        float E = __expf(a - rmv[r]) * (amv[r] * bmv[tx]);
        S1[((size_t)bb * LL + i) * LL + j0 + tx] = __float2half_rn(E);
        float s2 = E * ermv[r] * ecm[tx];
        s2t_sh[tx][r] = s2;
        colsum += s2;
        float rsum = E;
#pragma unroll
        for (int o = 16; o > 0; o >>= 1) rsum += __shfl_xor_sync(0xffffffffu, rsum, o);
        if (tx == 0) atomicAdd(&rs[bb * LL + i], rsum);
    }
    colp[ty][tx] = colsum;
    __syncthreads();
    if (ty == 0) {
        float c = 0.f;
#pragma unroll
        for (int k = 0; k < 8; k++) c += colp[k][tx];
        atomicAdd(&cs[bb * LL + j0 + tx], c);
    }
    for (int r = ty; r < 32; r += 8)
        S2t[((size_t)bb * LL + j0 + r) * LL + i0 + tx] = __float2half_rn(s2t_sh[r][tx]);
}

// ---------------------------------------------------------------------------
// paired ctx (NN, K=512): z pair selects (S1u,bp_)->beta/rs or (S2tu,ap)->alpha/cs
// epilogue applies deferred softmax normalization 1/(sum+EPS)
// ---------------------------------------------------------------------------
__global__ __launch_bounds__(256, 2) void k_ctx(
    const __half* __restrict__ Sa, const __half* __restrict__ Sb,
    const __half* __restrict__ Pa, const __half* __restrict__ Pb,
    const float* __restrict__ sca, const float* __restrict__ scb,
    __half* __restrict__ Ca, __half* __restrict__ Cb)
{
    extern __shared__ __half sm[];
    __half* smA = sm;
    __half* smB = sm + 4 * A_STG_H;
    LANE_SETUP
    const int pair = blockIdx.z >> 6;
    const int b = blockIdx.z & 63;
    const __half* S = pair ? Sb : Sa;
    const __half* P = pair ? Pb : Pa;
    const float* sc = pair ? scb : sca;
    __half* C = pair ? Cb : Ca;
    const int m0 = blockIdx.y * 128, n0 = blockIdx.x * 128;
    const __half* Abp = S + (size_t)b * LL * LL;
    const __half* Bbp = P + (size_t)b * LL * HH;
    const uint32_t a_base = (uint32_t)__cvta_generic_to_shared(smA);
    const uint32_t b_base = (uint32_t)__cvta_generic_to_shared(smB);
    const uint32_t a_addr = a_base + A_ADDR_EXPR;
    const uint32_t b_addr = b_base + B_ADDR_EXPR;
    float acc[4][4][4] = {};
    const int nt = LL / 32;
#define LOADT(st, k0)                                                                       \
    do {                                                                                    \
        _Pragma("unroll")                                                                   \
        for (int p = 0; p < 2; p++) {                                                       \
            int id = t + p * 256;                                                           \
            int arow = id >> 2, aq = id & 3;                                                \
            cp16(smA + (st) * A_STG_H + arow * 40 + aq * 8,                                 \
                 Abp + (size_t)(m0 + arow) * LL + (k0) + aq * 8);                           \
            int brow = id >> 4, bc = id & 15;                                               \
            cp16(smB + (st) * B_STG_H + brow * 136 + bc * 8,                                \
                 Bbp + (size_t)((k0) + brow) * HH + n0 + bc * 8);                           \
        }                                                                                   \
    } while (0)
    PIPE4_PROLOG()
    PIPE4_BODY(COMPUTE32_KN)
#undef LOADT
    const int mbase = m0 + wm * 64, nbase = n0 + wn * 32;
#pragma unroll
    for (int fm = 0; fm < 4; fm++) {
        int m = mbase + fm * 16 + g;
        float s0 = 1.0f / (sc[b * LL + m] + 1e-8f);
        float s1v = 1.0f / (sc[b * LL + m + 8] + 1e-8f);
#pragma unroll
        for (int fn = 0; fn < 4; fn++) {
            int n = nbase + fn * 8 + 2 * q;
            *(half2*)&C[((size_t)b * LL + m) * HH + n] =
                __floats2half2_rn(acc[fm][fn][0] * s0, acc[fm][fn][1] * s0);
            *(half2*)&C[((size_t)b * LL + m + 8) * HH + n] =
                __floats2half2_rn(acc[fm][fn][2] * s1v, acc[fm][fn][3] * s1v);
        }
    }
}

// ---------------------------------------------------------------------------
// paired compare + aggregate
// ---------------------------------------------------------------------------
__global__ __launch_bounds__(256, 2) void k_cmp(
    const __half* __restrict__ Pa, const __half* __restrict__ Pb,
    const __half* __restrict__ Xa, const __half* __restrict__ Xb,
    const __half* __restrict__ Wg, const float* __restrict__ bg,
    const int* __restrict__ ma, const int* __restrict__ mb,
    float* __restrict__ out)
{
    extern __shared__ __half sm[];
    __half* smA = sm;
    __half* smB = sm + 4 * A_STG_H;
    __shared__ float red_s[128][2];
    __shared__ float red_m[128][2];
    LANE_SETUP
    const int z = blockIdx.z;
    const __half* P = z ? Pb : Pa;
    const __half* CTX = z ? Xb : Xa;
    const int* mask = z ? mb : ma;
    const int sumoff = z ? 768 : 0, maxoff = z ? 2304 : 1536;
    const int m0 = blockIdx.y * 128, n0 = blockIdx.x * 128;
    const uint32_t a_base = (uint32_t)__cvta_generic_to_shared(smA);
    const uint32_t b_base = (uint32_t)__cvta_generic_to_shared(smB);
    const uint32_t a_addr = a_base + A_ADDR_EXPR;
    const uint32_t b_addr = b_base + B_ADDR_EXPR;
    float acc[4][4][4] = {};
    const int nt = (2 * HH) / 32;  // 48
#define LOADT(st, k0)                                                                       \
    do {                                                                                    \
        const __half* Asrc = ((k0) < HH) ? P : CTX;                                         \
        const int kk0 = ((k0) < HH) ? (k0) : ((k0) - HH);                                   \
        _Pragma("unroll")                                                                   \
        for (int p = 0; p < 2; p++) {                                                       \
            int id = t + p * 256;                                                           \
            int arow = id >> 2, aq = id & 3;                                                \
            cp16(smA + (st) * A_STG_H + arow * 40 + aq * 8,                                 \
                 Asrc + (size_t)(m0 + arow) * HH + kk0 + aq * 8);                           \
            int brow = id >> 4, bc = id & 15;                                               \
            cp16(smB + (st) * B_STG_H + brow * 136 + bc * 8,                                \
                 Wg + (size_t)((k0) + brow) * HH + n0 + bc * 8);                            \
        }                                                                                   \
    } while (0)
    PIPE4_PROLOG()
    PIPE4_BODY(COMPUTE32_KN)
#undef LOADT
    const int mbase = m0 + wm * 64, nbase = n0 + wn * 32;
    float psum[4][2] = {}, pmax[4][2] = {};
#pragma unroll
    for (int fm = 0; fm < 4; fm++) {
        int m = mbase + fm * 16 + g;
        float mk0 = (float)mask[m];
        float mk1 = (float)mask[m + 8];
#pragma unroll
        for (int fn = 0; fn < 4; fn++) {
            int n = nbase + fn * 8 + 2 * q;
            float b0 = bg[n], b1 = bg[n + 1];
            float v00 = fmaxf(acc[fm][fn][0] + b0, 0.f) * mk0;
            float v01 = fmaxf(acc[fm][fn][1] + b1, 0.f) * mk0;
            float v10 = fmaxf(acc[fm][fn][2] + b0, 0.f) * mk1;
            float v11 = fmaxf(acc[fm][fn][3] + b1, 0.f) * mk1;
            psum[fn][0] += v00 + v10;
            psum[fn][1] += v01 + v11;
            pmax[fn][0] = fmaxf(pmax[fn][0], fmaxf(v00, v10));
            pmax[fn][1] = fmaxf(pmax[fn][1], fmaxf(v01, v11));
        }
    }
#pragma unroll
    for (int fn = 0; fn < 4; fn++)
#pragma unroll
        for (int e = 0; e < 2; e++) {
#pragma unroll
            for (int o = 4; o < 32; o <<= 1) {
                psum[fn][e] += __shfl_xor_sync(0xffffffffu, psum[fn][e], o);
                pmax[fn][e] = fmaxf(pmax[fn][e], __shfl_xor_sync(0xffffffffu, pmax[fn][e], o));
            }
        }
    if (l < 4) {
#pragma unroll
        for (int fn = 0; fn < 4; fn++)
#pragma unroll
            for (int e = 0; e < 2; e++) {
                int c = wn * 32 + fn * 8 + 2 * q + e;
                red_s[c][wm] = psum[fn][e];
                red_m[c][wm] = pmax[fn][e];
            }
    }
    __syncthreads();
    if (t < 128) {
        const int bb = m0 >> 9;
        float s = red_s[t][0] + red_s[t][1];
        float mx = fmaxf(red_m[t][0], red_m[t][1]);
        atomicAdd(&out[bb * 3072 + sumoff + n0 + t], s);
        atomicMax((int*)&out[bb * 3072 + maxoff + n0 + t], __float_as_int(mx));
    }
}

// zero out + stats accumulators (rm/cm encoded maxes, rs/cs sums)
__global__ void k_zero(float* __restrict__ out, float* __restrict__ stats)
{
    int i = blockIdx.x * blockDim.x + threadIdx.x;
    if (i < BB * 4 * HH) out[i] = 0.0f;
    if (i < 4 * M_ROWS) stats[i] = 0.0f;
}

extern "C" void kernel_launch(void* const* d_in, const int* in_sizes, int n_in,
                              void* d_out, int out_size)
{
    const float* a_embeds = (const float*)d_in[0];
    const float* b_embeds = (const float*)d_in[1];
    const int*   a_mask   = (const int*)d_in[2];
    const int*   b_mask   = (const int*)d_in[3];
    const float* Wp = (const float*)d_in[4];
    const float* bp = (const float*)d_in[5];
    const float* Wf = (const float*)d_in[6];
    const float* bf = (const float*)d_in[7];
    const float* Wg = (const float*)d_in[8];
    const float* bg = (const float*)d_in[9];
    float* out = (float*)d_out;

    float* base = nullptr;
    cudaGetSymbolAddress((void**)&base, g_scratch);
    float* att = base;
    float* rm  = att + ALL;          // encoded uint maxes
    float* cm  = rm + M_ROWS;
    float* rs  = cm + M_ROWS;
    float* cs  = rs + M_ROWS;
    __half* ah    = (__half*)(cs + M_ROWS);
    __half* bh    = ah + PLH;
    __half* ap    = bh + PLH;
    __half* bp_   = ap + PLH;
    __half* Fa    = bp_ + PLH;
    __half* Fb    = Fa + PLH;
    __half* beta  = Fb + PLH;
    __half* alpha = beta + PLH;
    __half* S1    = alpha + PLH;
    __half* S2t   = S1 + ALL;
    __half* hWp   = S2t + ALL;
    __half* hWf   = hWp + DD * HH;
    __half* hWg   = hWf + HH * HH;

    cudaFuncSetAttribute(k_proj, cudaFuncAttributeMaxDynamicSharedMemorySize, KN_SMEM);
    cudaFuncSetAttribute(k_att,  cudaFuncAttributeMaxDynamicSharedMemorySize, NT_SMEM);
    cudaFuncSetAttribute(k_ctx,  cudaFuncAttributeMaxDynamicSharedMemorySize, KN_SMEM);
    cudaFuncSetAttribute(k_cmp,  cudaFuncAttributeMaxDynamicSharedMemorySize, KN_SMEM);

    k_zero<<<(BB * 4 * HH + 1023) / 1024, 1024>>>(out, rm);

    // fp32 -> fp16 conversions
    k_cvth2<<<dim3((int)((PLH / 4 + 255) / 256), 1, 2), 256>>>(a_embeds, b_embeds, ah, bh, (int)PLH);
    k_cvtw<<<dim3((2 * HH * HH / 4 + 255) / 256, 1, 3), 256>>>(Wp, Wf, Wg, hWp, hWf, hWg);

    // shared projection FFN (paired a/b)
    k_proj<<<dim3(6, 256, 2), 256, KN_SMEM>>>(ah, bh, hWp, bp, nullptr, nullptr, ap, bp_, DD);

    // attend features (paired, relu + mask)
    k_proj<<<dim3(6, 256, 2), 256, KN_SMEM>>>(ap, bp_, hWf, bf, a_mask, b_mask, Fa, Fb, HH);

    // attention scores + fused row/col max
    k_att<<<dim3(4, 4, 64), 256, NT_SMEM>>>(Fa, Fb, att, (uint32_t*)rm, (uint32_t*)cm);

    // map: unnormalized softmax numerators + sum accumulation
    k_map<<<dim3(16, 16, 64), dim3(32, 8)>>>(att, a_mask, b_mask,
                                             (const uint32_t*)rm, (const uint32_t*)cm,
                                             rs, cs, S1, S2t);

    // contexts (paired; deferred normalization in epilogue)
    k_ctx<<<dim3(6, 4, 128), 256, KN_SMEM>>>(S1, S2t, bp_, ap, rs, cs, beta, alpha);

    // compare + aggregate (paired)
    k_cmp<<<dim3(6, 256, 2), 256, KN_SMEM>>>(ap, bp_, beta, alpha, hWg, bg, a_mask, b_mask, out);
}

// round 8
// speedup vs baseline: 10.0743x; 1.0312x over previous
#include <cuda_runtime.h>
#include <cuda_fp16.h>
#include <stdint.h>
#include <math.h>

// Problem constants
#define BB 64
#define LL 512
#define DD 768
#define HH 768

static const int    M_ROWS = BB * LL;                  // 32768
static const size_t PLH = (size_t)BB * LL * HH;        // 25165824
static const size_t ALL = (size_t)BB * LL * LL;        // 16777216

__device__ __align__(16) float g_scratch[6 * 25165824ULL + 3 * 16777216ULL + 4 * 32768ULL + 2359296ULL];

// ---------------------------------------------------------------------------
// helpers
// ---------------------------------------------------------------------------
__device__ __forceinline__ void cp16(void* s, const void* g) {
    uint32_t sa = (uint32_t)__cvta_generic_to_shared(s);
    asm volatile("cp.async.cg.shared.global [%0], [%1], 16;" :: "r"(sa), "l"(g));
}
__device__ __forceinline__ void cp_commit() { asm volatile("cp.async.commit_group;"); }
__device__ __forceinline__ void cp_wait1()  { asm volatile("cp.async.wait_group 1;"); }

__device__ __forceinline__ void ldsm_x4(uint32_t* r, uint32_t addr) {
    asm volatile("ldmatrix.sync.aligned.m8n8.x4.shared.b16 {%0,%1,%2,%3}, [%4];"
        : "=r"(r[0]), "=r"(r[1]), "=r"(r[2]), "=r"(r[3]) : "r"(addr));
}
__device__ __forceinline__ void ldsm_x4t(uint32_t* r, uint32_t addr) {
    asm volatile("ldmatrix.sync.aligned.m8n8.x4.trans.shared.b16 {%0,%1,%2,%3}, [%4];"
        : "=r"(r[0]), "=r"(r[1]), "=r"(r[2]), "=r"(r[3]) : "r"(addr));
}
__device__ __forceinline__ void mma16(float* c, const uint32_t* a, const uint32_t* b) {
    asm volatile(
        "mma.sync.aligned.m16n8k16.row.col.f32.f16.f16.f32 "
        "{%0,%1,%2,%3},{%4,%5,%6,%7},{%8,%9},{%0,%1,%2,%3};"
        : "+f"(c[0]), "+f"(c[1]), "+f"(c[2]), "+f"(c[3])
        : "r"(a[0]), "r"(a[1]), "r"(a[2]), "r"(a[3]), "r"(b[0]), "r"(b[1]));
}

// monotone float<->uint encoding for atomicMax on floats of any sign
__device__ __forceinline__ uint32_t encf(float f) {
    uint32_t u = __float_as_uint(f);
    return u ^ (uint32_t)(((int32_t)u >> 31) | 0x80000000);
}
__device__ __forceinline__ float decf(uint32_t u) {
    u = (u & 0x80000000u) ? (u ^ 0x80000000u) : ~u;
    return __uint_as_float(u);
}

// SMEM staging (BK = 64, 3 stages):
//  A tile: [128][72] halves, pitch 144 B, stage = 18432 B  (conflict-free ldmatrix)
//  B KN:   [64][136] halves, pitch 272 B, stage = 17408 B
//  B NT:   same layout as A
#define A_STG_B 18432u
#define B_STG_B 17408u
#define A_STG_H 9216
#define B_STG_H 8704

#define COMPUTE64_KN(buf)                                                      \
    _Pragma("unroll")                                                          \
    for (int ks = 0; ks < 4; ks++) {                                           \
        uint32_t af[4][4], bt0[4], bt1[4];                                     \
        _Pragma("unroll")                                                      \
        for (int fm = 0; fm < 4; fm++)                                         \
            ldsm_x4(af[fm], a_addr + (buf) * A_STG_B + ks * 32u + fm * 2304u); \
        ldsm_x4t(bt0, b_addr + (buf) * B_STG_B + ks * 4352u);                  \
        ldsm_x4t(bt1, b_addr + (buf) * B_STG_B + ks * 4352u + 32u);            \
        uint32_t bf[4][2] = {{bt0[0], bt0[1]}, {bt0[2], bt0[3]},               \
                             {bt1[0], bt1[1]}, {bt1[2], bt1[3]}};              \
        _Pragma("unroll")                                                      \
        for (int fm = 0; fm < 4; fm++)                                         \
            _Pragma("unroll")                                                  \
            for (int fn = 0; fn < 4; fn++)                                     \
                mma16(acc[fm][fn], af[fm], bf[fn]);                            \
    }

#define COMPUTE64_NT(buf)                                                      \
    _Pragma("unroll")                                                          \
    for (int ks = 0; ks < 4; ks++) {                                           \
        uint32_t af[4][4], bt0[4], bt1[4];                                     \
        _Pragma("unroll")                                                      \
        for (int fm = 0; fm < 4; fm++)                                         \
            ldsm_x4(af[fm], a_addr + (buf) * A_STG_B + ks * 32u + fm * 2304u); \
        ldsm_x4(bt0, bn_addr + (buf) * A_STG_B + ks * 32u);                    \
        ldsm_x4(bt1, bn_addr + (buf) * A_STG_B + ks * 32u + 2304u);            \
        uint32_t bf[4][2] = {{bt0[0], bt0[2]}, {bt0[1], bt0[3]},               \
                             {bt1[0], bt1[2]}, {bt1[1], bt1[3]}};              \
        _Pragma("unroll")                                                      \
        for (int fm = 0; fm < 4; fm++)                                         \
            _Pragma("unroll")                                                  \
            for (int fn = 0; fn < 4; fn++)                                     \
                mma16(acc[fm][fn], af[fm], bf[fn]);                            \
    }

#define LANE_SETUP                                                             \
    const int t = threadIdx.x;                                                 \
    const int w = t >> 5, l = t & 31, g = l >> 2, q = l & 3;                   \
    const int wm = w >> 2, wn = w & 3;

#define A_ADDR_EXPR (uint32_t)(((wm * 64 + (l & 7) + ((l & 8) ? 8 : 0)) * 72 + ((l & 16) ? 8 : 0)) << 1)
#define B_ADDR_EXPR (uint32_t)((((l & 7) + ((l & 8) ? 8 : 0)) * 136 + wn * 32 + ((l & 16) ? 8 : 0)) << 1)
#define BN_ADDR_EXPR (uint32_t)(((wn * 32 + (l & 7) + ((l & 8) ? 8 : 0)) * 72 + ((l & 16) ? 8 : 0)) << 1)

static const int KN_SMEM = 3 * (A_STG_B + B_STG_B);   // 107520
static const int NT_SMEM = 3 * 2 * A_STG_B;           // 110592

// 3-stage pipeline over BK=64 stages
#define PIPE3_PROLOG()                                                         \
    LOADT(0, 0);  cp_commit();                                                 \
    LOADT(1, 64); cp_commit();

#define PIPE3_BODY(COMPUTE)                                                    \
    {                                                                          \
        int buf = 0, ldst = 2;                                                 \
        for (int kt = 0; kt < nt; kt++) {                                      \
            cp_wait1();                                                        \
            __syncthreads();                                                   \
            if (kt + 2 < nt) { LOADT(ldst, (kt + 2) * 64); }                   \
            cp_commit();                                                       \
            COMPUTE(buf);                                                      \
            if (++buf == 3) buf = 0;                                           \
            if (++ldst == 3) ldst = 0;                                         \
        }                                                                      \
    }

// ---------------------------------------------------------------------------
// converts
// ---------------------------------------------------------------------------
__global__ void k_cvth2(const float* __restrict__ s0, const float* __restrict__ s1,
                        __half* __restrict__ d0, __half* __restrict__ d1, int n)
{
    const float* src = blockIdx.z ? s1 : s0;
    __half* dst = blockIdx.z ? d1 : d0;
    int i = (blockIdx.x * blockDim.x + threadIdx.x) * 4;
    if (i < n) {
        float4 v = *(const float4*)(src + i);
        *(half2*)(dst + i)     = __floats2half2_rn(v.x, v.y);
        *(half2*)(dst + i + 2) = __floats2half2_rn(v.z, v.w);
    }
}
__global__ void k_cvtw(const float* __restrict__ w0, const float* __restrict__ w1,
                       const float* __restrict__ w2,
                       __half* __restrict__ d0, __half* __restrict__ d1, __half* __restrict__ d2)
{
    int z = blockIdx.z;
    const float* src = (z == 0) ? w0 : (z == 1 ? w1 : w2);
    __half* dst = (z == 0) ? d0 : (z == 1 ? d1 : d2);
    int n = (z == 2) ? 2 * HH * HH : DD * HH;
    int i = (blockIdx.x * blockDim.x + threadIdx.x) * 4;
    if (i < n) {
        float4 v = *(const float4*)(src + i);
        *(half2*)(dst + i)     = __floats2half2_rn(v.x, v.y);
        *(half2*)(dst + i + 2) = __floats2half2_rn(v.z, v.w);
    }
}

// ---------------------------------------------------------------------------
// paired proj / attend-F: C = half(relu(A @ W + bias) * mask)   (z selects a/b)
// ---------------------------------------------------------------------------
__global__ __launch_bounds__(256, 2) void k_proj(
    const __half* __restrict__ Aa, const __half* __restrict__ Ab,
    const __half* __restrict__ W, const float* __restrict__ bias,
    const int* __restrict__ ma, const int* __restrict__ mb,
    __half* __restrict__ Ca, __half* __restrict__ Cb, int K)
{
    extern __shared__ __half sm[];
    __half* smA = sm;
    __half* smB = sm + 3 * A_STG_H;
    LANE_SETUP
    const __half* A = blockIdx.z ? Ab : Aa;
    const int* mask = blockIdx.z ? mb : ma;
    __half* C = blockIdx.z ? Cb : Ca;
    const int m0 = blockIdx.y * 128, n0 = blockIdx.x * 128;
    const uint32_t a_base = (uint32_t)__cvta_generic_to_shared(smA);
    const uint32_t b_base = (uint32_t)__cvta_generic_to_shared(smB);
    const uint32_t a_addr = a_base + A_ADDR_EXPR;
    const uint32_t b_addr = b_base + B_ADDR_EXPR;
    float acc[4][4][4] = {};
    const int nt = K / 64;
#define LOADT(st, k0)                                                                       \
    do {                                                                                    \
        _Pragma("unroll")                                                                   \
        for (int p = 0; p < 4; p++) {                                                       \
            int id = t + p * 256;                                                           \
            int arow = id >> 3, ac = id & 7;                                                \
            cp16(smA + (st) * A_STG_H + arow * 72 + ac * 8,                                 \
                 A + (size_t)(m0 + arow) * K + (k0) + ac * 8);                              \
            int brow = id >> 4, bc = id & 15;                                               \
            cp16(smB + (st) * B_STG_H + brow * 136 + bc * 8,                                \
                 W + (size_t)((k0) + brow) * HH + n0 + bc * 8);                             \
        }                                                                                   \
    } while (0)
    PIPE3_PROLOG()
    PIPE3_BODY(COMPUTE64_KN)
#undef LOADT
    const int mbase = m0 + wm * 64, nbase = n0 + wn * 32;
#pragma unroll
    for (int fm = 0; fm < 4; fm++) {
        int m = mbase + fm * 16 + g;
        float mk0 = mask ? (float)mask[m] : 1.0f;
        float mk1 = mask ? (float)mask[m + 8] : 1.0f;
#pragma unroll
        for (int fn = 0; fn < 4; fn++) {
            int n = nbase + fn * 8 + 2 * q;
            float b0 = bias[n], b1 = bias[n + 1];
            *(half2*)&C[(size_t)m * HH + n] =
                __floats2half2_rn(fmaxf(acc[fm][fn][0] + b0, 0.f) * mk0,
                                  fmaxf(acc[fm][fn][1] + b1, 0.f) * mk0);
            *(half2*)&C[(size_t)(m + 8) * HH + n] =
                __floats2half2_rn(fmaxf(acc[fm][fn][2] + b0, 0.f) * mk1,
                                  fmaxf(acc[fm][fn][3] + b1, 0.f) * mk1);
        }
    }
}

// ---------------------------------------------------------------------------
// att[b,i,j] = Fa[b,i,:] . Fb[b,j,:]  (NT), fp32 out + fused row/col max atomics
// ---------------------------------------------------------------------------
__global__ __launch_bounds__(256, 2) void k_att(
    const __half* __restrict__ Fa, const __half* __restrict__ Fb, float* __restrict__ att,
    uint32_t* __restrict__ rm, uint32_t* __restrict__ cm)
{
    extern __shared__ __half sm[];
    __half* smA = sm;
    __half* smB = sm + 3 * A_STG_H;
    LANE_SETUP
    const int b = blockIdx.z;
    const int m0 = blockIdx.y * 128, n0 = blockIdx.x * 128;
    const __half* Ab = Fa + (size_t)b * LL * HH;
    const __half* Bb = Fb + (size_t)b * LL * HH;
    const uint32_t a_base = (uint32_t)__cvta_generic_to_shared(smA);
    const uint32_t b_base = (uint32_t)__cvta_generic_to_shared(smB);
    const uint32_t a_addr  = a_base + A_ADDR_EXPR;
    const uint32_t bn_addr = b_base + BN_ADDR_EXPR;
    float acc[4][4][4] = {};
    const int nt = HH / 64;
#define LOADT(st, k0)                                                                       \
    do {                                                                                    \
        _Pragma("unroll")                                                                   \
        for (int p = 0; p < 4; p++) {                                                       \
            int id = t + p * 256;                                                           \
            int row = id >> 3, cc = id & 7;                                                 \
            cp16(smA + (st) * A_STG_H + row * 72 + cc * 8,                                  \
                 Ab + (size_t)(m0 + row) * HH + (k0) + cc * 8);                             \
            cp16(smB + (st) * A_STG_H + row * 72 + cc * 8,                                  \
                 Bb + (size_t)(n0 + row) * HH + (k0) + cc * 8);                             \
        }                                                                                   \
    } while (0)
    PIPE3_PROLOG()
    PIPE3_BODY(COMPUTE64_NT)
#undef LOADT
    const int mbase = m0 + wm * 64, nbase = n0 + wn * 32;
#pragma unroll
    for (int fm = 0; fm < 4; fm++) {
        int m = mbase + fm * 16 + g;
#pragma unroll
        for (int fn = 0; fn < 4; fn++) {
            int n = nbase + fn * 8 + 2 * q;
            *(float2*)&att[((size_t)b * LL + m) * LL + n] =
                make_float2(acc[fm][fn][0], acc[fm][fn][1]);
            *(float2*)&att[((size_t)b * LL + m + 8) * LL + n] =
                make_float2(acc[fm][fn][2], acc[fm][fn][3]);
        }
    }
    // fused row maxes -> global atomicMax
#pragma unroll
    for (int fm = 0; fm < 4; fm++) {
        float r0 = acc[fm][0][0], r1 = acc[fm][0][2];
#pragma unroll
        for (int fn = 0; fn < 4; fn++) {
            r0 = fmaxf(r0, fmaxf(acc[fm][fn][0], acc[fm][fn][1]));
            r1 = fmaxf(r1, fmaxf(acc[fm][fn][2], acc[fm][fn][3]));
        }
        r0 = fmaxf(r0, __shfl_xor_sync(0xffffffffu, r0, 1));
        r0 = fmaxf(r0, __shfl_xor_sync(0xffffffffu, r0, 2));
        r1 = fmaxf(r1, __shfl_xor_sync(0xffffffffu, r1, 1));
        r1 = fmaxf(r1, __shfl_xor_sync(0xffffffffu, r1, 2));
        if (q == 0) {
            int m = mbase + fm * 16 + g;
            atomicMax(&rm[b * LL + m], encf(r0));
            atomicMax(&rm[b * LL + m + 8], encf(r1));
        }
    }
    // fused col maxes
#pragma unroll
    for (int fn = 0; fn < 4; fn++) {
        float c0 = acc[0][fn][0], c1 = acc[0][fn][1];
#pragma unroll
        for (int fm = 0; fm < 4; fm++) {
            c0 = fmaxf(c0, fmaxf(acc[fm][fn][0], acc[fm][fn][2]));
            c1 = fmaxf(c1, fmaxf(acc[fm][fn][1], acc[fm][fn][3]));
        }
        c0 = fmaxf(c0, __shfl_xor_sync(0xffffffffu, c0, 4));
        c0 = fmaxf(c0, __shfl_xor_sync(0xffffffffu, c0, 8));
        c0 = fmaxf(c0, __shfl_xor_sync(0xffffffffu, c0, 16));
        c1 = fmaxf(c1, __shfl_xor_sync(0xffffffffu, c1, 4));
        c1 = fmaxf(c1, __shfl_xor_sync(0xffffffffu, c1, 8));
        c1 = fmaxf(c1, __shfl_xor_sync(0xffffffffu, c1, 16));
        if (g == 0) {
            int n = nbase + fn * 8 + 2 * q;
            atomicMax(&cm[b * LL + n], encf(c0));
            atomicMax(&cm[b * LL + n + 1], encf(c1));
        }
    }
}

// ---------------------------------------------------------------------------
// map: att -> S1u [b,i,j], S2tu [b,j,i] (unnormalized, half), accumulates rs, cs
// ---------------------------------------------------------------------------
__global__ void k_map(const float* __restrict__ att,
                      const int* __restrict__ a_mask, const int* __restrict__ b_mask,
                      const uint32_t* __restrict__ rm, const uint32_t* __restrict__ cm,
                      float* __restrict__ rs, float* __restrict__ cs,
                      __half* __restrict__ S1, __half* __restrict__ S2t)
{
    const int bb = blockIdx.z;
    const int i0 = blockIdx.y * 32, j0 = blockIdx.x * 32;
    const int tx = threadIdx.x, ty = threadIdx.y;
    const int tid = ty * 32 + tx;
    __shared__ float rmv[32], ermv[32], amv[32];
    __shared__ float ecm[32], bmv[32];
    __shared__ float s2t_sh[32][33];
    __shared__ float colp[8][32];
    if (tid < 32) {
        float c = decf(cm[bb * LL + j0 + tid]);
        ecm[tid] = __expf(-c);
        bmv[tid] = 768.0f * (float)b_mask[bb * LL + j0 + tid];
    } else if (tid < 64) {
        int r = tid - 32;
        float rf = decf(rm[bb * LL + i0 + r]);
        rmv[r] = rf;
        ermv[r] = __expf(rf);
        amv[r] = (float)a_mask[bb * LL + i0 + r];
    }
    __syncthreads();
    float colsum = 0.f;
    for (int r = ty; r < 32; r += 8) {
        const int i = i0 + r;
        float a = att[((size_t)bb * LL + i) * LL + j0 + tx];
        float E = __expf(a - rmv[r]) * (amv[r] * bmv[tx]);
        S1[((size_t)bb * LL + i) * LL + j0 + tx] = __float2half_rn(E);
        float s2 = E * ermv[r] * ecm[tx];
        s2t_sh[tx][r] = s2;
        colsum += s2;
        float rsum = E;
#pragma unroll
        for (int o = 16; o > 0; o >>= 1) rsum += __shfl_xor_sync(0xffffffffu, rsum, o);
        if (tx == 0) atomicAdd(&rs[bb * LL + i], rsum);
    }
    colp[ty][tx] = colsum;
    __syncthreads();
    if (ty == 0) {
        float c = 0.f;
#pragma unroll
        for (int k = 0; k < 8; k++) c += colp[k][tx];
        atomicAdd(&cs[bb * LL + j0 + tx], c);
    }
    for (int r = ty; r < 32; r += 8)
        S2t[((size_t)bb * LL + j0 + r) * LL + i0 + tx] = __float2half_rn(s2t_sh[r][tx]);
}

// ---------------------------------------------------------------------------
// paired ctx (NN, K=512): deferred softmax normalization in epilogue
// ---------------------------------------------------------------------------
__global__ __launch_bounds__(256, 2) void k_ctx(
    const __half* __restrict__ Sa, const __half* __restrict__ Sb,
    const __half* __restrict__ Pa, const __half* __restrict__ Pb,
    const float* __restrict__ sca, const float* __restrict__ scb,
    __half* __restrict__ Ca, __half* __restrict__ Cb)
{
    extern __shared__ __half sm[];
    __half* smA = sm;
    __half* smB = sm + 3 * A_STG_H;
    LANE_SETUP
    const int pair = blockIdx.z >> 6;
    const int b = blockIdx.z & 63;
    const __half* S = pair ? Sb : Sa;
    const __half* P = pair ? Pb : Pa;
    const float* sc = pair ? scb : sca;
    __half* C = pair ? Cb : Ca;
    const int m0 = blockIdx.y * 128, n0 = blockIdx.x * 128;
    const __half* Abp = S + (size_t)b * LL * LL;
    const __half* Bbp = P + (size_t)b * LL * HH;
    const uint32_t a_base = (uint32_t)__cvta_generic_to_shared(smA);
    const uint32_t b_base = (uint32_t)__cvta_generic_to_shared(smB);
    const uint32_t a_addr = a_base + A_ADDR_EXPR;
    const uint32_t b_addr = b_base + B_ADDR_EXPR;
    float acc[4][4][4] = {};
    const int nt = LL / 64;
#define LOADT(st, k0)                                                                       \
    do {                                                                                    \
        _Pragma("unroll")                                                                   \
        for (int p = 0; p < 4; p++) {                                                       \
            int id = t + p * 256;                                                           \
            int arow = id >> 3, ac = id & 7;                                                \
            cp16(smA + (st) * A_STG_H + arow * 72 + ac * 8,                                 \
                 Abp + (size_t)(m0 + arow) * LL + (k0) + ac * 8);                           \
            int brow = id >> 4, bc = id & 15;                                               \
            cp16(smB + (st) * B_STG_H + brow * 136 + bc * 8,                                \
                 Bbp + (size_t)((k0) + brow) * HH + n0 + bc * 8);                           \
        }                                                                                   \
    } while (0)
    PIPE3_PROLOG()
    PIPE3_BODY(COMPUTE64_KN)
#undef LOADT
    const int mbase = m0 + wm * 64, nbase = n0 + wn * 32;
#pragma unroll
    for (int fm = 0; fm < 4; fm++) {
        int m = mbase + fm * 16 + g;
        float s0 = 1.0f / (sc[b * LL + m] + 1e-8f);
        float s1v = 1.0f / (sc[b * LL + m + 8] + 1e-8f);
#pragma unroll
        for (int fn = 0; fn < 4; fn++) {
            int n = nbase + fn * 8 + 2 * q;
            *(half2*)&C[((size_t)b * LL + m) * HH + n] =
                __floats2half2_rn(acc[fm][fn][0] * s0, acc[fm][fn][1] * s0);
            *(half2*)&C[((size_t)b * LL + m + 8) * HH + n] =
                __floats2half2_rn(acc[fm][fn][2] * s1v, acc[fm][fn][3] * s1v);
        }
    }
}

// ---------------------------------------------------------------------------
// paired compare + aggregate
// ---------------------------------------------------------------------------
__global__ __launch_bounds__(256, 2) void k_cmp(
    const __half* __restrict__ Pa, const __half* __restrict__ Pb,
    const __half* __restrict__ Xa, const __half* __restrict__ Xb,
    const __half* __restrict__ Wg, const float* __restrict__ bg,
    const int* __restrict__ ma, const int* __restrict__ mb,
    float* __restrict__ out)
{
    extern __shared__ __half sm[];
    __half* smA = sm;
    __half* smB = sm + 3 * A_STG_H;
    __shared__ float red_s[128][2];
    __shared__ float red_m[128][2];
    LANE_SETUP
    const int z = blockIdx.z;
    const __half* P = z ? Pb : Pa;
    const __half* CTX = z ? Xb : Xa;
    const int* mask = z ? mb : ma;
    const int sumoff = z ? 768 : 0, maxoff = z ? 2304 : 1536;
    const int m0 = blockIdx.y * 128, n0 = blockIdx.x * 128;
    const uint32_t a_base = (uint32_t)__cvta_generic_to_shared(smA);
    const uint32_t b_base = (uint32_t)__cvta_generic_to_shared(smB);
    const uint32_t a_addr = a_base + A_ADDR_EXPR;
    const uint32_t b_addr = b_base + B_ADDR_EXPR;
    float acc[4][4][4] = {};
    const int nt = (2 * HH) / 64;  // 24
#define LOADT(st, k0)                                                                       \
    do {                                                                                    \
        const __half* Asrc = ((k0) < HH) ? P : CTX;                                         \
        const int kk0 = ((k0) < HH) ? (k0) : ((k0) - HH);                                   \
        _Pragma("unroll")                                                                   \
        for (int p = 0; p < 4; p++) {                                                       \
            int id = t + p * 256;                                                           \
            int arow = id >> 3, ac = id & 7;                                                \
            cp16(smA + (st) * A_STG_H + arow * 72 + ac * 8,                                 \
                 Asrc + (size_t)(m0 + arow) * HH + kk0 + ac * 8);                           \
            int brow = id >> 4, bc = id & 15;                                               \
            cp16(smB + (st) * B_STG_H + brow * 136 + bc * 8,                                \
                 Wg + (size_t)((k0) + brow) * HH + n0 + bc * 8);                            \
        }                                                                                   \
    } while (0)
    PIPE3_PROLOG()
    PIPE3_BODY(COMPUTE64_KN)
#undef LOADT
    const int mbase = m0 + wm * 64, nbase = n0 + wn * 32;
    float psum[4][2] = {}, pmax[4][2] = {};
#pragma unroll
    for (int fm = 0; fm < 4; fm++) {
        int m = mbase + fm * 16 + g;
        float mk0 = (float)mask[m];
        float mk1 = (float)mask[m + 8];
#pragma unroll
        for (int fn = 0; fn < 4; fn++) {
            int n = nbase + fn * 8 + 2 * q;
            float b0 = bg[n], b1 = bg[n + 1];
            float v00 = fmaxf(acc[fm][fn][0] + b0, 0.f) * mk0;
            float v01 = fmaxf(acc[fm][fn][1] + b1, 0.f) * mk0;
            float v10 = fmaxf(acc[fm][fn][2] + b0, 0.f) * mk1;
            float v11 = fmaxf(acc[fm][fn][3] + b1, 0.f) * mk1;
            psum[fn][0] += v00 + v10;
            psum[fn][1] += v01 + v11;
            pmax[fn][0] = fmaxf(pmax[fn][0], fmaxf(v00, v10));
            pmax[fn][1] = fmaxf(pmax[fn][1], fmaxf(v01, v11));
        }
    }
#pragma unroll
    for (int fn = 0; fn < 4; fn++)
#pragma unroll
        for (int e = 0; e < 2; e++) {
#pragma unroll
            for (int o = 4; o < 32; o <<= 1) {
                psum[fn][e] += __shfl_xor_sync(0xffffffffu, psum[fn][e], o);
                pmax[fn][e] = fmaxf(pmax[fn][e], __shfl_xor_sync(0xffffffffu, pmax[fn][e], o));
            }
        }
    if (l < 4) {
#pragma unroll
        for (int fn = 0; fn < 4; fn++)
#pragma unroll
            for (int e = 0; e < 2; e++) {
                int c = wn * 32 + fn * 8 + 2 * q + e;
                red_s[c][wm] = psum[fn][e];
                red_m[c][wm] = pmax[fn][e];
            }
    }
    __syncthreads();
    if (t < 128) {
        const int bb = m0 >> 9;
        float s = red_s[t][0] + red_s[t][1];
        float mx = fmaxf(red_m[t][0], red_m[t][1]);
        atomicAdd(&out[bb * 3072 + sumoff + n0 + t], s);
        atomicMax((int*)&out[bb * 3072 + maxoff + n0 + t], __float_as_int(mx));
    }
}

// zero out + stats accumulators (rm/cm encoded maxes, rs/cs sums)
__global__ void k_zero(float* __restrict__ out, float* __restrict__ stats)
{
    int i = blockIdx.x * blockDim.x + threadIdx.x;
    if (i < BB * 4 * HH) out[i] = 0.0f;
    if (i < 4 * M_ROWS) stats[i] = 0.0f;
}

extern "C" void kernel_launch(void* const* d_in, const int* in_sizes, int n_in,
                              void* d_out, int out_size)
{
    const float* a_embeds = (const float*)d_in[0];
    const float* b_embeds = (const float*)d_in[1];
    const int*   a_mask   = (const int*)d_in[2];
    const int*   b_mask   = (const int*)d_in[3];
    const float* Wp = (const float*)d_in[4];
    const float* bp = (const float*)d_in[5];
    const float* Wf = (const float*)d_in[6];
    const float* bf = (const float*)d_in[7];
    const float* Wg = (const float*)d_in[8];
    const float* bg = (const float*)d_in[9];
    float* out = (float*)d_out;

    float* base = nullptr;
    cudaGetSymbolAddress((void**)&base, g_scratch);
    float* att = base;
    float* rm  = att + ALL;          // encoded uint maxes
    float* cm  = rm + M_ROWS;
    float* rs  = cm + M_ROWS;
    float* cs  = rs + M_ROWS;
    __half* ah    = (__half*)(cs + M_ROWS);
    __half* bh    = ah + PLH;
    __half* ap    = bh + PLH;
    __half* bp_   = ap + PLH;
    __half* Fa    = bp_ + PLH;
    __half* Fb    = Fa + PLH;
    __half* beta  = Fb + PLH;
    __half* alpha = beta + PLH;
    __half* S1    = alpha + PLH;
    __half* S2t   = S1 + ALL;
    __half* hWp   = S2t + ALL;
    __half* hWf   = hWp + DD * HH;
    __half* hWg   = hWf + HH * HH;

    cudaFuncSetAttribute(k_proj, cudaFuncAttributeMaxDynamicSharedMemorySize, KN_SMEM);
    cudaFuncSetAttribute(k_att,  cudaFuncAttributeMaxDynamicSharedMemorySize, NT_SMEM);
    cudaFuncSetAttribute(k_ctx,  cudaFuncAttributeMaxDynamicSharedMemorySize, KN_SMEM);
    cudaFuncSetAttribute(k_cmp,  cudaFuncAttributeMaxDynamicSharedMemorySize, KN_SMEM);

    k_zero<<<(BB * 4 * HH + 1023) / 1024, 1024>>>(out, rm);

    // fp32 -> fp16 conversions
    k_cvth2<<<dim3((int)((PLH / 4 + 255) / 256), 1, 2), 256>>>(a_embeds, b_embeds, ah, bh, (int)PLH);
    k_cvtw<<<dim3((2 * HH * HH / 4 + 255) / 256, 1, 3), 256>>>(Wp, Wf, Wg, hWp, hWf, hWg);

    // shared projection FFN (paired a/b)
    k_proj<<<dim3(6, 256, 2), 256, KN_SMEM>>>(ah, bh, hWp, bp, nullptr, nullptr, ap, bp_, DD);

    // attend features (paired, relu + mask)
    k_proj<<<dim3(6, 256, 2), 256, KN_SMEM>>>(ap, bp_, hWf, bf, a_mask, b_mask, Fa, Fb, HH);

    // attention scores + fused row/col max
    k_att<<<dim3(4, 4, 64), 256, NT_SMEM>>>(Fa, Fb, att, (uint32_t*)rm, (uint32_t*)cm);

    // map: unnormalized softmax numerators + sum accumulation
    k_map<<<dim3(16, 16, 64), dim3(32, 8)>>>(att, a_mask, b_mask,
                                             (const uint32_t*)rm, (const uint32_t*)cm,
                                             rs, cs, S1, S2t);

    // contexts (paired; deferred normalization in epilogue)
    k_ctx<<<dim3(6, 4, 128), 256, KN_SMEM>>>(S1, S2t, bp_, ap, rs, cs, beta, alpha);

    // compare + aggregate (paired)
    k_cmp<<<dim3(6, 256, 2), 256, KN_SMEM>>>(ap, bp_, beta, alpha, hWg, bg, a_mask, b_mask, out);
}

// round 9
// speedup vs baseline: 10.0857x; 1.0011x over previous
#include <cuda_runtime.h>
#include <cuda_fp16.h>
#include <stdint.h>
#include <math.h>

// Problem constants
#define BB 64
#define LL 512
#define DD 768
#define HH 768

static const int    M_ROWS = BB * LL;                  // 32768
static const size_t PLH = (size_t)BB * LL * HH;        // 25165824
static const size_t ALL = (size_t)BB * LL * LL;        // 16777216

__device__ __align__(16) float g_scratch[6 * 25165824ULL + 3 * 16777216ULL + 4 * 32768ULL + 2359296ULL];

// ---------------------------------------------------------------------------
// helpers
// ---------------------------------------------------------------------------
__device__ __forceinline__ void cp16(void* s, const void* g) {
    uint32_t sa = (uint32_t)__cvta_generic_to_shared(s);
    asm volatile("cp.async.cg.shared.global [%0], [%1], 16;" :: "r"(sa), "l"(g));
}
__device__ __forceinline__ void cp_commit() { asm volatile("cp.async.commit_group;"); }
__device__ __forceinline__ void cp_wait1()  { asm volatile("cp.async.wait_group 1;"); }

__device__ __forceinline__ void ldsm_x4(uint32_t* r, uint32_t addr) {
    asm volatile("ldmatrix.sync.aligned.m8n8.x4.shared.b16 {%0,%1,%2,%3}, [%4];"
        : "=r"(r[0]), "=r"(r[1]), "=r"(r[2]), "=r"(r[3]) : "r"(addr));
}
__device__ __forceinline__ void ldsm_x4t(uint32_t* r, uint32_t addr) {
    asm volatile("ldmatrix.sync.aligned.m8n8.x4.trans.shared.b16 {%0,%1,%2,%3}, [%4];"
        : "=r"(r[0]), "=r"(r[1]), "=r"(r[2]), "=r"(r[3]) : "r"(addr));
}
__device__ __forceinline__ void mma16(float* c, const uint32_t* a, const uint32_t* b) {
    asm volatile(
        "mma.sync.aligned.m16n8k16.row.col.f32.f16.f16.f32 "
        "{%0,%1,%2,%3},{%4,%5,%6,%7},{%8,%9},{%0,%1,%2,%3};"
        : "+f"(c[0]), "+f"(c[1]), "+f"(c[2]), "+f"(c[3])
        : "r"(a[0]), "r"(a[1]), "r"(a[2]), "r"(a[3]), "r"(b[0]), "r"(b[1]));
}

// monotone float<->uint encoding for atomicMax on floats of any sign
__device__ __forceinline__ uint32_t encf(float f) {
    uint32_t u = __float_as_uint(f);
    return u ^ (uint32_t)(((int32_t)u >> 31) | 0x80000000);
}
__device__ __forceinline__ float decf(uint32_t u) {
    u = (u & 0x80000000u) ? (u ^ 0x80000000u) : ~u;
    return __uint_as_float(u);
}

// SMEM staging (BK = 64, 3 stages):
//  A tile: [128][72] halves, pitch 144 B, stage = 18432 B  (conflict-free ldmatrix)
//  B KN:   [64][136] halves, pitch 272 B, stage = 17408 B
//  B NT:   same layout as A
#define A_STG_B 18432u
#define B_STG_B 17408u
#define A_STG_H 9216
#define B_STG_H 8704

#define COMPUTE64_KN(buf)                                                      \
    _Pragma("unroll")                                                          \
    for (int ks = 0; ks < 4; ks++) {                                           \
        uint32_t af[4][4], bt0[4], bt1[4];                                     \
        _Pragma("unroll")                                                      \
        for (int fm = 0; fm < 4; fm++)                                         \
            ldsm_x4(af[fm], a_addr + (buf) * A_STG_B + ks * 32u + fm * 2304u); \
        ldsm_x4t(bt0, b_addr + (buf) * B_STG_B + ks * 4352u);                  \
        ldsm_x4t(bt1, b_addr + (buf) * B_STG_B + ks * 4352u + 32u);            \
        uint32_t bf[4][2] = {{bt0[0], bt0[1]}, {bt0[2], bt0[3]},               \
                             {bt1[0], bt1[1]}, {bt1[2], bt1[3]}};              \
        _Pragma("unroll")                                                      \
        for (int fm = 0; fm < 4; fm++)                                         \
            _Pragma("unroll")                                                  \
            for (int fn = 0; fn < 4; fn++)                                     \
                mma16(acc[fm][fn], af[fm], bf[fn]);                            \
    }

#define COMPUTE64_NT(buf)                                                      \
    _Pragma("unroll")                                                          \
    for (int ks = 0; ks < 4; ks++) {                                           \
        uint32_t af[4][4], bt0[4], bt1[4];                                     \
        _Pragma("unroll")                                                      \
        for (int fm = 0; fm < 4; fm++)                                         \
            ldsm_x4(af[fm], a_addr + (buf) * A_STG_B + ks * 32u + fm * 2304u); \
        ldsm_x4(bt0, bn_addr + (buf) * A_STG_B + ks * 32u);                    \
        ldsm_x4(bt1, bn_addr + (buf) * A_STG_B + ks * 32u + 2304u);            \
        uint32_t bf[4][2] = {{bt0[0], bt0[2]}, {bt0[1], bt0[3]},               \
                             {bt1[0], bt1[2]}, {bt1[1], bt1[3]}};              \
        _Pragma("unroll")                                                      \
        for (int fm = 0; fm < 4; fm++)                                         \
            _Pragma("unroll")                                                  \
            for (int fn = 0; fn < 4; fn++)                                     \
                mma16(acc[fm][fn], af[fm], bf[fn]);                            \
    }

#define LANE_SETUP                                                             \
    const int t = threadIdx.x;                                                 \
    const int w = t >> 5, l = t & 31, g = l >> 2, q = l & 3;                   \
    const int wm = w >> 2, wn = w & 3;

#define A_ADDR_EXPR (uint32_t)(((wm * 64 + (l & 7) + ((l & 8) ? 8 : 0)) * 72 + ((l & 16) ? 8 : 0)) << 1)
#define B_ADDR_EXPR (uint32_t)((((l & 7) + ((l & 8) ? 8 : 0)) * 136 + wn * 32 + ((l & 16) ? 8 : 0)) << 1)
#define BN_ADDR_EXPR (uint32_t)(((wn * 32 + (l & 7) + ((l & 8) ? 8 : 0)) * 72 + ((l & 16) ? 8 : 0)) << 1)

static const int KN_SMEM = 3 * (A_STG_B + B_STG_B);   // 107520
static const int NT_SMEM = 3 * 2 * A_STG_B;           // 110592

// 3-stage pipeline over BK=64 stages
#define PIPE3_PROLOG()                                                         \
    LOADT(0, 0);  cp_commit();                                                 \
    LOADT(1, 64); cp_commit();

#define PIPE3_BODY(COMPUTE)                                                    \
    {                                                                          \
        int buf = 0, ldst = 2;                                                 \
        for (int kt = 0; kt < nt; kt++) {                                      \
            cp_wait1();                                                        \
            __syncthreads();                                                   \
            if (kt + 2 < nt) { LOADT(ldst, (kt + 2) * 64); }                   \
            cp_commit();                                                       \
            COMPUTE(buf);                                                      \
            if (++buf == 3) buf = 0;                                           \
            if (++ldst == 3) ldst = 0;                                         \
        }                                                                      \
    }

// ---------------------------------------------------------------------------
// converts
// ---------------------------------------------------------------------------
__global__ void k_cvth2(const float* __restrict__ s0, const float* __restrict__ s1,
                        __half* __restrict__ d0, __half* __restrict__ d1, int n)
{
    const float* src = blockIdx.z ? s1 : s0;
    __half* dst = blockIdx.z ? d1 : d0;
    int i = (blockIdx.x * blockDim.x + threadIdx.x) * 4;
    if (i < n) {
        float4 v = *(const float4*)(src + i);
        *(half2*)(dst + i)     = __floats2half2_rn(v.x, v.y);
        *(half2*)(dst + i + 2) = __floats2half2_rn(v.z, v.w);
    }
}
__global__ void k_cvtw(const float* __restrict__ w0, const float* __restrict__ w1,
                       const float* __restrict__ w2,
                       __half* __restrict__ d0, __half* __restrict__ d1, __half* __restrict__ d2)
{
    int z = blockIdx.z;
    const float* src = (z == 0) ? w0 : (z == 1 ? w1 : w2);
    __half* dst = (z == 0) ? d0 : (z == 1 ? d1 : d2);
    int n = (z == 2) ? 2 * HH * HH : DD * HH;
    int i = (blockIdx.x * blockDim.x + threadIdx.x) * 4;
    if (i < n) {
        float4 v = *(const float4*)(src + i);
        *(half2*)(dst + i)     = __floats2half2_rn(v.x, v.y);
        *(half2*)(dst + i + 2) = __floats2half2_rn(v.z, v.w);
    }
}

// ---------------------------------------------------------------------------
// paired proj / attend-F: C = half(relu(A @ W + bias) * mask)   (z selects a/b)
// ---------------------------------------------------------------------------
__global__ __launch_bounds__(256, 2) void k_proj(
    const __half* __restrict__ Aa, const __half* __restrict__ Ab,
    const __half* __restrict__ W, const float* __restrict__ bias,
    const int* __restrict__ ma, const int* __restrict__ mb,
    __half* __restrict__ Ca, __half* __restrict__ Cb, int K)
{
    extern __shared__ __half sm[];
    __half* smA = sm;
    __half* smB = sm + 3 * A_STG_H;
    LANE_SETUP
    const __half* A = blockIdx.z ? Ab : Aa;
    const int* mask = blockIdx.z ? mb : ma;
    __half* C = blockIdx.z ? Cb : Ca;
    const int m0 = blockIdx.y * 128, n0 = blockIdx.x * 128;
    const uint32_t a_base = (uint32_t)__cvta_generic_to_shared(smA);
    const uint32_t b_base = (uint32_t)__cvta_generic_to_shared(smB);
    const uint32_t a_addr = a_base + A_ADDR_EXPR;
    const uint32_t b_addr = b_base + B_ADDR_EXPR;
    float acc[4][4][4] = {};
    const int nt = K / 64;
#define LOADT(st, k0)                                                                       \
    do {                                                                                    \
        _Pragma("unroll")                                                                   \
        for (int p = 0; p < 4; p++) {                                                       \
            int id = t + p * 256;                                                           \
            int arow = id >> 3, ac = id & 7;                                                \
            cp16(smA + (st) * A_STG_H + arow * 72 + ac * 8,                                 \
                 A + (size_t)(m0 + arow) * K + (k0) + ac * 8);                              \
            int brow = id >> 4, bc = id & 15;                                               \
            cp16(smB + (st) * B_STG_H + brow * 136 + bc * 8,                                \
                 W + (size_t)((k0) + brow) * HH + n0 + bc * 8);                             \
        }                                                                                   \
    } while (0)
    PIPE3_PROLOG()
    PIPE3_BODY(COMPUTE64_KN)
#undef LOADT
    const int mbase = m0 + wm * 64, nbase = n0 + wn * 32;
#pragma unroll
    for (int fm = 0; fm < 4; fm++) {
        int m = mbase + fm * 16 + g;
        float mk0 = mask ? (float)mask[m] : 1.0f;
        float mk1 = mask ? (float)mask[m + 8] : 1.0f;
#pragma unroll
        for (int fn = 0; fn < 4; fn++) {
            int n = nbase + fn * 8 + 2 * q;
            float b0 = bias[n], b1 = bias[n + 1];
            *(half2*)&C[(size_t)m * HH + n] =
                __floats2half2_rn(fmaxf(acc[fm][fn][0] + b0, 0.f) * mk0,
                                  fmaxf(acc[fm][fn][1] + b1, 0.f) * mk0);
            *(half2*)&C[(size_t)(m + 8) * HH + n] =
                __floats2half2_rn(fmaxf(acc[fm][fn][2] + b0, 0.f) * mk1,
                                  fmaxf(acc[fm][fn][3] + b1, 0.f) * mk1);
        }
    }
}

// ---------------------------------------------------------------------------
// att[b,i,j] = Fa[b,i,:] . Fb[b,j,:]  (NT), fp32 out + fused row/col max atomics
// ---------------------------------------------------------------------------
__global__ __launch_bounds__(256, 2) void k_att(
    const __half* __restrict__ Fa, const __half* __restrict__ Fb, float* __restrict__ att,
    uint32_t* __restrict__ rm, uint32_t* __restrict__ cm)
{
    extern __shared__ __half sm[];
    __half* smA = sm;
    __half* smB = sm + 3 * A_STG_H;
    LANE_SETUP
    const int b = blockIdx.z;
    const int m0 = blockIdx.y * 128, n0 = blockIdx.x * 128;
    const __half* Ab = Fa + (size_t)b * LL * HH;
    const __half* Bb = Fb + (size_t)b * LL * HH;
    const uint32_t a_base = (uint32_t)__cvta_generic_to_shared(smA);
    const uint32_t b_base = (uint32_t)__cvta_generic_to_shared(smB);
    const uint32_t a_addr  = a_base + A_ADDR_EXPR;
    const uint32_t bn_addr = b_base + BN_ADDR_EXPR;
    float acc[4][4][4] = {};
    const int nt = HH / 64;
#define LOADT(st, k0)                                                                       \
    do {                                                                                    \
        _Pragma("unroll")                                                                   \
        for (int p = 0; p < 4; p++) {                                                       \
            int id = t + p * 256;                                                           \
            int row = id >> 3, cc = id & 7;                                                 \
            cp16(smA + (st) * A_STG_H + row * 72 + cc * 8,                                  \
                 Ab + (size_t)(m0 + row) * HH + (k0) + cc * 8);                             \
            cp16(smB + (st) * A_STG_H + row * 72 + cc * 8,                                  \
                 Bb + (size_t)(n0 + row) * HH + (k0) + cc * 8);                             \
        }                                                                                   \
    } while (0)
    PIPE3_PROLOG()
    PIPE3_BODY(COMPUTE64_NT)
#undef LOADT
    const int mbase = m0 + wm * 64, nbase = n0 + wn * 32;
#pragma unroll
    for (int fm = 0; fm < 4; fm++) {
        int m = mbase + fm * 16 + g;
#pragma unroll
        for (int fn = 0; fn < 4; fn++) {
            int n = nbase + fn * 8 + 2 * q;
            *(float2*)&att[((size_t)b * LL + m) * LL + n] =
                make_float2(acc[fm][fn][0], acc[fm][fn][1]);
            *(float2*)&att[((size_t)b * LL + m + 8) * LL + n] =
                make_float2(acc[fm][fn][2], acc[fm][fn][3]);
        }
    }
    // fused row maxes -> global atomicMax
#pragma unroll
    for (int fm = 0; fm < 4; fm++) {
        float r0 = acc[fm][0][0], r1 = acc[fm][0][2];
#pragma unroll
        for (int fn = 0; fn < 4; fn++) {
            r0 = fmaxf(r0, fmaxf(acc[fm][fn][0], acc[fm][fn][1]));
            r1 = fmaxf(r1, fmaxf(acc[fm][fn][2], acc[fm][fn][3]));
        }
        r0 = fmaxf(r0, __shfl_xor_sync(0xffffffffu, r0, 1));
        r0 = fmaxf(r0, __shfl_xor_sync(0xffffffffu, r0, 2));
        r1 = fmaxf(r1, __shfl_xor_sync(0xffffffffu, r1, 1));
        r1 = fmaxf(r1, __shfl_xor_sync(0xffffffffu, r1, 2));
        if (q == 0) {
            int m = mbase + fm * 16 + g;
            atomicMax(&rm[b * LL + m], encf(r0));
            atomicMax(&rm[b * LL + m + 8], encf(r1));
        }
    }
    // fused col maxes
#pragma unroll
    for (int fn = 0; fn < 4; fn++) {
        float c0 = acc[0][fn][0], c1 = acc[0][fn][1];
#pragma unroll
        for (int fm = 0; fm < 4; fm++) {
            c0 = fmaxf(c0, fmaxf(acc[fm][fn][0], acc[fm][fn][2]));
            c1 = fmaxf(c1, fmaxf(acc[fm][fn][1], acc[fm][fn][3]));
        }
        c0 = fmaxf(c0, __shfl_xor_sync(0xffffffffu, c0, 4));
        c0 = fmaxf(c0, __shfl_xor_sync(0xffffffffu, c0, 8));
        c0 = fmaxf(c0, __shfl_xor_sync(0xffffffffu, c0, 16));
        c1 = fmaxf(c1, __shfl_xor_sync(0xffffffffu, c1, 4));
        c1 = fmaxf(c1, __shfl_xor_sync(0xffffffffu, c1, 8));
        c1 = fmaxf(c1, __shfl_xor_sync(0xffffffffu, c1, 16));
        if (g == 0) {
            int n = nbase + fn * 8 + 2 * q;
            atomicMax(&cm[b * LL + n], encf(c0));
            atomicMax(&cm[b * LL + n + 1], encf(c1));
        }
    }
}

// ---------------------------------------------------------------------------
// map: att -> S1u [b,i,j], S2tu [b,j,i] (unnormalized, half), accumulates rs, cs
// ---------------------------------------------------------------------------
__global__ void k_map(const float* __restrict__ att,
                      const int* __restrict__ a_mask, const int* __restrict__ b_mask,
                      const uint32_t* __restrict__ rm, const uint32_t* __restrict__ cm,
                      float* __restrict__ rs, float* __restrict__ cs,
                      __half* __restrict__ S1, __half* __restrict__ S2t)
{
    const int bb = blockIdx.z;
    const int i0 = blockIdx.y * 32, j0 = blockIdx.x * 32;
    const int tx = threadIdx.x, ty = threadIdx.y;
    const int tid = ty * 32 + tx;
    __shared__ float rmv[32], ermv[32], amv[32];
    __shared__ float ecm[32], bmv[32];
    __shared__ float s2t_sh[32][33];
    __shared__ float colp[8][32];
    if (tid < 32) {
        float c = decf(cm[bb * LL + j0 + tid]);
        ecm[tid] = __expf(-c);
        bmv[tid] = 768.0f * (float)b_mask[bb * LL + j0 + tid];
    } else if (tid < 64) {
        int r = tid - 32;
        float rf = decf(rm[bb * LL + i0 + r]);
        rmv[r] = rf;
        ermv[r] = __expf(rf);
        amv[r] = (float)a_mask[bb * LL + i0 + r];
    }
    __syncthreads();
    float colsum = 0.f;
    for (int r = ty; r < 32; r += 8) {
        const int i = i0 + r;
        float a = att[((size_t)bb * LL + i) * LL + j0 + tx];
        float E = __expf(a - rmv[r]) * (amv[r] * bmv[tx]);
        S1[((size_t)bb * LL + i) * LL + j0 + tx] = __float2half_rn(E);
        float s2 = E * ermv[r] * ecm[tx];
        s2t_sh[tx][r] = s2;
        colsum += s2;
        float rsum = E;
#pragma unroll
        for (int o = 16; o > 0; o >>= 1) rsum += __shfl_xor_sync(0xffffffffu, rsum, o);
        if (tx == 0) atomicAdd(&rs[bb * LL + i], rsum);
    }
    colp[ty][tx] = colsum;
    __syncthreads();
    if (ty == 0) {
        float c = 0.f;
#pragma unroll
        for (int k = 0; k < 8; k++) c += colp[k][tx];
        atomicAdd(&cs[bb * LL + j0 + tx], c);
    }
    for (int r = ty; r < 32; r += 8)
        S2t[((size_t)bb * LL + j0 + r) * LL + i0 + tx] = __float2half_rn(s2t_sh[r][tx]);
}

// ---------------------------------------------------------------------------
// paired ctx (NN, K=512): deferred softmax normalization in epilogue
// ---------------------------------------------------------------------------
__global__ __launch_bounds__(256, 2) void k_ctx(
    const __half* __restrict__ Sa, const __half* __restrict__ Sb,
    const __half* __restrict__ Pa, const __half* __restrict__ Pb,
    const float* __restrict__ sca, const float* __restrict__ scb,
    __half* __restrict__ Ca, __half* __restrict__ Cb)
{
    extern __shared__ __half sm[];
    __half* smA = sm;
    __half* smB = sm + 3 * A_STG_H;
    LANE_SETUP
    const int pair = blockIdx.z >> 6;
    const int b = blockIdx.z & 63;
    const __half* S = pair ? Sb : Sa;
    const __half* P = pair ? Pb : Pa;
    const float* sc = pair ? scb : sca;
    __half* C = pair ? Cb : Ca;
    const int m0 = blockIdx.y * 128, n0 = blockIdx.x * 128;
    const __half* Abp = S + (size_t)b * LL * LL;
    const __half* Bbp = P + (size_t)b * LL * HH;
    const uint32_t a_base = (uint32_t)__cvta_generic_to_shared(smA);
    const uint32_t b_base = (uint32_t)__cvta_generic_to_shared(smB);
    const uint32_t a_addr = a_base + A_ADDR_EXPR;
    const uint32_t b_addr = b_base + B_ADDR_EXPR;
    float acc[4][4][4] = {};
    const int nt = LL / 64;
#define LOADT(st, k0)                                                                       \
    do {                                                                                    \
        _Pragma("unroll")                                                                   \
        for (int p = 0; p < 4; p++) {                                                       \
            int id = t + p * 256;                                                           \
            int arow = id >> 3, ac = id & 7;                                                \
            cp16(smA + (st) * A_STG_H + arow * 72 + ac * 8,                                 \
                 Abp + (size_t)(m0 + arow) * LL + (k0) + ac * 8);                           \
            int brow = id >> 4, bc = id & 15;                                               \
            cp16(smB + (st) * B_STG_H + brow * 136 + bc * 8,                                \
                 Bbp + (size_t)((k0) + brow) * HH + n0 + bc * 8);                           \
        }                                                                                   \
    } while (0)
    PIPE3_PROLOG()
    PIPE3_BODY(COMPUTE64_KN)
#undef LOADT
    const int mbase = m0 + wm * 64, nbase = n0 + wn * 32;
#pragma unroll
    for (int fm = 0; fm < 4; fm++) {
        int m = mbase + fm * 16 + g;
        float s0 = 1.0f / (sc[b * LL + m] + 1e-8f);
        float s1v = 1.0f / (sc[b * LL + m + 8] + 1e-8f);
#pragma unroll
        for (int fn = 0; fn < 4; fn++) {
            int n = nbase + fn * 8 + 2 * q;
            *(half2*)&C[((size_t)b * LL + m) * HH + n] =
                __floats2half2_rn(acc[fm][fn][0] * s0, acc[fm][fn][1] * s0);
            *(half2*)&C[((size_t)b * LL + m + 8) * HH + n] =
                __floats2half2_rn(acc[fm][fn][2] * s1v, acc[fm][fn][3] * s1v);
        }
    }
}

// ---------------------------------------------------------------------------
// paired compare + aggregate
// ---------------------------------------------------------------------------
__global__ __launch_bounds__(256, 2) void k_cmp(
    const __half* __restrict__ Pa, const __half* __restrict__ Pb,
    const __half* __restrict__ Xa, const __half* __restrict__ Xb,
    const __half* __restrict__ Wg, const float* __restrict__ bg,
    const int* __restrict__ ma, const int* __restrict__ mb,
    float* __restrict__ out)
{
    extern __shared__ __half sm[];
    __half* smA = sm;
    __half* smB = sm + 3 * A_STG_H;
    __shared__ float red_s[128][2];
    __shared__ float red_m[128][2];
    LANE_SETUP
    const int z = blockIdx.z;
    const __half* P = z ? Pb : Pa;
    const __half* CTX = z ? Xb : Xa;
    const int* mask = z ? mb : ma;
    const int sumoff = z ? 768 : 0, maxoff = z ? 2304 : 1536;
    const int m0 = blockIdx.y * 128, n0 = blockIdx.x * 128;
    const uint32_t a_base = (uint32_t)__cvta_generic_to_shared(smA);
    const uint32_t b_base = (uint32_t)__cvta_generic_to_shared(smB);
    const uint32_t a_addr = a_base + A_ADDR_EXPR;
    const uint32_t b_addr = b_base + B_ADDR_EXPR;
    float acc[4][4][4] = {};
    const int nt = (2 * HH) / 64;  // 24
#define LOADT(st, k0)                                                                       \
    do {                                                                                    \
        const __half* Asrc = ((k0) < HH) ? P : CTX;                                         \
        const int kk0 = ((k0) < HH) ? (k0) : ((k0) - HH);                                   \
        _Pragma("unroll")                                                                   \
        for (int p = 0; p < 4; p++) {                                                       \
            int id = t + p * 256;                                                           \
            int arow = id >> 3, ac = id & 7;                                                \
            cp16(smA + (st) * A_STG_H + arow * 72 + ac * 8,                                 \
                 Asrc + (size_t)(m0 + arow) * HH + kk0 + ac * 8);                           \
            int brow = id >> 4, bc = id & 15;                                               \
            cp16(smB + (st) * B_STG_H + brow * 136 + bc * 8,                                \
                 Wg + (size_t)((k0) + brow) * HH + n0 + bc * 8);                            \
        }                                                                                   \
    } while (0)
    PIPE3_PROLOG()
    PIPE3_BODY(COMPUTE64_KN)
#undef LOADT
    const int mbase = m0 + wm * 64, nbase = n0 + wn * 32;
    float psum[4][2] = {}, pmax[4][2] = {};
#pragma unroll
    for (int fm = 0; fm < 4; fm++) {
        int m = mbase + fm * 16 + g;
        float mk0 = (float)mask[m];
        float mk1 = (float)mask[m + 8];
#pragma unroll
        for (int fn = 0; fn < 4; fn++) {
            int n = nbase + fn * 8 + 2 * q;
            float b0 = bg[n], b1 = bg[n + 1];
            float v00 = fmaxf(acc[fm][fn][0] + b0, 0.f) * mk0;
            float v01 = fmaxf(acc[fm][fn][1] + b1, 0.f) * mk0;
            float v10 = fmaxf(acc[fm][fn][2] + b0, 0.f) * mk1;
            float v11 = fmaxf(acc[fm][fn][3] + b1, 0.f) * mk1;
            psum[fn][0] += v00 + v10;
            psum[fn][1] += v01 + v11;
            pmax[fn][0] = fmaxf(pmax[fn][0], fmaxf(v00, v10));
            pmax[fn][1] = fmaxf(pmax[fn][1], fmaxf(v01, v11));
        }
    }
#pragma unroll
    for (int fn = 0; fn < 4; fn++)
#pragma unroll
        for (int e = 0; e < 2; e++) {
#pragma unroll
            for (int o = 4; o < 32; o <<= 1) {
                psum[fn][e] += __shfl_xor_sync(0xffffffffu, psum[fn][e], o);
                pmax[fn][e] = fmaxf(pmax[fn][e], __shfl_xor_sync(0xffffffffu, pmax[fn][e], o));
            }
        }
    if (l < 4) {
#pragma unroll
        for (int fn = 0; fn < 4; fn++)
#pragma unroll
            for (int e = 0; e < 2; e++) {
                int c = wn * 32 + fn * 8 + 2 * q + e;
                red_s[c][wm] = psum[fn][e];
                red_m[c][wm] = pmax[fn][e];
            }
    }
    __syncthreads();
    if (t < 128) {
        const int bb = m0 >> 9;
        float s = red_s[t][0] + red_s[t][1];
        float mx = fmaxf(red_m[t][0], red_m[t][1]);
        atomicAdd(&out[bb * 3072 + sumoff + n0 + t], s);
        atomicMax((int*)&out[bb * 3072 + maxoff + n0 + t], __float_as_int(mx));
    }
}

// zero out + stats accumulators (rm/cm encoded maxes, rs/cs sums)
__global__ void k_zero(float* __restrict__ out, float* __restrict__ stats)
{
    int i = blockIdx.x * blockDim.x + threadIdx.x;
    if (i < BB * 4 * HH) out[i] = 0.0f;
    if (i < 4 * M_ROWS) stats[i] = 0.0f;
}

extern "C" void kernel_launch(void* const* d_in, const int* in_sizes, int n_in,
                              void* d_out, int out_size)
{
    const float* a_embeds = (const float*)d_in[0];
    const float* b_embeds = (const float*)d_in[1];
    const int*   a_mask   = (const int*)d_in[2];
    const int*   b_mask   = (const int*)d_in[3];
    const float* Wp = (const float*)d_in[4];
    const float* bp = (const float*)d_in[5];
    const float* Wf = (const float*)d_in[6];
    const float* bf = (const float*)d_in[7];
    const float* Wg = (const float*)d_in[8];
    const float* bg = (const float*)d_in[9];
    float* out = (float*)d_out;

    float* base = nullptr;
    cudaGetSymbolAddress((void**)&base, g_scratch);
    float* att = base;
    float* rm  = att + ALL;          // encoded uint maxes
    float* cm  = rm + M_ROWS;
    float* rs  = cm + M_ROWS;
    float* cs  = rs + M_ROWS;
    __half* ah    = (__half*)(cs + M_ROWS);
    __half* bh    = ah + PLH;
    __half* ap    = bh + PLH;
    __half* bp_   = ap + PLH;
    __half* Fa    = bp_ + PLH;
    __half* Fb    = Fa + PLH;
    __half* beta  = Fb + PLH;
    __half* alpha = beta + PLH;
    __half* S1    = alpha + PLH;
    __half* S2t   = S1 + ALL;
    __half* hWp   = S2t + ALL;
    __half* hWf   = hWp + DD * HH;
    __half* hWg   = hWf + HH * HH;

    cudaFuncSetAttribute(k_proj, cudaFuncAttributeMaxDynamicSharedMemorySize, KN_SMEM);
    cudaFuncSetAttribute(k_att,  cudaFuncAttributeMaxDynamicSharedMemorySize, NT_SMEM);
    cudaFuncSetAttribute(k_ctx,  cudaFuncAttributeMaxDynamicSharedMemorySize, KN_SMEM);
    cudaFuncSetAttribute(k_cmp,  cudaFuncAttributeMaxDynamicSharedMemorySize, KN_SMEM);

    k_zero<<<(BB * 4 * HH + 1023) / 1024, 1024>>>(out, rm);

    // fp32 -> fp16 conversions
    k_cvth2<<<dim3((int)((PLH / 4 + 255) / 256), 1, 2), 256>>>(a_embeds, b_embeds, ah, bh, (int)PLH);
    k_cvtw<<<dim3((2 * HH * HH / 4 + 255) / 256, 1, 3), 256>>>(Wp, Wf, Wg, hWp, hWf, hWg);

    // shared projection FFN (paired a/b)
    k_proj<<<dim3(6, 256, 2), 256, KN_SMEM>>>(ah, bh, hWp, bp, nullptr, nullptr, ap, bp_, DD);

    // attend features (paired, relu + mask)
    k_proj<<<dim3(6, 256, 2), 256, KN_SMEM>>>(ap, bp_, hWf, bf, a_mask, b_mask, Fa, Fb, HH);

    // attention scores + fused row/col max
    k_att<<<dim3(4, 4, 64), 256, NT_SMEM>>>(Fa, Fb, att, (uint32_t*)rm, (uint32_t*)cm);

    // map: unnormalized softmax numerators + sum accumulation
    k_map<<<dim3(16, 16, 64), dim3(32, 8)>>>(att, a_mask, b_mask,
                                             (const uint32_t*)rm, (const uint32_t*)cm,
                                             rs, cs, S1, S2t);

    // contexts (paired; deferred normalization in epilogue)
    k_ctx<<<dim3(6, 4, 128), 256, KN_SMEM>>>(S1, S2t, bp_, ap, rs, cs, beta, alpha);

    // compare + aggregate (paired)
    k_cmp<<<dim3(6, 256, 2), 256, KN_SMEM>>>(ap, bp_, beta, alpha, hWg, bg, a_mask, b_mask, out);
}